// round 6
// baseline (speedup 1.0000x reference)
#include <cuda_runtime.h>
#include <cuda_bf16.h>
#include <math.h>

// ---------------------------------------------------------------------------
// Problem constants
// ---------------------------------------------------------------------------
#define N_NODES 8000
#define N_EDGES 64000
#define NBATCH  64
#define NGRID   12
#define HID     128
#define BAS     128
#define NLAYERS 3
#define IN_S    16
#define IN_V    2
#define OUT_S   8
#define OUT_V   1
#define WIDE    4

#define R_E (N_EDGES * NGRID)   // 768000 edge-grid rows
#define R_N (N_NODES * NGRID)   // 96000  node-grid rows

// ---------------------------------------------------------------------------
// Device scratch (static __device__ globals -- the allowed scratch mechanism)
// ---------------------------------------------------------------------------
__device__ float g_grid0[NGRID * 3];
__device__ float g_node_grid[R_N * 3];
__device__ float g_kb_sh[144 * HID];
__device__ float g_fk[NLAYERS * 144 * HID];
__device__ float g_poly[R_E * 14];
__device__ float g_buf1[R_E * HID];    // kb_sp hidden; later reused as MLP hidden (96000x512)
__device__ float g_kb_sp[R_E * HID];
__device__ float g_h[R_N * HID];
__device__ float g_agg[R_N * HID];
__device__ float g_hn[R_N * HID];
__device__ float g_readout[R_N * (OUT_S + OUT_V)];

__device__ __forceinline__ float gelu_f(float x) {
    return 0.5f * x * (1.0f + erff(x * 0.70710678118654752440f));
}

// ---------------------------------------------------------------------------
// Setup kernels
// ---------------------------------------------------------------------------
__global__ void grid0_kernel() {
    int i = threadIdx.x;
    if (i < NGRID) {
        const float golden = 1.61803398874989484820f;
        float fi = (float)i;
        float theta = 6.28318530717958647692f * fi / golden;
        float z = 1.0f - (2.0f * fi + 1.0f) / (float)NGRID;
        float r = sqrtf(fmaxf(1.0f - z * z, 0.0f));
        g_grid0[i * 3 + 0] = r * cosf(theta);
        g_grid0[i * 3 + 1] = r * sinf(theta);
        g_grid0[i * 3 + 2] = z;
    }
}

// kb_sh: 144 rows (p,o), MLP 3 -> 128 (gelu) -> 128 (gelu)
__global__ void kbsh_kernel(const float* __restrict__ Wsh1, const float* __restrict__ bsh1,
                            const float* __restrict__ Wsh2, const float* __restrict__ bsh2) {
    int row = blockIdx.x;           // p*12 + o
    int p = row / NGRID, o = row % NGRID;
    int c = threadIdx.x;            // 128
    __shared__ float h1[HID];
    float t = g_grid0[p*3+0]*g_grid0[o*3+0] + g_grid0[p*3+1]*g_grid0[o*3+1] + g_grid0[p*3+2]*g_grid0[o*3+2];
    float t2 = t * t, t3 = t2 * t;
    float v = t * Wsh1[c] + t2 * Wsh1[HID + c] + t3 * Wsh1[2*HID + c] + bsh1[c];
    h1[c] = gelu_f(v);
    __syncthreads();
    float acc = bsh2[c];
    #pragma unroll 8
    for (int k = 0; k < HID; k++) acc = fmaf(h1[k], Wsh2[k*HID + c], acc);
    g_kb_sh[row * HID + c] = gelu_f(acc);
}

// fk[l] = kb_sh @ Wfk[l]  (3 * 144 rows)
__global__ void fk_kernel(const float* __restrict__ Wfk) {
    int blk = blockIdx.x;
    int l = blk / 144, row = blk % 144;
    int c = threadIdx.x;
    __shared__ float r128[HID];
    r128[c] = g_kb_sh[row * HID + c];
    __syncthreads();
    const float* W = Wfk + l * HID * HID;
    float acc = 0.0f;
    #pragma unroll 8
    for (int k = 0; k < HID; k++) acc = fmaf(r128[k], W[k*HID + c], acc);
    g_fk[l * 144 * HID + row * HID + c] = acc;
}

// node_grid + initial embedding h0 = f @ Wemb
__global__ void embed_kernel(const float* __restrict__ x, const float* __restrict__ vec,
                             const float* __restrict__ Q, const int* __restrict__ batch,
                             const float* __restrict__ Wemb) {
    int v = blockIdx.x;
    int c = threadIdx.x;  // 128
    __shared__ float sQ[9], sx[IN_S], sv[6], sng[NGRID * 3];
    int b = batch[v];
    if (c < 9)  sQ[c] = Q[b * 9 + c];
    if (c < IN_S) sx[c] = x[v * IN_S + c];
    if (c < 6)  sv[c] = vec[v * 6 + c];
    __syncthreads();
    if (c < NGRID * 3) {
        int n = c / 3, i = c % 3;
        float t = sQ[i*3+0]*g_grid0[n*3+0] + sQ[i*3+1]*g_grid0[n*3+1] + sQ[i*3+2]*g_grid0[n*3+2];
        sng[c] = t;
        g_node_grid[v * NGRID * 3 + c] = t;
    }
    __syncthreads();
    float s = 0.0f;
    #pragma unroll
    for (int j = 0; j < IN_S; j++) s = fmaf(sx[j], Wemb[j * HID + c], s);
    float w16 = Wemb[IN_S * HID + c];
    float w17 = Wemb[(IN_S + 1) * HID + c];
    #pragma unroll
    for (int n = 0; n < NGRID; n++) {
        float xv0 = sv[0]*sng[n*3+0] + sv[1]*sng[n*3+1] + sv[2]*sng[n*3+2];
        float xv1 = sv[3]*sng[n*3+0] + sv[4]*sng[n*3+1] + sv[5]*sng[n*3+2];
        g_h[(v * NGRID + n) * HID + c] = s + xv0 * w16 + xv1 * w17;
    }
}

// attr_sp -> degree-3 poly features (14), per edge-grid row
__global__ void poly_kernel(const float* __restrict__ pos,
                            const int* __restrict__ send, const int* __restrict__ recv) {
    int r = blockIdx.x * 256 + threadIdx.x;
    if (r >= R_E) return;
    int e = r / NGRID, o = r % NGRID;
    int s = send[e], rc = recv[e];
    float rx = pos[s*3+0] - pos[rc*3+0];
    float ry = pos[s*3+1] - pos[rc*3+1];
    float rz = pos[s*3+2] - pos[rc*3+2];
    const float* g = &g_node_grid[(rc * NGRID + o) * 3];
    float g0 = g[0], g1 = g[1], g2 = g[2];
    float inv1 = rx*g0 + ry*g1 + rz*g2;
    float dx = rx - inv1*g0, dy = ry - inv1*g1, dz = rz - inv1*g2;
    float inv2 = sqrtf(dx*dx + dy*dy + dz*dz);
    float* p = &g_poly[(size_t)r * 14];
    float a = inv1, b = inv2;
    p[0]=a; p[1]=b;
    p[2]=a*a; p[3]=a*b; p[4]=b*a; p[5]=b*b;
    p[6]=p[2]*a; p[7]=p[2]*b; p[8]=p[3]*a; p[9]=p[3]*b;
    p[10]=p[4]*a; p[11]=p[4]*b; p[12]=p[5]*a; p[13]=p[5]*b;
}

// ---------------------------------------------------------------------------
// Generic fp32 GEMM: C[M,N] = epilogue(A[M,K] @ B[K,N] + bias)
// BM=BN=128, BK=8, 256 threads, 8x8 per thread. M%128==0, N%128==0 assumed.
// MODE: 0 = bias, 1 = bias+gelu, 2 = bias + add addsrc
// ---------------------------------------------------------------------------
template<int MODE>
__global__ __launch_bounds__(256)
void sgemm_kernel(const float* __restrict__ A, const float* __restrict__ Bm,
                  const float* __restrict__ bias, const float* __restrict__ addsrc,
                  float* __restrict__ C, int M, int N, int K) {
    __shared__ __align__(16) float As[8][128];
    __shared__ __align__(16) float Bs[8][128];
    int tid = threadIdx.x;
    int row0 = blockIdx.y * 128;
    int col0 = blockIdx.x * 128;
    int tr = (tid / 16) * 8;
    int tc = (tid % 16) * 8;
    float acc[8][8];
    #pragma unroll
    for (int i = 0; i < 8; i++)
        #pragma unroll
        for (int j = 0; j < 8; j++) acc[i][j] = 0.0f;

    for (int k0 = 0; k0 < K; k0 += 8) {
        #pragma unroll
        for (int i = tid; i < 128 * 8; i += 256) {
            int m = i >> 3, kk = i & 7;
            int k = k0 + kk;
            As[kk][m] = (k < K) ? A[(size_t)(row0 + m) * K + k] : 0.0f;
        }
        #pragma unroll
        for (int i = tid; i < 8 * 128; i += 256) {
            int kk = i >> 7, n = i & 127;
            int k = k0 + kk;
            Bs[kk][n] = (k < K) ? Bm[(size_t)k * N + col0 + n] : 0.0f;
        }
        __syncthreads();
        #pragma unroll
        for (int kk = 0; kk < 8; kk++) {
            float4 a0 = *reinterpret_cast<const float4*>(&As[kk][tr]);
            float4 a1 = *reinterpret_cast<const float4*>(&As[kk][tr + 4]);
            float4 b0 = *reinterpret_cast<const float4*>(&Bs[kk][tc]);
            float4 b1 = *reinterpret_cast<const float4*>(&Bs[kk][tc + 4]);
            float a[8] = {a0.x,a0.y,a0.z,a0.w,a1.x,a1.y,a1.z,a1.w};
            float b[8] = {b0.x,b0.y,b0.z,b0.w,b1.x,b1.y,b1.z,b1.w};
            #pragma unroll
            for (int i = 0; i < 8; i++)
                #pragma unroll
                for (int j = 0; j < 8; j++) acc[i][j] = fmaf(a[i], b[j], acc[i][j]);
        }
        __syncthreads();
    }
    #pragma unroll
    for (int i = 0; i < 8; i++) {
        int r = row0 + tr + i;
        #pragma unroll
        for (int j = 0; j < 8; j++) {
            int cc = col0 + tc + j;
            float v = acc[i][j] + bias[cc];
            if (MODE == 1) v = gelu_f(v);
            if (MODE == 2) v += addsrc[(size_t)r * N + cc];
            C[(size_t)r * N + cc] = v;
        }
    }
}

// ---------------------------------------------------------------------------
// Fused: k = kb_sp @ Wk[l]; msg = h[send]*k; atomicAdd agg[recv]
// M = R_E (div by 128), K = N = 128.
// ---------------------------------------------------------------------------
__global__ __launch_bounds__(256)
void kconv_kernel(const float* __restrict__ kb, const float* __restrict__ Wk,
                  const float* __restrict__ h, float* __restrict__ agg,
                  const int* __restrict__ send, const int* __restrict__ recv) {
    __shared__ __align__(16) float As[8][128];
    __shared__ __align__(16) float Bs[8][128];
    __shared__ int hrow[128], arow[128];
    int tid = threadIdx.x;
    int row0 = blockIdx.x * 128;
    int tr = (tid / 16) * 8;
    int tc = (tid % 16) * 8;
    if (tid < 128) {
        int r = row0 + tid;
        int e = r / NGRID, o = r % NGRID;
        hrow[tid] = send[e] * NGRID + o;
        arow[tid] = recv[e] * NGRID + o;
    }
    float acc[8][8];
    #pragma unroll
    for (int i = 0; i < 8; i++)
        #pragma unroll
        for (int j = 0; j < 8; j++) acc[i][j] = 0.0f;

    for (int k0 = 0; k0 < 128; k0 += 8) {
        #pragma unroll
        for (int i = tid; i < 128 * 8; i += 256) {
            int m = i >> 3, kk = i & 7;
            As[kk][m] = kb[(size_t)(row0 + m) * 128 + k0 + kk];
        }
        #pragma unroll
        for (int i = tid; i < 8 * 128; i += 256) {
            int kk = i >> 7, n = i & 127;
            Bs[kk][n] = Wk[(k0 + kk) * 128 + n];
        }
        __syncthreads();
        #pragma unroll
        for (int kk = 0; kk < 8; kk++) {
            float4 a0 = *reinterpret_cast<const float4*>(&As[kk][tr]);
            float4 a1 = *reinterpret_cast<const float4*>(&As[kk][tr + 4]);
            float4 b0 = *reinterpret_cast<const float4*>(&Bs[kk][tc]);
            float4 b1 = *reinterpret_cast<const float4*>(&Bs[kk][tc + 4]);
            float a[8] = {a0.x,a0.y,a0.z,a0.w,a1.x,a1.y,a1.z,a1.w};
            float b[8] = {b0.x,b0.y,b0.z,b0.w,b1.x,b1.y,b1.z,b1.w};
            #pragma unroll
            for (int i = 0; i < 8; i++)
                #pragma unroll
                for (int j = 0; j < 8; j++) acc[i][j] = fmaf(a[i], b[j], acc[i][j]);
        }
        __syncthreads();
    }
    #pragma unroll
    for (int i = 0; i < 8; i++) {
        int hb = hrow[tr + i] * 128 + tc;
        int ab = arow[tr + i] * 128 + tc;
        float4 h0 = *reinterpret_cast<const float4*>(&h[hb]);
        float4 h1 = *reinterpret_cast<const float4*>(&h[hb + 4]);
        float hv[8] = {h0.x,h0.y,h0.z,h0.w,h1.x,h1.y,h1.z,h1.w};
        #pragma unroll
        for (int j = 0; j < 8; j++) {
            atomicAdd(&agg[ab + j], acc[i][j] * hv[j]);
        }
    }
}

// ---------------------------------------------------------------------------
// x2 = einsum('boc,poc->bpc', agg, fk)/NGRID + bconv ; LayerNorm -> hn
// one block per node, 128 threads (channel)
// ---------------------------------------------------------------------------
__global__ void conv_ln_kernel(const float* __restrict__ agg, const float* __restrict__ fk,
                               const float* __restrict__ bconv, const float* __restrict__ lng,
                               const float* __restrict__ lnb, float* __restrict__ hn) {
    int v = blockIdx.x;
    int c = threadIdx.x;
    float a[NGRID];
    #pragma unroll
    for (int o = 0; o < NGRID; o++) a[o] = agg[(v * NGRID + o) * HID + c];
    __shared__ float warp_red[4];
    __shared__ float bc_val;
    int lane = c & 31, wid = c >> 5;
    float gc = lng[c], bbc = lnb[c], bcv = bconv[c];
    for (int p = 0; p < NGRID; p++) {
        float s = 0.0f;
        #pragma unroll
        for (int o = 0; o < NGRID; o++) s = fmaf(a[o], fk[(p * NGRID + o) * HID + c], s);
        s = s * (1.0f / (float)NGRID) + bcv;
        // mean
        float t = s;
        #pragma unroll
        for (int off = 16; off > 0; off >>= 1) t += __shfl_xor_sync(0xffffffffu, t, off);
        if (lane == 0) warp_red[wid] = t;
        __syncthreads();
        if (c == 0) bc_val = (warp_red[0] + warp_red[1] + warp_red[2] + warp_red[3]) * (1.0f / HID);
        __syncthreads();
        float mu = bc_val;
        float d = s - mu;
        t = d * d;
        #pragma unroll
        for (int off = 16; off > 0; off >>= 1) t += __shfl_xor_sync(0xffffffffu, t, off);
        if (lane == 0) warp_red[wid] = t;
        __syncthreads();
        if (c == 0) bc_val = rsqrtf((warp_red[0] + warp_red[1] + warp_red[2] + warp_red[3]) * (1.0f / HID) + 1e-5f);
        __syncthreads();
        float rstd = bc_val;
        hn[(v * NGRID + p) * HID + c] = d * rstd * gc + bbc;
        __syncthreads();
    }
}

// ---------------------------------------------------------------------------
// readout += (h @ Wro[l] + bro[l]) / L
// 16 rows per block, 160 threads (144 active in compute)
// ---------------------------------------------------------------------------
__global__ void readout_kernel(const float* __restrict__ h, const float* __restrict__ Wro,
                               const float* __restrict__ bro, float* __restrict__ ro) {
    __shared__ float hs[16 * 129];
    int tid = threadIdx.x;
    int r0 = blockIdx.x * 16;
    for (int i = tid; i < 16 * 128; i += 160) {
        int row = i >> 7, cc = i & 127;
        hs[row * 129 + cc] = h[(size_t)(r0 + row) * HID + cc];
    }
    __syncthreads();
    if (tid < 16 * 9) {
        int row = tid / 9, oc = tid % 9;
        float acc = bro[oc];
        #pragma unroll 8
        for (int cc = 0; cc < 128; cc++) acc = fmaf(hs[row * 129 + cc], Wro[cc * 9 + oc], acc);
        int idx = (r0 + row) * 9 + oc;
        ro[idx] += acc * (1.0f / (float)NLAYERS);
    }
}

// ---------------------------------------------------------------------------
// Final pooling: out_s[B,8], out_v[B,1,3]
// ---------------------------------------------------------------------------
__global__ void finalize_kernel(const int* __restrict__ batch, float* __restrict__ out) {
    int v = blockIdx.x * 256 + threadIdx.x;
    if (v >= N_NODES) return;
    float ssum[OUT_S] = {0,0,0,0,0,0,0,0};
    float vsum[3] = {0,0,0};
    for (int n = 0; n < NGRID; n++) {
        const float* rr = &g_readout[(v * NGRID + n) * 9];
        #pragma unroll
        for (int j = 0; j < OUT_S; j++) ssum[j] += rr[j];
        float rv = rr[OUT_S];
        const float* g = &g_node_grid[(v * NGRID + n) * 3];
        vsum[0] += rv * g[0]; vsum[1] += rv * g[1]; vsum[2] += rv * g[2];
    }
    int b = batch[v];
    #pragma unroll
    for (int j = 0; j < OUT_S; j++) atomicAdd(&out[b * OUT_S + j], ssum[j] * (1.0f / NGRID));
    #pragma unroll
    for (int d = 0; d < 3; d++) atomicAdd(&out[NBATCH * OUT_S + b * 3 + d], vsum[d] * (1.0f / NGRID));
}

// grid-stride zeroing (robust to any grid size)
__global__ void zero_kernel(float* __restrict__ p, int n) {
    for (int i = blockIdx.x * blockDim.x + threadIdx.x; i < n; i += gridDim.x * blockDim.x)
        p[i] = 0.0f;
}

__global__ void zero_sym_kernel(int which) {
    // which 0: g_agg, 1: g_readout
    int stride = gridDim.x * blockDim.x;
    if (which == 0) {
        for (int i = blockIdx.x * blockDim.x + threadIdx.x; i < R_N * HID; i += stride) g_agg[i] = 0.0f;
    } else {
        for (int i = blockIdx.x * blockDim.x + threadIdx.x; i < R_N * 9; i += stride) g_readout[i] = 0.0f;
    }
}

// ---------------------------------------------------------------------------
// Host launcher
// ---------------------------------------------------------------------------
extern "C" void kernel_launch(void* const* d_in, const int* in_sizes, int n_in,
                              void* d_out, int out_size) {
    const float* x      = (const float*)d_in[0];
    const float* vec    = (const float*)d_in[1];
    const float* pos    = (const float*)d_in[2];
    const float* Q      = (const float*)d_in[3];
    const float* Wsp1   = (const float*)d_in[4];
    const float* bsp1   = (const float*)d_in[5];
    const float* Wsp2   = (const float*)d_in[6];
    const float* bsp2   = (const float*)d_in[7];
    const float* Wsh1   = (const float*)d_in[8];
    const float* bsh1   = (const float*)d_in[9];
    const float* Wsh2   = (const float*)d_in[10];
    const float* bsh2   = (const float*)d_in[11];
    const float* Wemb   = (const float*)d_in[12];
    const float* Wk     = (const float*)d_in[13];
    const float* Wfk    = (const float*)d_in[14];
    const float* bconv  = (const float*)d_in[15];
    const float* ln_g   = (const float*)d_in[16];
    const float* ln_b   = (const float*)d_in[17];
    const float* W1     = (const float*)d_in[18];
    const float* b1     = (const float*)d_in[19];
    const float* W2     = (const float*)d_in[20];
    const float* b2     = (const float*)d_in[21];
    const float* Wro    = (const float*)d_in[22];
    const float* bro    = (const float*)d_in[23];
    const int*   eidx   = (const int*)d_in[24];
    const int*   batch  = (const int*)d_in[25];
    float* out = (float*)d_out;

    const int* send = eidx;
    const int* recv = eidx + N_EDGES;

    // resolve device-symbol addresses (host-side lookup; not an allocation)
    float *p_poly, *p_buf1, *p_kb_sp, *p_h, *p_agg, *p_hn, *p_readout, *p_fk;
    cudaGetSymbolAddress((void**)&p_poly,   g_poly);
    cudaGetSymbolAddress((void**)&p_buf1,   g_buf1);
    cudaGetSymbolAddress((void**)&p_kb_sp,  g_kb_sp);
    cudaGetSymbolAddress((void**)&p_h,      g_h);
    cudaGetSymbolAddress((void**)&p_agg,    g_agg);
    cudaGetSymbolAddress((void**)&p_hn,     g_hn);
    cudaGetSymbolAddress((void**)&p_readout,g_readout);
    cudaGetSymbolAddress((void**)&p_fk,     g_fk);

    // setup
    grid0_kernel<<<1, 32>>>();
    kbsh_kernel<<<144, 128>>>(Wsh1, bsh1, Wsh2, bsh2);
    fk_kernel<<<NLAYERS * 144, 128>>>(Wfk);
    embed_kernel<<<N_NODES, 128>>>(x, vec, Q, batch, Wemb);
    poly_kernel<<<(R_E + 255) / 256, 256>>>(pos, send, recv);

    // kb_sp MLP: [R_E x 14] -> 128 (gelu) -> 128 (gelu)
    sgemm_kernel<1><<<dim3(1, R_E / 128), 256>>>(p_poly, Wsp1, bsp1, nullptr, p_buf1, R_E, 128, 14);
    sgemm_kernel<1><<<dim3(1, R_E / 128), 256>>>(p_buf1, Wsp2, bsp2, nullptr, p_kb_sp, R_E, 128, 128);

    zero_sym_kernel<<<1024, 256>>>(1);

    for (int l = 0; l < NLAYERS; l++) {
        zero_sym_kernel<<<4096, 256>>>(0);
        kconv_kernel<<<R_E / 128, 256>>>(p_kb_sp, Wk + l * HID * HID, p_h, p_agg, send, recv);
        conv_ln_kernel<<<N_NODES, 128>>>(p_agg, p_fk + l * 144 * HID,
                                         bconv + l * HID, ln_g + l * HID, ln_b + l * HID, p_hn);
        // MLP: hn @ W1 (128->512) gelu -> buf1 ; buf1 @ W2 (512->128) + b2 + h -> h
        sgemm_kernel<1><<<dim3(4, R_N / 128), 256>>>(p_hn, W1 + l * HID * WIDE * HID,
                                                     b1 + l * WIDE * HID, nullptr, p_buf1,
                                                     R_N, WIDE * HID, HID);
        sgemm_kernel<2><<<dim3(1, R_N / 128), 256>>>(p_buf1, W2 + l * WIDE * HID * HID,
                                                     b2 + l * HID, p_h, p_h,
                                                     R_N, HID, WIDE * HID);
        readout_kernel<<<R_N / 16, 160>>>(p_h, Wro + l * HID * 9, bro + l * 9, p_readout);
    }

    // zero the FULL output (704 floats) before atomics accumulate into it
    int out_elems = NBATCH * OUT_S + NBATCH * 3;
    zero_kernel<<<(out_elems + 255) / 256, 256>>>(out, out_elems);
    finalize_kernel<<<(N_NODES + 255) / 256, 256>>>(batch, out);
}

// round 8
// speedup vs baseline: 1.6016x; 1.6016x over previous
#include <cuda_runtime.h>
#include <cuda_bf16.h>
#include <math.h>
#include <stdint.h>

#define N_NODES 8000
#define N_EDGES 64000
#define NBATCH  64
#define NGRID   12
#define HID     128
#define NLAYERS 3
#define IN_S    16
#define OUT_S   8
#define WIDE    4
#define R_E (N_EDGES * NGRID)   // 768000
#define R_N (N_NODES * NGRID)   // 96000

// ---------------------------------------------------------------------------
// Device scratch
// ---------------------------------------------------------------------------
__device__ float g_grid0[NGRID * 3];
__device__ float g_node_grid[R_N * 3];
__device__ float g_kb_sh[144 * HID];
__device__ float g_fk[NLAYERS * 144 * HID];
__device__ float g_poly[R_E * 14];
__device__ float g_buf1[R_E * HID];    // kb_sp hidden; reused as MLP hidden (96000x512)
__device__ float g_kb_sp[R_E * HID];
__device__ float g_h[R_N * HID];
__device__ float g_agg[R_N * HID];
__device__ float g_hn[R_N * HID];
__device__ float g_readout[R_N * (OUT_S + 1)];

__device__ __forceinline__ float gelu_f(float x) {
    return 0.5f * x * (1.0f + erff(x * 0.70710678118654752440f));
}
__device__ __forceinline__ uint32_t sptr(const void* p) {
    uint32_t a;
    asm("{ .reg .u64 t; cvta.to.shared.u64 t, %1; cvt.u32.u64 %0, t; }" : "=r"(a) : "l"(p));
    return a;
}
__device__ __forceinline__ void ldsm_x4(uint32_t* r, uint32_t addr) {
    asm volatile("ldmatrix.sync.aligned.m8n8.x4.shared.b16 {%0,%1,%2,%3}, [%4];"
                 : "=r"(r[0]), "=r"(r[1]), "=r"(r[2]), "=r"(r[3]) : "r"(addr));
}
__device__ __forceinline__ void ldsm_x2t(uint32_t* r, uint32_t addr) {
    asm volatile("ldmatrix.sync.aligned.m8n8.x2.trans.shared.b16 {%0,%1}, [%2];"
                 : "=r"(r[0]), "=r"(r[1]) : "r"(addr));
}
__device__ __forceinline__ void mma16816(float* c, const uint32_t* a, const uint32_t* b) {
    asm volatile("mma.sync.aligned.m16n8k16.row.col.f32.bf16.bf16.f32 "
                 "{%0,%1,%2,%3}, {%4,%5,%6,%7}, {%8,%9}, {%0,%1,%2,%3};"
                 : "+f"(c[0]), "+f"(c[1]), "+f"(c[2]), "+f"(c[3])
                 : "r"(a[0]), "r"(a[1]), "r"(a[2]), "r"(a[3]), "r"(b[0]), "r"(b[1]));
}
__device__ __forceinline__ void split2(float v, unsigned short& h, unsigned short& l) {
    __nv_bfloat16 hb = __float2bfloat16(v);
    h = __bfloat16_as_ushort(hb);
    l = __bfloat16_as_ushort(__float2bfloat16(v - __bfloat162float(hb)));
}

// ---------------------------------------------------------------------------
// HMMA GEMM: C[128 x 128-per-nb] = A[128 x Ktrue] @ B[Ktrue x N] (+epilogue)
// split-bf16 3-pass (hi*hi + hi*lo + lo*hi), fp32 accumulate.
// 256 threads = 8 warps (4 m x 2 n), warp tile 32x64, mma m16n8k16.
// MODE 0: C = gelu(acc + bias[col])
// MODE 1: kconv: atomicAdd(C[arow*128+col], acc * aux[hrow*128+col])
// MODE 2: C = acc + bias[col] + aux[row*N+col]   (residual)
// ---------------------------------------------------------------------------
template<int MODE>
__global__ __launch_bounds__(256, 2)
void hmma_gemm(const float* __restrict__ A, const float* __restrict__ Bm,
               const float* __restrict__ bias, const float* __restrict__ aux,
               float* __restrict__ C,
               int Ktrue, int lda, int N,
               const int* __restrict__ send, const int* __restrict__ recv)
{
    __shared__ __align__(16) unsigned short As_h[128][40], As_l[128][40];
    __shared__ __align__(16) unsigned short Bs_h[32][136], Bs_l[32][136];
    __shared__ int hrow[128], arow[128];

    const int tid = threadIdx.x;
    const int l   = tid & 31;
    const int wid = tid >> 5;
    const int wm  = wid & 3;       // 0..3 -> m offset wm*32
    const int wn  = wid >> 2;      // 0..1 -> n offset wn*64
    const int row0 = blockIdx.x * 128;
    const int nbase = blockIdx.y * 128;

    if (MODE == 1 && tid < 128) {
        int r = row0 + tid;
        int e = r / NGRID, o = r - e * NGRID;
        hrow[tid] = send[e] * NGRID + o;
        arow[tid] = recv[e] * NGRID + o;
    }

    float acc[2][8][4];
    #pragma unroll
    for (int i = 0; i < 2; i++)
        #pragma unroll
        for (int j = 0; j < 8; j++)
            #pragma unroll
            for (int q = 0; q < 4; q++) acc[i][j][q] = 0.0f;

    // ldmatrix lane addressing offsets
    const int a_roff = (l & 7) + (((l >> 3) & 1) << 3);
    const int a_coff = (l >> 4) << 3;
    const int b_koff = l & 15;

    const int Kpad = (Ktrue + 31) & ~31;
    for (int k0 = 0; k0 < Kpad; k0 += 32) {
        // fill A tile 128x32 (split bf16)
        #pragma unroll 4
        for (int i = tid; i < 128 * 32; i += 256) {
            int r = i >> 5, c = i & 31;
            int k = k0 + c;
            float v = (k < Ktrue) ? A[(size_t)(row0 + r) * lda + k] : 0.0f;
            split2(v, As_h[r][c], As_l[r][c]);
        }
        // fill B tile 32x128 (split bf16)
        #pragma unroll 4
        for (int i = tid; i < 32 * 128; i += 256) {
            int kk = i >> 7, n = i & 127;
            int k = k0 + kk;
            float v = (k < Ktrue) ? Bm[(size_t)k * N + nbase + n] : 0.0f;
            split2(v, Bs_h[kk][n], Bs_l[kk][n]);
        }
        __syncthreads();

        #pragma unroll
        for (int ks = 0; ks < 2; ks++) {
            uint32_t ah[2][4], al[2][4];
            #pragma unroll
            for (int tm = 0; tm < 2; tm++) {
                int rr = wm * 32 + tm * 16 + a_roff;
                int cc = ks * 16 + a_coff;
                ldsm_x4(ah[tm], sptr(&As_h[rr][cc]));
                ldsm_x4(al[tm], sptr(&As_l[rr][cc]));
            }
            #pragma unroll
            for (int tn = 0; tn < 8; tn++) {
                uint32_t bh[2], bl[2];
                int kk = ks * 16 + b_koff;
                int nn = wn * 64 + tn * 8;
                ldsm_x2t(bh, sptr(&Bs_h[kk][nn]));
                ldsm_x2t(bl, sptr(&Bs_l[kk][nn]));
                #pragma unroll
                for (int tm = 0; tm < 2; tm++) {
                    mma16816(acc[tm][tn], ah[tm], bh);
                    mma16816(acc[tm][tn], ah[tm], bl);
                    mma16816(acc[tm][tn], al[tm], bh);
                }
            }
        }
        __syncthreads();
    }

    // epilogue
    #pragma unroll
    for (int tm = 0; tm < 2; tm++) {
        int lr0 = wm * 32 + tm * 16 + (l >> 2);
        int lr1 = lr0 + 8;
        #pragma unroll
        for (int tn = 0; tn < 8; tn++) {
            int cc = nbase + wn * 64 + tn * 8 + (l & 3) * 2;
            float* a4 = acc[tm][tn];
            if (MODE == 0) {
                size_t o0 = (size_t)(row0 + lr0) * N + cc;
                size_t o1 = (size_t)(row0 + lr1) * N + cc;
                C[o0]     = gelu_f(a4[0] + bias[cc]);
                C[o0 + 1] = gelu_f(a4[1] + bias[cc + 1]);
                C[o1]     = gelu_f(a4[2] + bias[cc]);
                C[o1 + 1] = gelu_f(a4[3] + bias[cc + 1]);
            } else if (MODE == 1) {
                int h0 = hrow[lr0] * 128 + cc, g0 = arow[lr0] * 128 + cc;
                int h1 = hrow[lr1] * 128 + cc, g1 = arow[lr1] * 128 + cc;
                float2 hv0 = *(const float2*)(aux + h0);
                float2 hv1 = *(const float2*)(aux + h1);
                atomicAdd(&C[g0],     a4[0] * hv0.x);
                atomicAdd(&C[g0 + 1], a4[1] * hv0.y);
                atomicAdd(&C[g1],     a4[2] * hv1.x);
                atomicAdd(&C[g1 + 1], a4[3] * hv1.y);
            } else {
                size_t o0 = (size_t)(row0 + lr0) * N + cc;
                size_t o1 = (size_t)(row0 + lr1) * N + cc;
                C[o0]     = a4[0] + bias[cc]     + aux[o0];
                C[o0 + 1] = a4[1] + bias[cc + 1] + aux[o0 + 1];
                C[o1]     = a4[2] + bias[cc]     + aux[o1];
                C[o1 + 1] = a4[3] + bias[cc + 1] + aux[o1 + 1];
            }
        }
    }
}

// ---------------------------------------------------------------------------
// Setup / small kernels (unchanged from the passing fp32 version)
// ---------------------------------------------------------------------------
__global__ void grid0_kernel() {
    int i = threadIdx.x;
    if (i < NGRID) {
        const float golden = 1.61803398874989484820f;
        float fi = (float)i;
        float theta = 6.28318530717958647692f * fi / golden;
        float z = 1.0f - (2.0f * fi + 1.0f) / (float)NGRID;
        float r = sqrtf(fmaxf(1.0f - z * z, 0.0f));
        g_grid0[i*3+0] = r * cosf(theta); g_grid0[i*3+1] = r * sinf(theta); g_grid0[i*3+2] = z;
    }
}

__global__ void kbsh_kernel(const float* __restrict__ Wsh1, const float* __restrict__ bsh1,
                            const float* __restrict__ Wsh2, const float* __restrict__ bsh2) {
    int row = blockIdx.x;
    int p = row / NGRID, o = row % NGRID;
    int c = threadIdx.x;
    __shared__ float h1[HID];
    float t = g_grid0[p*3+0]*g_grid0[o*3+0] + g_grid0[p*3+1]*g_grid0[o*3+1] + g_grid0[p*3+2]*g_grid0[o*3+2];
    float v = t*Wsh1[c] + t*t*Wsh1[HID+c] + t*t*t*Wsh1[2*HID+c] + bsh1[c];
    h1[c] = gelu_f(v);
    __syncthreads();
    float acc = bsh2[c];
    #pragma unroll 8
    for (int k = 0; k < HID; k++) acc = fmaf(h1[k], Wsh2[k*HID + c], acc);
    g_kb_sh[row * HID + c] = gelu_f(acc);
}

__global__ void fk_kernel(const float* __restrict__ Wfk) {
    int blk = blockIdx.x;
    int ll = blk / 144, row = blk % 144;
    int c = threadIdx.x;
    __shared__ float r128[HID];
    r128[c] = g_kb_sh[row * HID + c];
    __syncthreads();
    const float* W = Wfk + ll * HID * HID;
    float acc = 0.0f;
    #pragma unroll 8
    for (int k = 0; k < HID; k++) acc = fmaf(r128[k], W[k*HID + c], acc);
    g_fk[ll * 144 * HID + row * HID + c] = acc;
}

__global__ void embed_kernel(const float* __restrict__ x, const float* __restrict__ vec,
                             const float* __restrict__ Q, const int* __restrict__ batch,
                             const float* __restrict__ Wemb) {
    int v = blockIdx.x;
    int c = threadIdx.x;
    __shared__ float sQ[9], sx[IN_S], sv[6], sng[NGRID * 3];
    int b = batch[v];
    if (c < 9)  sQ[c] = Q[b * 9 + c];
    if (c < IN_S) sx[c] = x[v * IN_S + c];
    if (c < 6)  sv[c] = vec[v * 6 + c];
    __syncthreads();
    if (c < NGRID * 3) {
        int n = c / 3, i = c % 3;
        float t = sQ[i*3+0]*g_grid0[n*3+0] + sQ[i*3+1]*g_grid0[n*3+1] + sQ[i*3+2]*g_grid0[n*3+2];
        sng[c] = t;
        g_node_grid[v * NGRID * 3 + c] = t;
    }
    __syncthreads();
    float s = 0.0f;
    #pragma unroll
    for (int j = 0; j < IN_S; j++) s = fmaf(sx[j], Wemb[j * HID + c], s);
    float w16 = Wemb[IN_S * HID + c], w17 = Wemb[(IN_S + 1) * HID + c];
    #pragma unroll
    for (int n = 0; n < NGRID; n++) {
        float xv0 = sv[0]*sng[n*3+0] + sv[1]*sng[n*3+1] + sv[2]*sng[n*3+2];
        float xv1 = sv[3]*sng[n*3+0] + sv[4]*sng[n*3+1] + sv[5]*sng[n*3+2];
        g_h[(v * NGRID + n) * HID + c] = s + xv0 * w16 + xv1 * w17;
    }
}

__global__ void poly_kernel(const float* __restrict__ pos,
                            const int* __restrict__ send, const int* __restrict__ recv) {
    int r = blockIdx.x * 256 + threadIdx.x;
    if (r >= R_E) return;
    int e = r / NGRID, o = r % NGRID;
    int s = send[e], rc = recv[e];
    float rx = pos[s*3+0]-pos[rc*3+0], ry = pos[s*3+1]-pos[rc*3+1], rz = pos[s*3+2]-pos[rc*3+2];
    const float* g = &g_node_grid[(rc * NGRID + o) * 3];
    float inv1 = rx*g[0] + ry*g[1] + rz*g[2];
    float dx = rx-inv1*g[0], dy = ry-inv1*g[1], dz = rz-inv1*g[2];
    float inv2 = sqrtf(dx*dx + dy*dy + dz*dz);
    float* p = &g_poly[(size_t)r * 14];
    float a = inv1, b = inv2;
    p[0]=a; p[1]=b; p[2]=a*a; p[3]=a*b; p[4]=b*a; p[5]=b*b;
    p[6]=p[2]*a; p[7]=p[2]*b; p[8]=p[3]*a; p[9]=p[3]*b;
    p[10]=p[4]*a; p[11]=p[4]*b; p[12]=p[5]*a; p[13]=p[5]*b;
}

__global__ void conv_ln_kernel(const float* __restrict__ agg, const float* __restrict__ fk,
                               const float* __restrict__ bconv, const float* __restrict__ lng,
                               const float* __restrict__ lnb, float* __restrict__ hn) {
    int v = blockIdx.x;
    int c = threadIdx.x;
    float a[NGRID];
    #pragma unroll
    for (int o = 0; o < NGRID; o++) a[o] = agg[(v * NGRID + o) * HID + c];
    __shared__ float warp_red[4];
    __shared__ float bc_val;
    int lane = c & 31, wd = c >> 5;
    float gc = lng[c], bbc = lnb[c], bcv = bconv[c];
    for (int p = 0; p < NGRID; p++) {
        float s = 0.0f;
        #pragma unroll
        for (int o = 0; o < NGRID; o++) s = fmaf(a[o], fk[(p * NGRID + o) * HID + c], s);
        s = s * (1.0f / NGRID) + bcv;
        float t = s;
        #pragma unroll
        for (int off = 16; off > 0; off >>= 1) t += __shfl_xor_sync(0xffffffffu, t, off);
        if (lane == 0) warp_red[wd] = t;
        __syncthreads();
        if (c == 0) bc_val = (warp_red[0]+warp_red[1]+warp_red[2]+warp_red[3]) * (1.0f / HID);
        __syncthreads();
        float mu = bc_val, d = s - mu;
        t = d * d;
        #pragma unroll
        for (int off = 16; off > 0; off >>= 1) t += __shfl_xor_sync(0xffffffffu, t, off);
        if (lane == 0) warp_red[wd] = t;
        __syncthreads();
        if (c == 0) bc_val = rsqrtf((warp_red[0]+warp_red[1]+warp_red[2]+warp_red[3]) * (1.0f/HID) + 1e-5f);
        __syncthreads();
        hn[(v * NGRID + p) * HID + c] = d * bc_val * gc + bbc;
        __syncthreads();
    }
}

__global__ void readout_kernel(const float* __restrict__ h, const float* __restrict__ Wro,
                               const float* __restrict__ bro) {
    __shared__ float hs[16 * 129];
    int tid = threadIdx.x;
    int r0 = blockIdx.x * 16;
    for (int i = tid; i < 16 * 128; i += 160) {
        int row = i >> 7, cc = i & 127;
        hs[row * 129 + cc] = h[(size_t)(r0 + row) * HID + cc];
    }
    __syncthreads();
    if (tid < 16 * 9) {
        int row = tid / 9, oc = tid % 9;
        float acc = bro[oc];
        #pragma unroll 8
        for (int cc = 0; cc < 128; cc++) acc = fmaf(hs[row * 129 + cc], Wro[cc * 9 + oc], acc);
        g_readout[(r0 + row) * 9 + oc] += acc * (1.0f / NLAYERS);
    }
}

__global__ void finalize_kernel(const int* __restrict__ batch, float* __restrict__ out) {
    int v = blockIdx.x * 256 + threadIdx.x;
    if (v >= N_NODES) return;
    float ssum[OUT_S] = {0,0,0,0,0,0,0,0};
    float vsum[3] = {0,0,0};
    for (int n = 0; n < NGRID; n++) {
        const float* rr = &g_readout[(v * NGRID + n) * 9];
        #pragma unroll
        for (int j = 0; j < OUT_S; j++) ssum[j] += rr[j];
        float rv = rr[OUT_S];
        const float* g = &g_node_grid[(v * NGRID + n) * 3];
        vsum[0] += rv * g[0]; vsum[1] += rv * g[1]; vsum[2] += rv * g[2];
    }
    int b = batch[v];
    #pragma unroll
    for (int j = 0; j < OUT_S; j++) atomicAdd(&out[b * OUT_S + j], ssum[j] * (1.0f / NGRID));
    #pragma unroll
    for (int d = 0; d < 3; d++) atomicAdd(&out[NBATCH * OUT_S + b * 3 + d], vsum[d] * (1.0f / NGRID));
}

__global__ void zero_kernel(float* __restrict__ p, int n) {
    for (int i = blockIdx.x * blockDim.x + threadIdx.x; i < n; i += gridDim.x * blockDim.x)
        p[i] = 0.0f;
}
__global__ void zero_sym_kernel(int which) {
    int stride = gridDim.x * blockDim.x;
    if (which == 0) {
        for (int i = blockIdx.x*blockDim.x+threadIdx.x; i < R_N*HID; i += stride) g_agg[i] = 0.0f;
    } else {
        for (int i = blockIdx.x*blockDim.x+threadIdx.x; i < R_N*9; i += stride) g_readout[i] = 0.0f;
    }
}

// ---------------------------------------------------------------------------
// Host launcher
// ---------------------------------------------------------------------------
extern "C" void kernel_launch(void* const* d_in, const int* in_sizes, int n_in,
                              void* d_out, int out_size) {
    const float* x    = (const float*)d_in[0];
    const float* vec  = (const float*)d_in[1];
    const float* pos  = (const float*)d_in[2];
    const float* Q    = (const float*)d_in[3];
    const float* Wsp1 = (const float*)d_in[4];
    const float* bsp1 = (const float*)d_in[5];
    const float* Wsp2 = (const float*)d_in[6];
    const float* bsp2 = (const float*)d_in[7];
    const float* Wsh1 = (const float*)d_in[8];
    const float* bsh1 = (const float*)d_in[9];
    const float* Wsh2 = (const float*)d_in[10];
    const float* bsh2 = (const float*)d_in[11];
    const float* Wemb = (const float*)d_in[12];
    const float* Wk   = (const float*)d_in[13];
    const float* Wfk  = (const float*)d_in[14];
    const float* bconv= (const float*)d_in[15];
    const float* ln_g = (const float*)d_in[16];
    const float* ln_b = (const float*)d_in[17];
    const float* W1   = (const float*)d_in[18];
    const float* b1   = (const float*)d_in[19];
    const float* W2   = (const float*)d_in[20];
    const float* b2   = (const float*)d_in[21];
    const float* Wro  = (const float*)d_in[22];
    const float* bro  = (const float*)d_in[23];
    const int*   eidx = (const int*)d_in[24];
    const int*   batch= (const int*)d_in[25];
    float* out = (float*)d_out;
    const int* send = eidx;
    const int* recv = eidx + N_EDGES;

    float *p_poly, *p_buf1, *p_kb_sp, *p_h, *p_agg, *p_hn, *p_fk;
    cudaGetSymbolAddress((void**)&p_poly,  g_poly);
    cudaGetSymbolAddress((void**)&p_buf1,  g_buf1);
    cudaGetSymbolAddress((void**)&p_kb_sp, g_kb_sp);
    cudaGetSymbolAddress((void**)&p_h,     g_h);
    cudaGetSymbolAddress((void**)&p_agg,   g_agg);
    cudaGetSymbolAddress((void**)&p_hn,    g_hn);
    cudaGetSymbolAddress((void**)&p_fk,    g_fk);

    grid0_kernel<<<1, 32>>>();
    kbsh_kernel<<<144, 128>>>(Wsh1, bsh1, Wsh2, bsh2);
    fk_kernel<<<NLAYERS * 144, 128>>>(Wfk);
    embed_kernel<<<N_NODES, 128>>>(x, vec, Q, batch, Wemb);
    poly_kernel<<<(R_E + 255) / 256, 256>>>(pos, send, recv);

    // kb_sp MLP: [R_E x 14] -> 128 (gelu) -> 128 (gelu)
    hmma_gemm<0><<<dim3(R_E / 128, 1), 256>>>(p_poly, Wsp1, bsp1, nullptr, p_buf1,
                                              14, 14, 128, nullptr, nullptr);
    hmma_gemm<0><<<dim3(R_E / 128, 1), 256>>>(p_buf1, Wsp2, bsp2, nullptr, p_kb_sp,
                                              128, 128, 128, nullptr, nullptr);

    zero_sym_kernel<<<1024, 256>>>(1);

    for (int l = 0; l < NLAYERS; l++) {
        zero_sym_kernel<<<4096, 256>>>(0);
        // fused k = kb_sp @ Wk[l]; msg = h[send]*k; scatter-add into agg[recv]
        hmma_gemm<1><<<dim3(R_E / 128, 1), 256>>>(p_kb_sp, Wk + l * HID * HID, nullptr, p_h, p_agg,
                                                  128, 128, 128, send, recv);
        conv_ln_kernel<<<N_NODES, 128>>>(p_agg, p_fk + l * 144 * HID,
                                         bconv + l * HID, ln_g + l * HID, ln_b + l * HID, p_hn);
        // MLP: hn @ W1 (128->512) gelu -> buf1 ; buf1 @ W2 (512->128) + b2 + h -> h
        hmma_gemm<0><<<dim3(R_N / 128, 4), 256>>>(p_hn, W1 + l * HID * WIDE * HID,
                                                  b1 + l * WIDE * HID, nullptr, p_buf1,
                                                  128, 128, WIDE * HID, nullptr, nullptr);
        hmma_gemm<2><<<dim3(R_N / 128, 1), 256>>>(p_buf1, W2 + l * WIDE * HID * HID,
                                                  b2 + l * HID, p_h, p_h,
                                                  WIDE * HID, WIDE * HID, 128, nullptr, nullptr);
        readout_kernel<<<R_N / 16, 160>>>(p_h, Wro + l * HID * 9, bro + l * 9);
    }

    int out_elems = NBATCH * OUT_S + NBATCH * 3;
    zero_kernel<<<(out_elems + 255) / 256, 256>>>(out, out_elems);
    finalize_kernel<<<(N_NODES + 255) / 256, 256>>>(batch, out);
}

// round 9
// speedup vs baseline: 2.3120x; 1.4436x over previous
#include <cuda_runtime.h>
#include <cuda_bf16.h>
#include <math.h>
#include <stdint.h>

#define N_NODES 8000
#define N_EDGES 64000
#define NBATCH  64
#define NGRID   12
#define HID     128
#define NLAYERS 3
#define IN_S    16
#define OUT_S   8
#define WIDE    4
#define R_E (N_EDGES * NGRID)   // 768000
#define R_N (N_NODES * NGRID)   // 96000

// ---------------------------------------------------------------------------
// Device scratch
// ---------------------------------------------------------------------------
__device__ float g_grid0[NGRID * 3];
__device__ float g_node_grid[R_N * 3];
__device__ float g_kb_sh[144 * HID];
__device__ float g_fk[NLAYERS * 144 * HID];
__device__ float g_h[R_N * HID];
__device__ float g_agg[R_N * HID];
__device__ float g_readout[R_N * (OUT_S + 1)];

// bf16 hi/lo split operand storage
__device__ unsigned short g_poly_h[R_E * 32],  g_poly_l[R_E * 32];     // padded K=32
__device__ unsigned short g_buf1_h[R_E * 128], g_buf1_l[R_E * 128];    // gemm1 out / mlp hidden (R_N*512)
__device__ unsigned short g_kbsp_h[R_E * 128], g_kbsp_l[R_E * 128];
__device__ unsigned short g_hn_h[R_N * 128],   g_hn_l[R_N * 128];
__device__ unsigned short g_wsp1_h[32 * 128],  g_wsp1_l[32 * 128];     // padded K
__device__ unsigned short g_wsp2_h[128 * 128], g_wsp2_l[128 * 128];
__device__ unsigned short g_wk_h[NLAYERS * 128 * 128], g_wk_l[NLAYERS * 128 * 128];
__device__ unsigned short g_w1_h[NLAYERS * 128 * 512], g_w1_l[NLAYERS * 128 * 512];
__device__ unsigned short g_w2_h[NLAYERS * 512 * 128], g_w2_l[NLAYERS * 512 * 128];

__device__ __forceinline__ float gelu_f(float x) {
    return 0.5f * x * (1.0f + erff(x * 0.70710678118654752440f));
}
__device__ __forceinline__ uint32_t sptr(const void* p) {
    uint32_t a;
    asm("{ .reg .u64 t; cvta.to.shared.u64 t, %1; cvt.u32.u64 %0, t; }" : "=r"(a) : "l"(p));
    return a;
}
__device__ __forceinline__ void ldsm_x4(uint32_t* r, uint32_t addr) {
    asm volatile("ldmatrix.sync.aligned.m8n8.x4.shared.b16 {%0,%1,%2,%3}, [%4];"
                 : "=r"(r[0]), "=r"(r[1]), "=r"(r[2]), "=r"(r[3]) : "r"(addr));
}
__device__ __forceinline__ void ldsm_x2t(uint32_t* r, uint32_t addr) {
    asm volatile("ldmatrix.sync.aligned.m8n8.x2.trans.shared.b16 {%0,%1}, [%2];"
                 : "=r"(r[0]), "=r"(r[1]) : "r"(addr));
}
__device__ __forceinline__ void mma16816(float* c, const uint32_t* a, const uint32_t* b) {
    asm volatile("mma.sync.aligned.m16n8k16.row.col.f32.bf16.bf16.f32 "
                 "{%0,%1,%2,%3}, {%4,%5,%6,%7}, {%8,%9}, {%0,%1,%2,%3};"
                 : "+f"(c[0]), "+f"(c[1]), "+f"(c[2]), "+f"(c[3])
                 : "r"(a[0]), "r"(a[1]), "r"(a[2]), "r"(a[3]), "r"(b[0]), "r"(b[1]));
}
__device__ __forceinline__ void split2(float v, unsigned short& h, unsigned short& l) {
    __nv_bfloat16 hb = __float2bfloat16(v);
    h = __bfloat16_as_ushort(hb);
    l = __bfloat16_as_ushort(__float2bfloat16(v - __bfloat162float(hb)));
}

// ---------------------------------------------------------------------------
// HMMA GEMM on pre-split bf16 hi/lo operands.
// C[128 x 128-slab] = A[128 x 32*Ktiles] @ B[. x N], 3-pass split accumulation.
// 256 threads = 8 warps (4m x 2n), warp tile 32x64.
// MODE 0: write gelu(acc+bias[col]) as split hi/lo to Ch/Cl ([M][Nout])
// MODE 1: kconv: atomicAdd(Cf[arow*128+col], acc * aux[hrow*128+col])
// MODE 2: Cf = acc + bias[col] + aux (residual, fp32 out)
// ---------------------------------------------------------------------------
template<int MODE>
__global__ __launch_bounds__(256, 2)
void hmma_gemm(const unsigned short* __restrict__ Ah, const unsigned short* __restrict__ Al, int lda,
               const unsigned short* __restrict__ Bh, const unsigned short* __restrict__ Bl, int ldb,
               int Ktiles, int N,
               const float* __restrict__ bias, const float* __restrict__ aux,
               float* __restrict__ Cf, unsigned short* __restrict__ Ch, unsigned short* __restrict__ Cl,
               const int* __restrict__ send, const int* __restrict__ recv)
{
    __shared__ __align__(16) unsigned short As_h[128][40], As_l[128][40];
    __shared__ __align__(16) unsigned short Bs_h[32][136], Bs_l[32][136];
    __shared__ int hrow[128], arow[128];

    const int tid = threadIdx.x;
    const int l   = tid & 31;
    const int wid = tid >> 5;
    const int wm  = wid & 3;
    const int wn  = wid >> 2;
    const int row0 = blockIdx.x * 128;
    const int nbase = blockIdx.y * 128;

    if (MODE == 1 && tid < 128) {
        int r = row0 + tid;
        int e = r / NGRID, o = r - e * NGRID;
        hrow[tid] = send[e] * NGRID + o;
        arow[tid] = recv[e] * NGRID + o;
    }

    float acc[2][8][4];
    #pragma unroll
    for (int i = 0; i < 2; i++)
        #pragma unroll
        for (int j = 0; j < 8; j++)
            #pragma unroll
            for (int q = 0; q < 4; q++) acc[i][j][q] = 0.0f;

    const int a_roff = (l & 7) + (((l >> 3) & 1) << 3);
    const int a_coff = (l >> 4) << 3;
    const int b_koff = l & 15;

    for (int kt = 0; kt < Ktiles; kt++) {
        const int k0 = kt * 32;
        // A tiles: 128 rows x 32 cols = 512 16B-chunks per array (2/thread)
        #pragma unroll
        for (int i = tid; i < 512; i += 256) {
            int r = i >> 2, j = (i & 3) << 3;   // col offset in ushorts
            size_t g = (size_t)(row0 + r) * lda + k0 + j;
            *(uint4*)&As_h[r][j] = *(const uint4*)(Ah + g);
            *(uint4*)&As_l[r][j] = *(const uint4*)(Al + g);
        }
        // B tiles: 32 rows x 128 cols = 512 chunks per array
        #pragma unroll
        for (int i = tid; i < 512; i += 256) {
            int kk = i >> 4, j = (i & 15) << 3;
            size_t g = (size_t)(k0 + kk) * ldb + nbase + j;
            *(uint4*)&Bs_h[kk][j] = *(const uint4*)(Bh + g);
            *(uint4*)&Bs_l[kk][j] = *(const uint4*)(Bl + g);
        }
        __syncthreads();

        #pragma unroll
        for (int ks = 0; ks < 2; ks++) {
            uint32_t ah[2][4], al[2][4];
            #pragma unroll
            for (int tm = 0; tm < 2; tm++) {
                int rr = wm * 32 + tm * 16 + a_roff;
                int cc = ks * 16 + a_coff;
                ldsm_x4(ah[tm], sptr(&As_h[rr][cc]));
                ldsm_x4(al[tm], sptr(&As_l[rr][cc]));
            }
            #pragma unroll
            for (int tn = 0; tn < 8; tn++) {
                uint32_t bh[2], bl[2];
                int kk = ks * 16 + b_koff;
                int nn = wn * 64 + tn * 8;
                ldsm_x2t(bh, sptr(&Bs_h[kk][nn]));
                ldsm_x2t(bl, sptr(&Bs_l[kk][nn]));
                #pragma unroll
                for (int tm = 0; tm < 2; tm++) {
                    mma16816(acc[tm][tn], ah[tm], bh);
                    mma16816(acc[tm][tn], ah[tm], bl);
                    mma16816(acc[tm][tn], al[tm], bh);
                }
            }
        }
        __syncthreads();
    }

    // epilogue
    #pragma unroll
    for (int tm = 0; tm < 2; tm++) {
        int lr0 = wm * 32 + tm * 16 + (l >> 2);
        int lr1 = lr0 + 8;
        #pragma unroll
        for (int tn = 0; tn < 8; tn++) {
            int cc = nbase + wn * 64 + tn * 8 + (l & 3) * 2;
            float* a4 = acc[tm][tn];
            if (MODE == 0) {
                float v00 = gelu_f(a4[0] + bias[cc]);
                float v01 = gelu_f(a4[1] + bias[cc + 1]);
                float v10 = gelu_f(a4[2] + bias[cc]);
                float v11 = gelu_f(a4[3] + bias[cc + 1]);
                unsigned short h0, l0, h1, l1;
                size_t o0 = (size_t)(row0 + lr0) * N + cc;
                size_t o1 = (size_t)(row0 + lr1) * N + cc;
                split2(v00, h0, l0); split2(v01, h1, l1);
                *(uint32_t*)(Ch + o0) = (uint32_t)h0 | ((uint32_t)h1 << 16);
                *(uint32_t*)(Cl + o0) = (uint32_t)l0 | ((uint32_t)l1 << 16);
                split2(v10, h0, l0); split2(v11, h1, l1);
                *(uint32_t*)(Ch + o1) = (uint32_t)h0 | ((uint32_t)h1 << 16);
                *(uint32_t*)(Cl + o1) = (uint32_t)l0 | ((uint32_t)l1 << 16);
            } else if (MODE == 1) {
                int h0 = hrow[lr0] * 128 + cc, gg0 = arow[lr0] * 128 + cc;
                int h1 = hrow[lr1] * 128 + cc, gg1 = arow[lr1] * 128 + cc;
                float2 hv0 = *(const float2*)(aux + h0);
                float2 hv1 = *(const float2*)(aux + h1);
                atomicAdd(&Cf[gg0],     a4[0] * hv0.x);
                atomicAdd(&Cf[gg0 + 1], a4[1] * hv0.y);
                atomicAdd(&Cf[gg1],     a4[2] * hv1.x);
                atomicAdd(&Cf[gg1 + 1], a4[3] * hv1.y);
            } else {
                size_t o0 = (size_t)(row0 + lr0) * N + cc;
                size_t o1 = (size_t)(row0 + lr1) * N + cc;
                Cf[o0]     = a4[0] + bias[cc]     + aux[o0];
                Cf[o0 + 1] = a4[1] + bias[cc + 1] + aux[o0 + 1];
                Cf[o1]     = a4[2] + bias[cc]     + aux[o1];
                Cf[o1 + 1] = a4[3] + bias[cc + 1] + aux[o1 + 1];
            }
        }
    }
}

// ---------------------------------------------------------------------------
// Weight prep: fp32 W[Ktrue x N] -> split hi/lo [Kpad x N], zero-padded rows
// ---------------------------------------------------------------------------
__global__ void wprep_kernel(const float* __restrict__ W, int Ktrue, int Kpad, int N,
                             unsigned short* __restrict__ hi, unsigned short* __restrict__ lo) {
    int i = blockIdx.x * 256 + threadIdx.x;
    if (i >= Kpad * N) return;
    int k = i / N;
    float v = (k < Ktrue) ? W[i - (k - min(k, Ktrue)) * 0 + 0 * 0] : 0.0f;  // placeholder, fixed below
    // straightforward: W is [Ktrue x N] row-major; for k < Ktrue index is k*N+n = i
    v = (k < Ktrue) ? W[i] : 0.0f;
    unsigned short h, l;
    split2(v, h, l);
    hi[i] = h; lo[i] = l;
}

// ---------------------------------------------------------------------------
// Setup kernels
// ---------------------------------------------------------------------------
__global__ void grid0_kernel() {
    int i = threadIdx.x;
    if (i < NGRID) {
        const float golden = 1.61803398874989484820f;
        float fi = (float)i;
        float theta = 6.28318530717958647692f * fi / golden;
        float z = 1.0f - (2.0f * fi + 1.0f) / (float)NGRID;
        float r = sqrtf(fmaxf(1.0f - z * z, 0.0f));
        g_grid0[i*3+0] = r * cosf(theta); g_grid0[i*3+1] = r * sinf(theta); g_grid0[i*3+2] = z;
    }
}

__global__ void kbsh_kernel(const float* __restrict__ Wsh1, const float* __restrict__ bsh1,
                            const float* __restrict__ Wsh2, const float* __restrict__ bsh2) {
    int row = blockIdx.x;
    int p = row / NGRID, o = row % NGRID;
    int c = threadIdx.x;
    __shared__ float h1[HID];
    float t = g_grid0[p*3+0]*g_grid0[o*3+0] + g_grid0[p*3+1]*g_grid0[o*3+1] + g_grid0[p*3+2]*g_grid0[o*3+2];
    float v = t*Wsh1[c] + t*t*Wsh1[HID+c] + t*t*t*Wsh1[2*HID+c] + bsh1[c];
    h1[c] = gelu_f(v);
    __syncthreads();
    float acc = bsh2[c];
    #pragma unroll 8
    for (int k = 0; k < HID; k++) acc = fmaf(h1[k], Wsh2[k*HID + c], acc);
    g_kb_sh[row * HID + c] = gelu_f(acc);
}

__global__ void fk_kernel(const float* __restrict__ Wfk) {
    int blk = blockIdx.x;
    int ll = blk / 144, row = blk % 144;
    int c = threadIdx.x;
    __shared__ float r128[HID];
    r128[c] = g_kb_sh[row * HID + c];
    __syncthreads();
    const float* W = Wfk + ll * HID * HID;
    float acc = 0.0f;
    #pragma unroll 8
    for (int k = 0; k < HID; k++) acc = fmaf(r128[k], W[k*HID + c], acc);
    g_fk[ll * 144 * HID + row * HID + c] = acc;
}

__global__ void embed_kernel(const float* __restrict__ x, const float* __restrict__ vec,
                             const float* __restrict__ Q, const int* __restrict__ batch,
                             const float* __restrict__ Wemb) {
    int v = blockIdx.x;
    int c = threadIdx.x;
    __shared__ float sQ[9], sx[IN_S], sv[6], sng[NGRID * 3];
    int b = batch[v];
    if (c < 9)  sQ[c] = Q[b * 9 + c];
    if (c < IN_S) sx[c] = x[v * IN_S + c];
    if (c < 6)  sv[c] = vec[v * 6 + c];
    __syncthreads();
    if (c < NGRID * 3) {
        int n = c / 3, i = c % 3;
        float t = sQ[i*3+0]*g_grid0[n*3+0] + sQ[i*3+1]*g_grid0[n*3+1] + sQ[i*3+2]*g_grid0[n*3+2];
        sng[c] = t;
        g_node_grid[v * NGRID * 3 + c] = t;
    }
    __syncthreads();
    float s = 0.0f;
    #pragma unroll
    for (int j = 0; j < IN_S; j++) s = fmaf(sx[j], Wemb[j * HID + c], s);
    float w16 = Wemb[IN_S * HID + c], w17 = Wemb[(IN_S + 1) * HID + c];
    #pragma unroll
    for (int n = 0; n < NGRID; n++) {
        float xv0 = sv[0]*sng[n*3+0] + sv[1]*sng[n*3+1] + sv[2]*sng[n*3+2];
        float xv1 = sv[3]*sng[n*3+0] + sv[4]*sng[n*3+1] + sv[5]*sng[n*3+2];
        g_h[(v * NGRID + n) * HID + c] = s + xv0 * w16 + xv1 * w17;
    }
}

// poly features -> split hi/lo, padded to 32 cols
__global__ void poly_kernel(const float* __restrict__ pos,
                            const int* __restrict__ send, const int* __restrict__ recv) {
    int r = blockIdx.x * 256 + threadIdx.x;
    if (r >= R_E) return;
    int e = r / NGRID, o = r % NGRID;
    int s = send[e], rc = recv[e];
    float rx = pos[s*3+0]-pos[rc*3+0], ry = pos[s*3+1]-pos[rc*3+1], rz = pos[s*3+2]-pos[rc*3+2];
    const float* g = &g_node_grid[(rc * NGRID + o) * 3];
    float inv1 = rx*g[0] + ry*g[1] + rz*g[2];
    float dx = rx-inv1*g[0], dy = ry-inv1*g[1], dz = rz-inv1*g[2];
    float inv2 = sqrtf(dx*dx + dy*dy + dz*dz);
    float q[16];
    float a = inv1, b = inv2;
    q[0]=a; q[1]=b; q[2]=a*a; q[3]=a*b; q[4]=b*a; q[5]=b*b;
    q[6]=q[2]*a; q[7]=q[2]*b; q[8]=q[3]*a; q[9]=q[3]*b;
    q[10]=q[4]*a; q[11]=q[4]*b; q[12]=q[5]*a; q[13]=q[5]*b;
    q[14]=0.0f; q[15]=0.0f;
    size_t base = (size_t)r * 32;
    #pragma unroll
    for (int j = 0; j < 16; j += 2) {
        unsigned short h0, l0, h1, l1;
        split2(q[j], h0, l0); split2(q[j+1], h1, l1);
        *(uint32_t*)(g_poly_h + base + j) = (uint32_t)h0 | ((uint32_t)h1 << 16);
        *(uint32_t*)(g_poly_l + base + j) = (uint32_t)l0 | ((uint32_t)l1 << 16);
    }
    #pragma unroll
    for (int j = 16; j < 32; j += 2) {
        *(uint32_t*)(g_poly_h + base + j) = 0u;
        *(uint32_t*)(g_poly_l + base + j) = 0u;
    }
}

// conv einsum + LN -> split hi/lo hn
__global__ void conv_ln_kernel(const float* __restrict__ agg, const float* __restrict__ fk,
                               const float* __restrict__ bconv, const float* __restrict__ lng,
                               const float* __restrict__ lnb) {
    int v = blockIdx.x;
    int c = threadIdx.x;
    float a[NGRID];
    #pragma unroll
    for (int o = 0; o < NGRID; o++) a[o] = agg[(v * NGRID + o) * HID + c];
    __shared__ float warp_red[4];
    __shared__ float bc_val;
    int lane = c & 31, wd = c >> 5;
    float gc = lng[c], bbc = lnb[c], bcv = bconv[c];
    for (int p = 0; p < NGRID; p++) {
        float s = 0.0f;
        #pragma unroll
        for (int o = 0; o < NGRID; o++) s = fmaf(a[o], fk[(p * NGRID + o) * HID + c], s);
        s = s * (1.0f / NGRID) + bcv;
        float t = s;
        #pragma unroll
        for (int off = 16; off > 0; off >>= 1) t += __shfl_xor_sync(0xffffffffu, t, off);
        if (lane == 0) warp_red[wd] = t;
        __syncthreads();
        if (c == 0) bc_val = (warp_red[0]+warp_red[1]+warp_red[2]+warp_red[3]) * (1.0f / HID);
        __syncthreads();
        float mu = bc_val, d = s - mu;
        t = d * d;
        #pragma unroll
        for (int off = 16; off > 0; off >>= 1) t += __shfl_xor_sync(0xffffffffu, t, off);
        if (lane == 0) warp_red[wd] = t;
        __syncthreads();
        if (c == 0) bc_val = rsqrtf((warp_red[0]+warp_red[1]+warp_red[2]+warp_red[3]) * (1.0f/HID) + 1e-5f);
        __syncthreads();
        float val = d * bc_val * gc + bbc;
        unsigned short hh, lll;
        split2(val, hh, lll);
        size_t idx = (size_t)(v * NGRID + p) * HID + c;
        g_hn_h[idx] = hh;
        g_hn_l[idx] = lll;
        __syncthreads();
    }
}

__global__ void readout_kernel(const float* __restrict__ h, const float* __restrict__ Wro,
                               const float* __restrict__ bro) {
    __shared__ float hs[16 * 129];
    int tid = threadIdx.x;
    int r0 = blockIdx.x * 16;
    for (int i = tid; i < 16 * 128; i += 160) {
        int row = i >> 7, cc = i & 127;
        hs[row * 129 + cc] = h[(size_t)(r0 + row) * HID + cc];
    }
    __syncthreads();
    if (tid < 16 * 9) {
        int row = tid / 9, oc = tid % 9;
        float acc = bro[oc];
        #pragma unroll 8
        for (int cc = 0; cc < 128; cc++) acc = fmaf(hs[row * 129 + cc], Wro[cc * 9 + oc], acc);
        g_readout[(r0 + row) * 9 + oc] += acc * (1.0f / NLAYERS);
    }
}

__global__ void finalize_kernel(const int* __restrict__ batch, float* __restrict__ out) {
    int v = blockIdx.x * 256 + threadIdx.x;
    if (v >= N_NODES) return;
    float ssum[OUT_S] = {0,0,0,0,0,0,0,0};
    float vsum[3] = {0,0,0};
    for (int n = 0; n < NGRID; n++) {
        const float* rr = &g_readout[(v * NGRID + n) * 9];
        #pragma unroll
        for (int j = 0; j < OUT_S; j++) ssum[j] += rr[j];
        float rv = rr[OUT_S];
        const float* g = &g_node_grid[(v * NGRID + n) * 3];
        vsum[0] += rv * g[0]; vsum[1] += rv * g[1]; vsum[2] += rv * g[2];
    }
    int b = batch[v];
    #pragma unroll
    for (int j = 0; j < OUT_S; j++) atomicAdd(&out[b * OUT_S + j], ssum[j] * (1.0f / NGRID));
    #pragma unroll
    for (int d = 0; d < 3; d++) atomicAdd(&out[NBATCH * OUT_S + b * 3 + d], vsum[d] * (1.0f / NGRID));
}

__global__ void zero_kernel(float* __restrict__ p, int n) {
    for (int i = blockIdx.x * blockDim.x + threadIdx.x; i < n; i += gridDim.x * blockDim.x)
        p[i] = 0.0f;
}
__global__ void zero_sym_kernel(int which) {
    int stride = gridDim.x * blockDim.x;
    if (which == 0) {
        for (int i = blockIdx.x*blockDim.x+threadIdx.x; i < R_N*HID; i += stride) g_agg[i] = 0.0f;
    } else {
        for (int i = blockIdx.x*blockDim.x+threadIdx.x; i < R_N*9; i += stride) g_readout[i] = 0.0f;
    }
}

// ---------------------------------------------------------------------------
// Host launcher
// ---------------------------------------------------------------------------
extern "C" void kernel_launch(void* const* d_in, const int* in_sizes, int n_in,
                              void* d_out, int out_size) {
    const float* x    = (const float*)d_in[0];
    const float* vec  = (const float*)d_in[1];
    const float* pos  = (const float*)d_in[2];
    const float* Q    = (const float*)d_in[3];
    const float* Wsp1 = (const float*)d_in[4];
    const float* bsp1 = (const float*)d_in[5];
    const float* Wsp2 = (const float*)d_in[6];
    const float* bsp2 = (const float*)d_in[7];
    const float* Wsh1 = (const float*)d_in[8];
    const float* bsh1 = (const float*)d_in[9];
    const float* Wsh2 = (const float*)d_in[10];
    const float* bsh2 = (const float*)d_in[11];
    const float* Wemb = (const float*)d_in[12];
    const float* Wk   = (const float*)d_in[13];
    const float* Wfk  = (const float*)d_in[14];
    const float* bconv= (const float*)d_in[15];
    const float* ln_g = (const float*)d_in[16];
    const float* ln_b = (const float*)d_in[17];
    const float* W1   = (const float*)d_in[18];
    const float* b1   = (const float*)d_in[19];
    const float* W2   = (const float*)d_in[20];
    const float* b2   = (const float*)d_in[21];
    const float* Wro  = (const float*)d_in[22];
    const float* bro  = (const float*)d_in[23];
    const int*   eidx = (const int*)d_in[24];
    const int*   batch= (const int*)d_in[25];
    float* out = (float*)d_out;
    const int* send = eidx;
    const int* recv = eidx + N_EDGES;

    float *p_h, *p_agg, *p_fk;
    unsigned short *p_ph,*p_pl,*p_b1h,*p_b1l,*p_kbh,*p_kbl,*p_hnh,*p_hnl;
    unsigned short *p_wsp1h,*p_wsp1l,*p_wsp2h,*p_wsp2l,*p_wkh,*p_wkl,*p_w1h,*p_w1l,*p_w2h,*p_w2l;
    cudaGetSymbolAddress((void**)&p_h,   g_h);
    cudaGetSymbolAddress((void**)&p_agg, g_agg);
    cudaGetSymbolAddress((void**)&p_fk,  g_fk);
    cudaGetSymbolAddress((void**)&p_ph,  g_poly_h);  cudaGetSymbolAddress((void**)&p_pl,  g_poly_l);
    cudaGetSymbolAddress((void**)&p_b1h, g_buf1_h);  cudaGetSymbolAddress((void**)&p_b1l, g_buf1_l);
    cudaGetSymbolAddress((void**)&p_kbh, g_kbsp_h);  cudaGetSymbolAddress((void**)&p_kbl, g_kbsp_l);
    cudaGetSymbolAddress((void**)&p_hnh, g_hn_h);    cudaGetSymbolAddress((void**)&p_hnl, g_hn_l);
    cudaGetSymbolAddress((void**)&p_wsp1h, g_wsp1_h); cudaGetSymbolAddress((void**)&p_wsp1l, g_wsp1_l);
    cudaGetSymbolAddress((void**)&p_wsp2h, g_wsp2_h); cudaGetSymbolAddress((void**)&p_wsp2l, g_wsp2_l);
    cudaGetSymbolAddress((void**)&p_wkh, g_wk_h);    cudaGetSymbolAddress((void**)&p_wkl, g_wk_l);
    cudaGetSymbolAddress((void**)&p_w1h, g_w1_h);    cudaGetSymbolAddress((void**)&p_w1l, g_w1_l);
    cudaGetSymbolAddress((void**)&p_w2h, g_w2_h);    cudaGetSymbolAddress((void**)&p_w2l, g_w2_l);

    // weight prep (split once)
    wprep_kernel<<<(32*128 + 255)/256, 256>>>(Wsp1, 14, 32, 128, p_wsp1h, p_wsp1l);
    wprep_kernel<<<(128*128 + 255)/256, 256>>>(Wsp2, 128, 128, 128, p_wsp2h, p_wsp2l);
    for (int l = 0; l < NLAYERS; l++) {
        wprep_kernel<<<(128*128 + 255)/256, 256>>>(Wk + l*128*128, 128, 128, 128,
                                                   p_wkh + l*128*128, p_wkl + l*128*128);
        wprep_kernel<<<(128*512 + 255)/256, 256>>>(W1 + l*128*512, 128, 128, 512,
                                                   p_w1h + l*128*512, p_w1l + l*128*512);
        wprep_kernel<<<(512*128 + 255)/256, 256>>>(W2 + l*512*128, 512, 512, 128,
                                                   p_w2h + l*512*128, p_w2l + l*512*128);
    }

    grid0_kernel<<<1, 32>>>();
    kbsh_kernel<<<144, 128>>>(Wsh1, bsh1, Wsh2, bsh2);
    fk_kernel<<<NLAYERS * 144, 128>>>(Wfk);
    embed_kernel<<<N_NODES, 128>>>(x, vec, Q, batch, Wemb);
    poly_kernel<<<(R_E + 255) / 256, 256>>>(pos, send, recv);

    // kb_sp MLP: [R_E x 14(pad32)] -> 128 (gelu) -> 128 (gelu)
    hmma_gemm<0><<<dim3(R_E / 128, 1), 256>>>(p_ph, p_pl, 32, p_wsp1h, p_wsp1l, 128,
                                              1, 128, bsp1, nullptr, nullptr, p_b1h, p_b1l,
                                              nullptr, nullptr);
    hmma_gemm<0><<<dim3(R_E / 128, 1), 256>>>(p_b1h, p_b1l, 128, p_wsp2h, p_wsp2l, 128,
                                              4, 128, bsp2, nullptr, nullptr, p_kbh, p_kbl,
                                              nullptr, nullptr);

    zero_sym_kernel<<<1024, 256>>>(1);

    for (int l = 0; l < NLAYERS; l++) {
        zero_sym_kernel<<<4096, 256>>>(0);
        // fused k = kb_sp @ Wk[l]; msg = h[send]*k; scatter-add into agg[recv]
        hmma_gemm<1><<<dim3(R_E / 128, 1), 256>>>(p_kbh, p_kbl, 128,
                                                  p_wkh + l*128*128, p_wkl + l*128*128, 128,
                                                  4, 128, nullptr, p_h, p_agg, nullptr, nullptr,
                                                  send, recv);
        conv_ln_kernel<<<N_NODES, 128>>>(p_agg, p_fk + l * 144 * HID,
                                         bconv + l * HID, ln_g + l * HID, ln_b + l * HID);
        // MLP: hn @ W1 (128->512) gelu -> buf1 ; buf1 @ W2 (512->128) + b2 + h -> h
        hmma_gemm<0><<<dim3(R_N / 128, 4), 256>>>(p_hnh, p_hnl, 128,
                                                  p_w1h + l*128*512, p_w1l + l*128*512, 512,
                                                  4, 512, b1 + l*512, nullptr, nullptr, p_b1h, p_b1l,
                                                  nullptr, nullptr);
        hmma_gemm<2><<<dim3(R_N / 128, 1), 256>>>(p_b1h, p_b1l, 512,
                                                  p_w2h + l*512*128, p_w2l + l*512*128, 128,
                                                  16, 128, b2 + l*128, p_h, p_h, nullptr, nullptr,
                                                  nullptr, nullptr);
        readout_kernel<<<R_N / 16, 160>>>(p_h, Wro + l * HID * 9, bro + l * 9);
    }

    int out_elems = NBATCH * OUT_S + NBATCH * 3;
    zero_kernel<<<(out_elems + 255) / 256, 256>>>(out, out_elems);
    finalize_kernel<<<(N_NODES + 255) / 256, 256>>>(batch, out);
}

// round 10
// speedup vs baseline: 2.4895x; 1.0768x over previous
#include <cuda_runtime.h>
#include <cuda_bf16.h>
#include <math.h>
#include <stdint.h>

#define N_NODES 8000
#define N_EDGES 64000
#define NBATCH  64
#define NGRID   12
#define HID     128
#define NLAYERS 3
#define IN_S    16
#define OUT_S   8
#define WIDE    4
#define R_E (N_EDGES * NGRID)   // 768000
#define R_N (N_NODES * NGRID)   // 96000

// ---------------------------------------------------------------------------
// Device scratch
// ---------------------------------------------------------------------------
__device__ float g_grid0[NGRID * 3];
__device__ float g_node_grid[R_N * 3];
__device__ float g_kb_sh[144 * HID];
__device__ float g_fk[NLAYERS * 144 * HID];
__device__ float g_h[R_N * HID];
__device__ float g_agg[R_N * HID];
__device__ float g_readout[R_N * (OUT_S + 1)];

// bf16 hi/lo split operand storage
__device__ unsigned short g_poly_h[R_E * 32],  g_poly_l[R_E * 32];
__device__ unsigned short g_buf1_h[R_E * 128], g_buf1_l[R_E * 128];
__device__ unsigned short g_kbsp_h[R_E * 128], g_kbsp_l[R_E * 128];
__device__ unsigned short g_hn_h[R_N * 128],   g_hn_l[R_N * 128];
__device__ unsigned short g_wsp1_h[32 * 128],  g_wsp1_l[32 * 128];
__device__ unsigned short g_wsp2_h[128 * 128], g_wsp2_l[128 * 128];
__device__ unsigned short g_wk_h[NLAYERS * 128 * 128], g_wk_l[NLAYERS * 128 * 128];
__device__ unsigned short g_w1_h[NLAYERS * 128 * 512], g_w1_l[NLAYERS * 128 * 512];
__device__ unsigned short g_w2_h[NLAYERS * 512 * 128], g_w2_l[NLAYERS * 512 * 128];

__device__ __forceinline__ float gelu_f(float x) {
    return 0.5f * x * (1.0f + erff(x * 0.70710678118654752440f));
}
__device__ __forceinline__ uint32_t sptr(const void* p) {
    uint32_t a;
    asm("{ .reg .u64 t; cvta.to.shared.u64 t, %1; cvt.u32.u64 %0, t; }" : "=r"(a) : "l"(p));
    return a;
}
__device__ __forceinline__ void ldsm_x4(uint32_t* r, uint32_t addr) {
    asm volatile("ldmatrix.sync.aligned.m8n8.x4.shared.b16 {%0,%1,%2,%3}, [%4];"
                 : "=r"(r[0]), "=r"(r[1]), "=r"(r[2]), "=r"(r[3]) : "r"(addr));
}
__device__ __forceinline__ void ldsm_x2t(uint32_t* r, uint32_t addr) {
    asm volatile("ldmatrix.sync.aligned.m8n8.x2.trans.shared.b16 {%0,%1}, [%2];"
                 : "=r"(r[0]), "=r"(r[1]) : "r"(addr));
}
__device__ __forceinline__ void mma16816(float* c, const uint32_t* a, const uint32_t* b) {
    asm volatile("mma.sync.aligned.m16n8k16.row.col.f32.bf16.bf16.f32 "
                 "{%0,%1,%2,%3}, {%4,%5,%6,%7}, {%8,%9}, {%0,%1,%2,%3};"
                 : "+f"(c[0]), "+f"(c[1]), "+f"(c[2]), "+f"(c[3])
                 : "r"(a[0]), "r"(a[1]), "r"(a[2]), "r"(a[3]), "r"(b[0]), "r"(b[1]));
}
__device__ __forceinline__ void split2(float v, unsigned short& h, unsigned short& l) {
    __nv_bfloat16 hb = __float2bfloat16(v);
    h = __bfloat16_as_ushort(hb);
    l = __bfloat16_as_ushort(__float2bfloat16(v - __bfloat162float(hb)));
}
__device__ __forceinline__ void cpasync16(uint32_t dst, const void* src) {
    asm volatile("cp.async.cg.shared.global [%0], [%1], 16;" :: "r"(dst), "l"(src));
}
__device__ __forceinline__ void cp_commit() {
    asm volatile("cp.async.commit_group;" ::: "memory");
}
template<int N>
__device__ __forceinline__ void cp_wait() {
    asm volatile("cp.async.wait_group %0;" :: "n"(N) : "memory");
}

// ---------------------------------------------------------------------------
// smem stage layout (ushort units)
//   A_h: 128*40, A_l: 128*40, B_h: 32*136, B_l: 32*136  => 37888 B per stage
// ---------------------------------------------------------------------------
#define A_STR 40
#define B_STR 136
#define ST_AH 0
#define ST_AL (128 * A_STR)
#define ST_BH (2 * 128 * A_STR)
#define ST_BL (2 * 128 * A_STR + 32 * B_STR)
#define STAGE_USH (2 * 128 * A_STR + 2 * 32 * B_STR)   // 18944 ushorts = 37888 B
#define SMEM_DYN (2 * STAGE_USH * 2)                    // bytes = 75776

// ---------------------------------------------------------------------------
// HMMA GEMM, cp.async double-buffered, pre-split bf16 hi/lo operands.
// MODE 0: gelu(acc+bias[col]) -> split hi/lo out
// MODE 1: kconv: atomicAdd(Cf[arow*128+col], acc * aux[hrow*128+col])
// MODE 2: Cf = acc + bias[col] + aux (residual)
// ---------------------------------------------------------------------------
template<int MODE>
__global__ __launch_bounds__(256, 2)
void hmma_gemm(const unsigned short* __restrict__ Ah, const unsigned short* __restrict__ Al, int lda,
               const unsigned short* __restrict__ Bh, const unsigned short* __restrict__ Bl, int ldb,
               int Ktiles, int N,
               const float* __restrict__ bias, const float* __restrict__ aux,
               float* __restrict__ Cf, unsigned short* __restrict__ Ch, unsigned short* __restrict__ Cl,
               const int* __restrict__ send, const int* __restrict__ recv)
{
    extern __shared__ __align__(16) unsigned short smem[];
    __shared__ int hrow[128], arow[128];

    const int tid = threadIdx.x;
    const int l   = tid & 31;
    const int wid = tid >> 5;
    const int wm  = wid & 3;
    const int wn  = wid >> 2;
    const int row0 = blockIdx.x * 128;
    const int nbase = blockIdx.y * 128;

    if (MODE == 1 && tid < 128) {
        int r = row0 + tid;
        int e = r / NGRID, o = r - e * NGRID;
        hrow[tid] = send[e] * NGRID + o;
        arow[tid] = recv[e] * NGRID + o;
    }

    float acc[2][8][4];
    #pragma unroll
    for (int i = 0; i < 2; i++)
        #pragma unroll
        for (int j = 0; j < 8; j++)
            #pragma unroll
            for (int q = 0; q < 4; q++) acc[i][j][q] = 0.0f;

    const int a_roff = (l & 7) + (((l >> 3) & 1) << 3);
    const int a_coff = (l >> 4) << 3;
    const int b_koff = l & 15;

    // per-thread fill coordinates (2 chunks for A arrays, 2 for B arrays)
    //   A: chunk i in [0,512): row = i>>2, col = (i&3)*8
    //   B: chunk i in [0,512): krow = i>>4, col = (i&15)*8
    const int a_i0 = tid, a_i1 = tid + 256;
    const int ar0 = a_i0 >> 2, ac0 = (a_i0 & 3) << 3;
    const int ar1 = a_i1 >> 2, ac1 = (a_i1 & 3) << 3;
    const int bk0 = a_i0 >> 4, bc0 = (a_i0 & 15) << 3;
    const int bk1 = a_i1 >> 4, bc1 = (a_i1 & 15) << 3;

    auto issue_tile = [&](int kt, int stage) {
        unsigned short* st = smem + stage * STAGE_USH;
        const int k0 = kt * 32;
        uint32_t sA = sptr(st);
        size_t gA0 = (size_t)(row0 + ar0) * lda + k0 + ac0;
        size_t gA1 = (size_t)(row0 + ar1) * lda + k0 + ac1;
        cpasync16(sA + (ST_AH + ar0 * A_STR + ac0) * 2, Ah + gA0);
        cpasync16(sA + (ST_AH + ar1 * A_STR + ac1) * 2, Ah + gA1);
        cpasync16(sA + (ST_AL + ar0 * A_STR + ac0) * 2, Al + gA0);
        cpasync16(sA + (ST_AL + ar1 * A_STR + ac1) * 2, Al + gA1);
        size_t gB0 = (size_t)(k0 + bk0) * ldb + nbase + bc0;
        size_t gB1 = (size_t)(k0 + bk1) * ldb + nbase + bc1;
        cpasync16(sA + (ST_BH + bk0 * B_STR + bc0) * 2, Bh + gB0);
        cpasync16(sA + (ST_BH + bk1 * B_STR + bc1) * 2, Bh + gB1);
        cpasync16(sA + (ST_BL + bk0 * B_STR + bc0) * 2, Bl + gB0);
        cpasync16(sA + (ST_BL + bk1 * B_STR + bc1) * 2, Bl + gB1);
        cp_commit();
    };

    issue_tile(0, 0);

    for (int kt = 0; kt < Ktiles; kt++) {
        const int stage = kt & 1;
        if (kt + 1 < Ktiles) {
            issue_tile(kt + 1, stage ^ 1);
            cp_wait<1>();
        } else {
            cp_wait<0>();
        }
        __syncthreads();

        unsigned short* st = smem + stage * STAGE_USH;
        unsigned short* sAh = st + ST_AH;
        unsigned short* sAl = st + ST_AL;
        unsigned short* sBh = st + ST_BH;
        unsigned short* sBl = st + ST_BL;

        #pragma unroll
        for (int ks = 0; ks < 2; ks++) {
            uint32_t ah[2][4], al[2][4];
            #pragma unroll
            for (int tm = 0; tm < 2; tm++) {
                int rr = wm * 32 + tm * 16 + a_roff;
                int cc = ks * 16 + a_coff;
                ldsm_x4(ah[tm], sptr(sAh + rr * A_STR + cc));
                ldsm_x4(al[tm], sptr(sAl + rr * A_STR + cc));
            }
            #pragma unroll
            for (int tn = 0; tn < 8; tn++) {
                uint32_t bh[2], bl[2];
                int kk = ks * 16 + b_koff;
                int nn = wn * 64 + tn * 8;
                ldsm_x2t(bh, sptr(sBh + kk * B_STR + nn));
                ldsm_x2t(bl, sptr(sBl + kk * B_STR + nn));
                #pragma unroll
                for (int tm = 0; tm < 2; tm++) {
                    mma16816(acc[tm][tn], ah[tm], bh);
                    mma16816(acc[tm][tn], ah[tm], bl);
                    mma16816(acc[tm][tn], al[tm], bh);
                }
            }
        }
        __syncthreads();
    }

    // epilogue
    #pragma unroll
    for (int tm = 0; tm < 2; tm++) {
        int lr0 = wm * 32 + tm * 16 + (l >> 2);
        int lr1 = lr0 + 8;
        #pragma unroll
        for (int tn = 0; tn < 8; tn++) {
            int cc = nbase + wn * 64 + tn * 8 + (l & 3) * 2;
            float* a4 = acc[tm][tn];
            if (MODE == 0) {
                float v00 = gelu_f(a4[0] + bias[cc]);
                float v01 = gelu_f(a4[1] + bias[cc + 1]);
                float v10 = gelu_f(a4[2] + bias[cc]);
                float v11 = gelu_f(a4[3] + bias[cc + 1]);
                unsigned short h0, l0, h1, l1;
                size_t o0 = (size_t)(row0 + lr0) * N + cc;
                size_t o1 = (size_t)(row0 + lr1) * N + cc;
                split2(v00, h0, l0); split2(v01, h1, l1);
                *(uint32_t*)(Ch + o0) = (uint32_t)h0 | ((uint32_t)h1 << 16);
                *(uint32_t*)(Cl + o0) = (uint32_t)l0 | ((uint32_t)l1 << 16);
                split2(v10, h0, l0); split2(v11, h1, l1);
                *(uint32_t*)(Ch + o1) = (uint32_t)h0 | ((uint32_t)h1 << 16);
                *(uint32_t*)(Cl + o1) = (uint32_t)l0 | ((uint32_t)l1 << 16);
            } else if (MODE == 1) {
                int h0 = hrow[lr0] * 128 + cc, gg0 = arow[lr0] * 128 + cc;
                int h1 = hrow[lr1] * 128 + cc, gg1 = arow[lr1] * 128 + cc;
                float2 hv0 = *(const float2*)(aux + h0);
                float2 hv1 = *(const float2*)(aux + h1);
                atomicAdd(&Cf[gg0],     a4[0] * hv0.x);
                atomicAdd(&Cf[gg0 + 1], a4[1] * hv0.y);
                atomicAdd(&Cf[gg1],     a4[2] * hv1.x);
                atomicAdd(&Cf[gg1 + 1], a4[3] * hv1.y);
            } else {
                size_t o0 = (size_t)(row0 + lr0) * N + cc;
                size_t o1 = (size_t)(row0 + lr1) * N + cc;
                Cf[o0]     = a4[0] + bias[cc]     + aux[o0];
                Cf[o0 + 1] = a4[1] + bias[cc + 1] + aux[o0 + 1];
                Cf[o1]     = a4[2] + bias[cc]     + aux[o1];
                Cf[o1 + 1] = a4[3] + bias[cc + 1] + aux[o1 + 1];
            }
        }
    }
}

// ---------------------------------------------------------------------------
// Weight prep: fp32 W[Ktrue x N] -> split hi/lo [Kpad x N]
// ---------------------------------------------------------------------------
__global__ void wprep_kernel(const float* __restrict__ W, int Ktrue, int Kpad, int N,
                             unsigned short* __restrict__ hi, unsigned short* __restrict__ lo) {
    int i = blockIdx.x * 256 + threadIdx.x;
    if (i >= Kpad * N) return;
    int k = i / N;
    float v = (k < Ktrue) ? W[i] : 0.0f;
    unsigned short h, l;
    split2(v, h, l);
    hi[i] = h; lo[i] = l;
}

// ---------------------------------------------------------------------------
// Setup / aux kernels (unchanged)
// ---------------------------------------------------------------------------
__global__ void grid0_kernel() {
    int i = threadIdx.x;
    if (i < NGRID) {
        const float golden = 1.61803398874989484820f;
        float fi = (float)i;
        float theta = 6.28318530717958647692f * fi / golden;
        float z = 1.0f - (2.0f * fi + 1.0f) / (float)NGRID;
        float r = sqrtf(fmaxf(1.0f - z * z, 0.0f));
        g_grid0[i*3+0] = r * cosf(theta); g_grid0[i*3+1] = r * sinf(theta); g_grid0[i*3+2] = z;
    }
}

__global__ void kbsh_kernel(const float* __restrict__ Wsh1, const float* __restrict__ bsh1,
                            const float* __restrict__ Wsh2, const float* __restrict__ bsh2) {
    int row = blockIdx.x;
    int p = row / NGRID, o = row % NGRID;
    int c = threadIdx.x;
    __shared__ float h1[HID];
    float t = g_grid0[p*3+0]*g_grid0[o*3+0] + g_grid0[p*3+1]*g_grid0[o*3+1] + g_grid0[p*3+2]*g_grid0[o*3+2];
    float v = t*Wsh1[c] + t*t*Wsh1[HID+c] + t*t*t*Wsh1[2*HID+c] + bsh1[c];
    h1[c] = gelu_f(v);
    __syncthreads();
    float acc = bsh2[c];
    #pragma unroll 8
    for (int k = 0; k < HID; k++) acc = fmaf(h1[k], Wsh2[k*HID + c], acc);
    g_kb_sh[row * HID + c] = gelu_f(acc);
}

__global__ void fk_kernel(const float* __restrict__ Wfk) {
    int blk = blockIdx.x;
    int ll = blk / 144, row = blk % 144;
    int c = threadIdx.x;
    __shared__ float r128[HID];
    r128[c] = g_kb_sh[row * HID + c];
    __syncthreads();
    const float* W = Wfk + ll * HID * HID;
    float acc = 0.0f;
    #pragma unroll 8
    for (int k = 0; k < HID; k++) acc = fmaf(r128[k], W[k*HID + c], acc);
    g_fk[ll * 144 * HID + row * HID + c] = acc;
}

__global__ void embed_kernel(const float* __restrict__ x, const float* __restrict__ vec,
                             const float* __restrict__ Q, const int* __restrict__ batch,
                             const float* __restrict__ Wemb) {
    int v = blockIdx.x;
    int c = threadIdx.x;
    __shared__ float sQ[9], sx[IN_S], sv[6], sng[NGRID * 3];
    int b = batch[v];
    if (c < 9)  sQ[c] = Q[b * 9 + c];
    if (c < IN_S) sx[c] = x[v * IN_S + c];
    if (c < 6)  sv[c] = vec[v * 6 + c];
    __syncthreads();
    if (c < NGRID * 3) {
        int n = c / 3, i = c % 3;
        float t = sQ[i*3+0]*g_grid0[n*3+0] + sQ[i*3+1]*g_grid0[n*3+1] + sQ[i*3+2]*g_grid0[n*3+2];
        sng[c] = t;
        g_node_grid[v * NGRID * 3 + c] = t;
    }
    __syncthreads();
    float s = 0.0f;
    #pragma unroll
    for (int j = 0; j < IN_S; j++) s = fmaf(sx[j], Wemb[j * HID + c], s);
    float w16 = Wemb[IN_S * HID + c], w17 = Wemb[(IN_S + 1) * HID + c];
    #pragma unroll
    for (int n = 0; n < NGRID; n++) {
        float xv0 = sv[0]*sng[n*3+0] + sv[1]*sng[n*3+1] + sv[2]*sng[n*3+2];
        float xv1 = sv[3]*sng[n*3+0] + sv[4]*sng[n*3+1] + sv[5]*sng[n*3+2];
        g_h[(v * NGRID + n) * HID + c] = s + xv0 * w16 + xv1 * w17;
    }
}

__global__ void poly_kernel(const float* __restrict__ pos,
                            const int* __restrict__ send, const int* __restrict__ recv) {
    int r = blockIdx.x * 256 + threadIdx.x;
    if (r >= R_E) return;
    int e = r / NGRID, o = r % NGRID;
    int s = send[e], rc = recv[e];
    float rx = pos[s*3+0]-pos[rc*3+0], ry = pos[s*3+1]-pos[rc*3+1], rz = pos[s*3+2]-pos[rc*3+2];
    const float* g = &g_node_grid[(rc * NGRID + o) * 3];
    float inv1 = rx*g[0] + ry*g[1] + rz*g[2];
    float dx = rx-inv1*g[0], dy = ry-inv1*g[1], dz = rz-inv1*g[2];
    float inv2 = sqrtf(dx*dx + dy*dy + dz*dz);
    float q[16];
    float a = inv1, b = inv2;
    q[0]=a; q[1]=b; q[2]=a*a; q[3]=a*b; q[4]=b*a; q[5]=b*b;
    q[6]=q[2]*a; q[7]=q[2]*b; q[8]=q[3]*a; q[9]=q[3]*b;
    q[10]=q[4]*a; q[11]=q[4]*b; q[12]=q[5]*a; q[13]=q[5]*b;
    q[14]=0.0f; q[15]=0.0f;
    size_t base = (size_t)r * 32;
    #pragma unroll
    for (int j = 0; j < 16; j += 2) {
        unsigned short h0, l0, h1, l1;
        split2(q[j], h0, l0); split2(q[j+1], h1, l1);
        *(uint32_t*)(g_poly_h + base + j) = (uint32_t)h0 | ((uint32_t)h1 << 16);
        *(uint32_t*)(g_poly_l + base + j) = (uint32_t)l0 | ((uint32_t)l1 << 16);
    }
    #pragma unroll
    for (int j = 16; j < 32; j += 2) {
        *(uint32_t*)(g_poly_h + base + j) = 0u;
        *(uint32_t*)(g_poly_l + base + j) = 0u;
    }
}

__global__ void conv_ln_kernel(const float* __restrict__ agg, const float* __restrict__ fk,
                               const float* __restrict__ bconv, const float* __restrict__ lng,
                               const float* __restrict__ lnb) {
    int v = blockIdx.x;
    int c = threadIdx.x;
    float a[NGRID];
    #pragma unroll
    for (int o = 0; o < NGRID; o++) a[o] = agg[(v * NGRID + o) * HID + c];
    __shared__ float warp_red[4];
    __shared__ float bc_val;
    int lane = c & 31, wd = c >> 5;
    float gc = lng[c], bbc = lnb[c], bcv = bconv[c];
    for (int p = 0; p < NGRID; p++) {
        float s = 0.0f;
        #pragma unroll
        for (int o = 0; o < NGRID; o++) s = fmaf(a[o], fk[(p * NGRID + o) * HID + c], s);
        s = s * (1.0f / NGRID) + bcv;
        float t = s;
        #pragma unroll
        for (int off = 16; off > 0; off >>= 1) t += __shfl_xor_sync(0xffffffffu, t, off);
        if (lane == 0) warp_red[wd] = t;
        __syncthreads();
        if (c == 0) bc_val = (warp_red[0]+warp_red[1]+warp_red[2]+warp_red[3]) * (1.0f / HID);
        __syncthreads();
        float mu = bc_val, d = s - mu;
        t = d * d;
        #pragma unroll
        for (int off = 16; off > 0; off >>= 1) t += __shfl_xor_sync(0xffffffffu, t, off);
        if (lane == 0) warp_red[wd] = t;
        __syncthreads();
        if (c == 0) bc_val = rsqrtf((warp_red[0]+warp_red[1]+warp_red[2]+warp_red[3]) * (1.0f/HID) + 1e-5f);
        __syncthreads();
        float val = d * bc_val * gc + bbc;
        unsigned short hh, lll;
        split2(val, hh, lll);
        size_t idx = (size_t)(v * NGRID + p) * HID + c;
        g_hn_h[idx] = hh;
        g_hn_l[idx] = lll;
        __syncthreads();
    }
}

__global__ void readout_kernel(const float* __restrict__ h, const float* __restrict__ Wro,
                               const float* __restrict__ bro) {
    __shared__ float hs[16 * 129];
    int tid = threadIdx.x;
    int r0 = blockIdx.x * 16;
    for (int i = tid; i < 16 * 128; i += 160) {
        int row = i >> 7, cc = i & 127;
        hs[row * 129 + cc] = h[(size_t)(r0 + row) * HID + cc];
    }
    __syncthreads();
    if (tid < 16 * 9) {
        int row = tid / 9, oc = tid % 9;
        float acc = bro[oc];
        #pragma unroll 8
        for (int cc = 0; cc < 128; cc++) acc = fmaf(hs[row * 129 + cc], Wro[cc * 9 + oc], acc);
        g_readout[(r0 + row) * 9 + oc] += acc * (1.0f / NLAYERS);
    }
}

__global__ void finalize_kernel(const int* __restrict__ batch, float* __restrict__ out) {
    int v = blockIdx.x * 256 + threadIdx.x;
    if (v >= N_NODES) return;
    float ssum[OUT_S] = {0,0,0,0,0,0,0,0};
    float vsum[3] = {0,0,0};
    for (int n = 0; n < NGRID; n++) {
        const float* rr = &g_readout[(v * NGRID + n) * 9];
        #pragma unroll
        for (int j = 0; j < OUT_S; j++) ssum[j] += rr[j];
        float rv = rr[OUT_S];
        const float* g = &g_node_grid[(v * NGRID + n) * 3];
        vsum[0] += rv * g[0]; vsum[1] += rv * g[1]; vsum[2] += rv * g[2];
    }
    int b = batch[v];
    #pragma unroll
    for (int j = 0; j < OUT_S; j++) atomicAdd(&out[b * OUT_S + j], ssum[j] * (1.0f / NGRID));
    #pragma unroll
    for (int d = 0; d < 3; d++) atomicAdd(&out[NBATCH * OUT_S + b * 3 + d], vsum[d] * (1.0f / NGRID));
}

__global__ void zero_kernel(float* __restrict__ p, int n) {
    for (int i = blockIdx.x * blockDim.x + threadIdx.x; i < n; i += gridDim.x * blockDim.x)
        p[i] = 0.0f;
}
__global__ void zero_sym_kernel(int which) {
    int stride = gridDim.x * blockDim.x;
    if (which == 0) {
        for (int i = blockIdx.x*blockDim.x+threadIdx.x; i < R_N*HID; i += stride) g_agg[i] = 0.0f;
    } else {
        for (int i = blockIdx.x*blockDim.x+threadIdx.x; i < R_N*9; i += stride) g_readout[i] = 0.0f;
    }
}

// ---------------------------------------------------------------------------
// Host launcher
// ---------------------------------------------------------------------------
extern "C" void kernel_launch(void* const* d_in, const int* in_sizes, int n_in,
                              void* d_out, int out_size) {
    const float* x    = (const float*)d_in[0];
    const float* vec  = (const float*)d_in[1];
    const float* pos  = (const float*)d_in[2];
    const float* Q    = (const float*)d_in[3];
    const float* Wsp1 = (const float*)d_in[4];
    const float* bsp1 = (const float*)d_in[5];
    const float* Wsp2 = (const float*)d_in[6];
    const float* bsp2 = (const float*)d_in[7];
    const float* Wsh1 = (const float*)d_in[8];
    const float* bsh1 = (const float*)d_in[9];
    const float* Wsh2 = (const float*)d_in[10];
    const float* bsh2 = (const float*)d_in[11];
    const float* Wemb = (const float*)d_in[12];
    const float* Wk   = (const float*)d_in[13];
    const float* Wfk  = (const float*)d_in[14];
    const float* bconv= (const float*)d_in[15];
    const float* ln_g = (const float*)d_in[16];
    const float* ln_b = (const float*)d_in[17];
    const float* W1   = (const float*)d_in[18];
    const float* b1   = (const float*)d_in[19];
    const float* W2   = (const float*)d_in[20];
    const float* b2   = (const float*)d_in[21];
    const float* Wro  = (const float*)d_in[22];
    const float* bro  = (const float*)d_in[23];
    const int*   eidx = (const int*)d_in[24];
    const int*   batch= (const int*)d_in[25];
    float* out = (float*)d_out;
    const int* send = eidx;
    const int* recv = eidx + N_EDGES;

    float *p_h, *p_agg, *p_fk;
    unsigned short *p_ph,*p_pl,*p_b1h,*p_b1l,*p_kbh,*p_kbl,*p_hnh,*p_hnl;
    unsigned short *p_wsp1h,*p_wsp1l,*p_wsp2h,*p_wsp2l,*p_wkh,*p_wkl,*p_w1h,*p_w1l,*p_w2h,*p_w2l;
    cudaGetSymbolAddress((void**)&p_h,   g_h);
    cudaGetSymbolAddress((void**)&p_agg, g_agg);
    cudaGetSymbolAddress((void**)&p_fk,  g_fk);
    cudaGetSymbolAddress((void**)&p_ph,  g_poly_h);  cudaGetSymbolAddress((void**)&p_pl,  g_poly_l);
    cudaGetSymbolAddress((void**)&p_b1h, g_buf1_h);  cudaGetSymbolAddress((void**)&p_b1l, g_buf1_l);
    cudaGetSymbolAddress((void**)&p_kbh, g_kbsp_h);  cudaGetSymbolAddress((void**)&p_kbl, g_kbsp_l);
    cudaGetSymbolAddress((void**)&p_hnh, g_hn_h);    cudaGetSymbolAddress((void**)&p_hnl, g_hn_l);
    cudaGetSymbolAddress((void**)&p_wsp1h, g_wsp1_h); cudaGetSymbolAddress((void**)&p_wsp1l, g_wsp1_l);
    cudaGetSymbolAddress((void**)&p_wsp2h, g_wsp2_h); cudaGetSymbolAddress((void**)&p_wsp2l, g_wsp2_l);
    cudaGetSymbolAddress((void**)&p_wkh, g_wk_h);    cudaGetSymbolAddress((void**)&p_wkl, g_wk_l);
    cudaGetSymbolAddress((void**)&p_w1h, g_w1_h);    cudaGetSymbolAddress((void**)&p_w1l, g_w1_l);
    cudaGetSymbolAddress((void**)&p_w2h, g_w2_h);    cudaGetSymbolAddress((void**)&p_w2l, g_w2_l);

    cudaFuncSetAttribute(hmma_gemm<0>, cudaFuncAttributeMaxDynamicSharedMemorySize, SMEM_DYN);
    cudaFuncSetAttribute(hmma_gemm<1>, cudaFuncAttributeMaxDynamicSharedMemorySize, SMEM_DYN);
    cudaFuncSetAttribute(hmma_gemm<2>, cudaFuncAttributeMaxDynamicSharedMemorySize, SMEM_DYN);

    // weight prep (split once)
    wprep_kernel<<<(32*128 + 255)/256, 256>>>(Wsp1, 14, 32, 128, p_wsp1h, p_wsp1l);
    wprep_kernel<<<(128*128 + 255)/256, 256>>>(Wsp2, 128, 128, 128, p_wsp2h, p_wsp2l);
    for (int l = 0; l < NLAYERS; l++) {
        wprep_kernel<<<(128*128 + 255)/256, 256>>>(Wk + l*128*128, 128, 128, 128,
                                                   p_wkh + l*128*128, p_wkl + l*128*128);
        wprep_kernel<<<(128*512 + 255)/256, 256>>>(W1 + l*128*512, 128, 128, 512,
                                                   p_w1h + l*128*512, p_w1l + l*128*512);
        wprep_kernel<<<(512*128 + 255)/256, 256>>>(W2 + l*512*128, 512, 512, 128,
                                                   p_w2h + l*512*128, p_w2l + l*512*128);
    }

    grid0_kernel<<<1, 32>>>();
    kbsh_kernel<<<144, 128>>>(Wsh1, bsh1, Wsh2, bsh2);
    fk_kernel<<<NLAYERS * 144, 128>>>(Wfk);
    embed_kernel<<<N_NODES, 128>>>(x, vec, Q, batch, Wemb);
    poly_kernel<<<(R_E + 255) / 256, 256>>>(pos, send, recv);

    // kb_sp MLP: [R_E x 14(pad32)] -> 128 (gelu) -> 128 (gelu)
    hmma_gemm<0><<<dim3(R_E / 128, 1), 256, SMEM_DYN>>>(p_ph, p_pl, 32, p_wsp1h, p_wsp1l, 128,
                                                        1, 128, bsp1, nullptr, nullptr, p_b1h, p_b1l,
                                                        nullptr, nullptr);
    hmma_gemm<0><<<dim3(R_E / 128, 1), 256, SMEM_DYN>>>(p_b1h, p_b1l, 128, p_wsp2h, p_wsp2l, 128,
                                                        4, 128, bsp2, nullptr, nullptr, p_kbh, p_kbl,
                                                        nullptr, nullptr);

    zero_sym_kernel<<<1024, 256>>>(1);

    for (int l = 0; l < NLAYERS; l++) {
        zero_sym_kernel<<<4096, 256>>>(0);
        hmma_gemm<1><<<dim3(R_E / 128, 1), 256, SMEM_DYN>>>(p_kbh, p_kbl, 128,
                                                  p_wkh + l*128*128, p_wkl + l*128*128, 128,
                                                  4, 128, nullptr, p_h, p_agg, nullptr, nullptr,
                                                  send, recv);
        conv_ln_kernel<<<N_NODES, 128>>>(p_agg, p_fk + l * 144 * HID,
                                         bconv + l * HID, ln_g + l * HID, ln_b + l * HID);
        hmma_gemm<0><<<dim3(R_N / 128, 4), 256, SMEM_DYN>>>(p_hnh, p_hnl, 128,
                                                  p_w1h + l*128*512, p_w1l + l*128*512, 512,
                                                  4, 512, b1 + l*512, nullptr, nullptr, p_b1h, p_b1l,
                                                  nullptr, nullptr);
        hmma_gemm<2><<<dim3(R_N / 128, 1), 256, SMEM_DYN>>>(p_b1h, p_b1l, 512,
                                                  p_w2h + l*512*128, p_w2l + l*512*128, 128,
                                                  16, 128, b2 + l*128, p_h, p_h, nullptr, nullptr,
                                                  nullptr, nullptr);
        readout_kernel<<<R_N / 16, 160>>>(p_h, Wro + l * HID * 9, bro + l * 9);
    }

    int out_elems = NBATCH * OUT_S + NBATCH * 3;
    zero_kernel<<<(out_elems + 255) / 256, 256>>>(out, out_elems);
    finalize_kernel<<<(N_NODES + 255) / 256, 256>>>(batch, out);
}

// round 11
// speedup vs baseline: 2.5765x; 1.0349x over previous
#include <cuda_runtime.h>
#include <cuda_bf16.h>
#include <math.h>
#include <stdint.h>

#define N_NODES 8000
#define N_EDGES 64000
#define NBATCH  64
#define NGRID   12
#define HID     128
#define NLAYERS 3
#define IN_S    16
#define OUT_S   8
#define WIDE    4
#define R_E (N_EDGES * NGRID)   // 768000
#define R_N (N_NODES * NGRID)   // 96000

// ---------------------------------------------------------------------------
// Device scratch
// ---------------------------------------------------------------------------
__device__ float g_grid0[NGRID * 3];
__device__ float g_node_grid[R_N * 3];
__device__ float g_kb_sh[144 * HID];
__device__ float g_fk[NLAYERS * 144 * HID];
__device__ float g_h[R_N * HID];
__device__ float g_agg[R_N * HID];
__device__ float g_readout[R_N * (OUT_S + 1)];

// bf16 hi/lo split operand storage
__device__ unsigned short g_poly_h[R_E * 32],  g_poly_l[R_E * 32];
__device__ unsigned short g_buf1_h[R_E * 128], g_buf1_l[R_E * 128];
__device__ unsigned short g_kbsp_h[R_E * 128], g_kbsp_l[R_E * 128];
__device__ unsigned short g_hn_h[R_N * 128],   g_hn_l[R_N * 128];
__device__ unsigned short g_wsp1_h[32 * 128],  g_wsp1_l[32 * 128];
__device__ unsigned short g_wsp2_h[128 * 128], g_wsp2_l[128 * 128];
__device__ unsigned short g_wk_h[NLAYERS * 128 * 128], g_wk_l[NLAYERS * 128 * 128];
__device__ unsigned short g_w1_h[NLAYERS * 128 * 512], g_w1_l[NLAYERS * 128 * 512];
__device__ unsigned short g_w2_h[NLAYERS * 512 * 128], g_w2_l[NLAYERS * 512 * 128];

__device__ __forceinline__ float gelu_f(float x) {
    return 0.5f * x * (1.0f + erff(x * 0.70710678118654752440f));
}
__device__ __forceinline__ uint32_t sptr(const void* p) {
    uint32_t a;
    asm("{ .reg .u64 t; cvta.to.shared.u64 t, %1; cvt.u32.u64 %0, t; }" : "=r"(a) : "l"(p));
    return a;
}
__device__ __forceinline__ void ldsm_x4(uint32_t* r, uint32_t addr) {
    asm volatile("ldmatrix.sync.aligned.m8n8.x4.shared.b16 {%0,%1,%2,%3}, [%4];"
                 : "=r"(r[0]), "=r"(r[1]), "=r"(r[2]), "=r"(r[3]) : "r"(addr));
}
__device__ __forceinline__ void ldsm_x4t(uint32_t* r, uint32_t addr) {
    asm volatile("ldmatrix.sync.aligned.m8n8.x4.trans.shared.b16 {%0,%1,%2,%3}, [%4];"
                 : "=r"(r[0]), "=r"(r[1]), "=r"(r[2]), "=r"(r[3]) : "r"(addr));
}
__device__ __forceinline__ void mma16816(float* c, const uint32_t* a, const uint32_t* b) {
    asm volatile("mma.sync.aligned.m16n8k16.row.col.f32.bf16.bf16.f32 "
                 "{%0,%1,%2,%3}, {%4,%5,%6,%7}, {%8,%9}, {%0,%1,%2,%3};"
                 : "+f"(c[0]), "+f"(c[1]), "+f"(c[2]), "+f"(c[3])
                 : "r"(a[0]), "r"(a[1]), "r"(a[2]), "r"(a[3]), "r"(b[0]), "r"(b[1]));
}
__device__ __forceinline__ void split2(float v, unsigned short& h, unsigned short& l) {
    __nv_bfloat16 hb = __float2bfloat16(v);
    h = __bfloat16_as_ushort(hb);
    l = __bfloat16_as_ushort(__float2bfloat16(v - __bfloat162float(hb)));
}
__device__ __forceinline__ void cpasync16(uint32_t dst, const void* src) {
    asm volatile("cp.async.cg.shared.global [%0], [%1], 16;" :: "r"(dst), "l"(src));
}
__device__ __forceinline__ void cp_commit() {
    asm volatile("cp.async.commit_group;" ::: "memory");
}
template<int N>
__device__ __forceinline__ void cp_wait() {
    asm volatile("cp.async.wait_group %0;" :: "n"(N) : "memory");
}

// ---------------------------------------------------------------------------
// smem stage layout (ushort units): A_h 128*40, A_l 128*40, B_h 32*136, B_l 32*136
// ---------------------------------------------------------------------------
#define A_STR 40
#define B_STR 136
#define ST_AH 0
#define ST_AL (128 * A_STR)
#define ST_BH (2 * 128 * A_STR)
#define ST_BL (2 * 128 * A_STR + 32 * B_STR)
#define STAGE_USH (2 * 128 * A_STR + 2 * 32 * B_STR)   // 18944 ushorts = 37888 B
#define SMEM_DYN (2 * STAGE_USH * 2)                    // 75776 B

// ---------------------------------------------------------------------------
// HMMA GEMM: 128x128 block, 4 warps (2m x 2n), warp tile 64x64.
// cp.async double-buffered, split-bf16 3-pass, B frags via ldmatrix.x4.trans.
// Ks16 = number of real k16 steps (skips zero-padded tail).
// MODE 0: gelu(acc+bias[col]) -> split hi/lo out
// MODE 1: kconv: atomicAdd(Cf[arow*128+col], acc * aux[hrow*128+col])
// MODE 2: Cf = acc + bias[col] + aux (residual)
// ---------------------------------------------------------------------------
template<int MODE>
__global__ __launch_bounds__(128, 2)
void hmma_gemm(const unsigned short* __restrict__ Ah, const unsigned short* __restrict__ Al, int lda,
               const unsigned short* __restrict__ Bh, const unsigned short* __restrict__ Bl, int ldb,
               int Ktiles, int Ks16, int N,
               const float* __restrict__ bias, const float* __restrict__ aux,
               float* __restrict__ Cf, unsigned short* __restrict__ Ch, unsigned short* __restrict__ Cl,
               const int* __restrict__ send, const int* __restrict__ recv)
{
    extern __shared__ __align__(16) unsigned short smem[];
    __shared__ int hrow[128], arow[128];

    const int tid = threadIdx.x;
    const int l   = tid & 31;
    const int wid = tid >> 5;
    const int wm  = wid & 1;       // 64-row half
    const int wn  = wid >> 1;      // 64-col half
    const int row0 = blockIdx.x * 128;
    const int nbase = blockIdx.y * 128;

    if (MODE == 1) {
        int r = row0 + tid;
        int e = r / NGRID, o = r - e * NGRID;
        hrow[tid] = send[e] * NGRID + o;
        arow[tid] = recv[e] * NGRID + o;
    }

    float acc[4][8][4];
    #pragma unroll
    for (int i = 0; i < 4; i++)
        #pragma unroll
        for (int j = 0; j < 8; j++)
            #pragma unroll
            for (int q = 0; q < 4; q++) acc[i][j][q] = 0.0f;

    // A ldmatrix lane mapping (x4, row-major 16x16)
    const int a_row = (l & 7) + (((l >> 3) & 1) << 3);
    const int a_col = (l >> 4) << 3;
    // B ldmatrix.x4.trans lane mapping: g = l>>3 -> (k-half, n-half)
    const int bg = l >> 3, br = l & 7;
    const int b_lane_off = ((bg & 1) * 8 + br) * B_STR + (bg >> 1) * 8;

    auto issue_tile = [&](int kt, int stage) {
        unsigned short* st = smem + stage * STAGE_USH;
        const int k0 = kt * 32;
        uint32_t sA = sptr(st);
        #pragma unroll
        for (int j = 0; j < 4; j++) {
            int i = tid + j * 128;
            int ar = i >> 2, ac = (i & 3) << 3;
            size_t gA = (size_t)(row0 + ar) * lda + k0 + ac;
            cpasync16(sA + (ST_AH + ar * A_STR + ac) * 2, Ah + gA);
            cpasync16(sA + (ST_AL + ar * A_STR + ac) * 2, Al + gA);
            int bk = i >> 4, bc = (i & 15) << 3;
            size_t gB = (size_t)(k0 + bk) * ldb + nbase + bc;
            cpasync16(sA + (ST_BH + bk * B_STR + bc) * 2, Bh + gB);
            cpasync16(sA + (ST_BL + bk * B_STR + bc) * 2, Bl + gB);
        }
        cp_commit();
    };

    issue_tile(0, 0);

    for (int kt = 0; kt < Ktiles; kt++) {
        const int stage = kt & 1;
        if (kt + 1 < Ktiles) {
            issue_tile(kt + 1, stage ^ 1);
            cp_wait<1>();
        } else {
            cp_wait<0>();
        }
        __syncthreads();

        unsigned short* st = smem + stage * STAGE_USH;
        unsigned short* sAh = st + ST_AH;
        unsigned short* sAl = st + ST_AL;
        unsigned short* sBh = st + ST_BH;
        unsigned short* sBl = st + ST_BL;

        const int ksmax = min(2, Ks16 - kt * 2);
        for (int ks = 0; ks < ksmax; ks++) {
            uint32_t ah[4][4], al[4][4];
            #pragma unroll
            for (int tm = 0; tm < 4; tm++) {
                int rr = wm * 64 + tm * 16 + a_row;
                int cc = ks * 16 + a_col;
                ldsm_x4(ah[tm], sptr(sAh + rr * A_STR + cc));
                ldsm_x4(al[tm], sptr(sAl + rr * A_STR + cc));
            }
            #pragma unroll
            for (int tn2 = 0; tn2 < 4; tn2++) {
                int nn = wn * 64 + tn2 * 16;
                uint32_t bh4[4], bl4[4];
                uint32_t baddr = ks * 16 * B_STR + nn + b_lane_off;
                ldsm_x4t(bh4, sptr(sBh + baddr));
                ldsm_x4t(bl4, sptr(sBl + baddr));
                #pragma unroll
                for (int tm = 0; tm < 4; tm++) {
                    mma16816(acc[tm][2*tn2],     ah[tm], bh4);
                    mma16816(acc[tm][2*tn2],     ah[tm], bl4);
                    mma16816(acc[tm][2*tn2],     al[tm], bh4);
                    mma16816(acc[tm][2*tn2 + 1], ah[tm], bh4 + 2);
                    mma16816(acc[tm][2*tn2 + 1], ah[tm], bl4 + 2);
                    mma16816(acc[tm][2*tn2 + 1], al[tm], bh4 + 2);
                }
            }
        }
        __syncthreads();
    }

    // epilogue
    #pragma unroll
    for (int tm = 0; tm < 4; tm++) {
        int lr0 = wm * 64 + tm * 16 + (l >> 2);
        int lr1 = lr0 + 8;
        #pragma unroll
        for (int tn = 0; tn < 8; tn++) {
            int cc = nbase + wn * 64 + tn * 8 + (l & 3) * 2;
            float* a4 = acc[tm][tn];
            if (MODE == 0) {
                float v00 = gelu_f(a4[0] + bias[cc]);
                float v01 = gelu_f(a4[1] + bias[cc + 1]);
                float v10 = gelu_f(a4[2] + bias[cc]);
                float v11 = gelu_f(a4[3] + bias[cc + 1]);
                unsigned short h0, l0, h1, l1;
                size_t o0 = (size_t)(row0 + lr0) * N + cc;
                size_t o1 = (size_t)(row0 + lr1) * N + cc;
                split2(v00, h0, l0); split2(v01, h1, l1);
                *(uint32_t*)(Ch + o0) = (uint32_t)h0 | ((uint32_t)h1 << 16);
                *(uint32_t*)(Cl + o0) = (uint32_t)l0 | ((uint32_t)l1 << 16);
                split2(v10, h0, l0); split2(v11, h1, l1);
                *(uint32_t*)(Ch + o1) = (uint32_t)h0 | ((uint32_t)h1 << 16);
                *(uint32_t*)(Cl + o1) = (uint32_t)l0 | ((uint32_t)l1 << 16);
            } else if (MODE == 1) {
                int h0 = hrow[lr0] * 128 + cc, gg0 = arow[lr0] * 128 + cc;
                int h1 = hrow[lr1] * 128 + cc, gg1 = arow[lr1] * 128 + cc;
                float2 hv0 = *(const float2*)(aux + h0);
                float2 hv1 = *(const float2*)(aux + h1);
                atomicAdd(&Cf[gg0],     a4[0] * hv0.x);
                atomicAdd(&Cf[gg0 + 1], a4[1] * hv0.y);
                atomicAdd(&Cf[gg1],     a4[2] * hv1.x);
                atomicAdd(&Cf[gg1 + 1], a4[3] * hv1.y);
            } else {
                size_t o0 = (size_t)(row0 + lr0) * N + cc;
                size_t o1 = (size_t)(row0 + lr1) * N + cc;
                Cf[o0]     = a4[0] + bias[cc]     + aux[o0];
                Cf[o0 + 1] = a4[1] + bias[cc + 1] + aux[o0 + 1];
                Cf[o1]     = a4[2] + bias[cc]     + aux[o1];
                Cf[o1 + 1] = a4[3] + bias[cc + 1] + aux[o1 + 1];
            }
        }
    }
}

// ---------------------------------------------------------------------------
// Weight prep: fp32 W[Ktrue x N] -> split hi/lo [Kpad x N]
// ---------------------------------------------------------------------------
__global__ void wprep_kernel(const float* __restrict__ W, int Ktrue, int Kpad, int N,
                             unsigned short* __restrict__ hi, unsigned short* __restrict__ lo) {
    int i = blockIdx.x * 256 + threadIdx.x;
    if (i >= Kpad * N) return;
    int k = i / N;
    float v = (k < Ktrue) ? W[i] : 0.0f;
    unsigned short h, l;
    split2(v, h, l);
    hi[i] = h; lo[i] = l;
}

// ---------------------------------------------------------------------------
// Setup / aux kernels (unchanged)
// ---------------------------------------------------------------------------
__global__ void grid0_kernel() {
    int i = threadIdx.x;
    if (i < NGRID) {
        const float golden = 1.61803398874989484820f;
        float fi = (float)i;
        float theta = 6.28318530717958647692f * fi / golden;
        float z = 1.0f - (2.0f * fi + 1.0f) / (float)NGRID;
        float r = sqrtf(fmaxf(1.0f - z * z, 0.0f));
        g_grid0[i*3+0] = r * cosf(theta); g_grid0[i*3+1] = r * sinf(theta); g_grid0[i*3+2] = z;
    }
}

__global__ void kbsh_kernel(const float* __restrict__ Wsh1, const float* __restrict__ bsh1,
                            const float* __restrict__ Wsh2, const float* __restrict__ bsh2) {
    int row = blockIdx.x;
    int p = row / NGRID, o = row % NGRID;
    int c = threadIdx.x;
    __shared__ float h1[HID];
    float t = g_grid0[p*3+0]*g_grid0[o*3+0] + g_grid0[p*3+1]*g_grid0[o*3+1] + g_grid0[p*3+2]*g_grid0[o*3+2];
    float v = t*Wsh1[c] + t*t*Wsh1[HID+c] + t*t*t*Wsh1[2*HID+c] + bsh1[c];
    h1[c] = gelu_f(v);
    __syncthreads();
    float acc = bsh2[c];
    #pragma unroll 8
    for (int k = 0; k < HID; k++) acc = fmaf(h1[k], Wsh2[k*HID + c], acc);
    g_kb_sh[row * HID + c] = gelu_f(acc);
}

__global__ void fk_kernel(const float* __restrict__ Wfk) {
    int blk = blockIdx.x;
    int ll = blk / 144, row = blk % 144;
    int c = threadIdx.x;
    __shared__ float r128[HID];
    r128[c] = g_kb_sh[row * HID + c];
    __syncthreads();
    const float* W = Wfk + ll * HID * HID;
    float acc = 0.0f;
    #pragma unroll 8
    for (int k = 0; k < HID; k++) acc = fmaf(r128[k], W[k*HID + c], acc);
    g_fk[ll * 144 * HID + row * HID + c] = acc;
}

__global__ void embed_kernel(const float* __restrict__ x, const float* __restrict__ vec,
                             const float* __restrict__ Q, const int* __restrict__ batch,
                             const float* __restrict__ Wemb) {
    int v = blockIdx.x;
    int c = threadIdx.x;
    __shared__ float sQ[9], sx[IN_S], sv[6], sng[NGRID * 3];
    int b = batch[v];
    if (c < 9)  sQ[c] = Q[b * 9 + c];
    if (c < IN_S) sx[c] = x[v * IN_S + c];
    if (c < 6)  sv[c] = vec[v * 6 + c];
    __syncthreads();
    if (c < NGRID * 3) {
        int n = c / 3, i = c % 3;
        float t = sQ[i*3+0]*g_grid0[n*3+0] + sQ[i*3+1]*g_grid0[n*3+1] + sQ[i*3+2]*g_grid0[n*3+2];
        sng[c] = t;
        g_node_grid[v * NGRID * 3 + c] = t;
    }
    __syncthreads();
    float s = 0.0f;
    #pragma unroll
    for (int j = 0; j < IN_S; j++) s = fmaf(sx[j], Wemb[j * HID + c], s);
    float w16 = Wemb[IN_S * HID + c], w17 = Wemb[(IN_S + 1) * HID + c];
    #pragma unroll
    for (int n = 0; n < NGRID; n++) {
        float xv0 = sv[0]*sng[n*3+0] + sv[1]*sng[n*3+1] + sv[2]*sng[n*3+2];
        float xv1 = sv[3]*sng[n*3+0] + sv[4]*sng[n*3+1] + sv[5]*sng[n*3+2];
        g_h[(v * NGRID + n) * HID + c] = s + xv0 * w16 + xv1 * w17;
    }
}

__global__ void poly_kernel(const float* __restrict__ pos,
                            const int* __restrict__ send, const int* __restrict__ recv) {
    int r = blockIdx.x * 256 + threadIdx.x;
    if (r >= R_E) return;
    int e = r / NGRID, o = r % NGRID;
    int s = send[e], rc = recv[e];
    float rx = pos[s*3+0]-pos[rc*3+0], ry = pos[s*3+1]-pos[rc*3+1], rz = pos[s*3+2]-pos[rc*3+2];
    const float* g = &g_node_grid[(rc * NGRID + o) * 3];
    float inv1 = rx*g[0] + ry*g[1] + rz*g[2];
    float dx = rx-inv1*g[0], dy = ry-inv1*g[1], dz = rz-inv1*g[2];
    float inv2 = sqrtf(dx*dx + dy*dy + dz*dz);
    float q[16];
    float a = inv1, b = inv2;
    q[0]=a; q[1]=b; q[2]=a*a; q[3]=a*b; q[4]=b*a; q[5]=b*b;
    q[6]=q[2]*a; q[7]=q[2]*b; q[8]=q[3]*a; q[9]=q[3]*b;
    q[10]=q[4]*a; q[11]=q[4]*b; q[12]=q[5]*a; q[13]=q[5]*b;
    q[14]=0.0f; q[15]=0.0f;
    size_t base = (size_t)r * 32;
    #pragma unroll
    for (int j = 0; j < 16; j += 2) {
        unsigned short h0, l0, h1, l1;
        split2(q[j], h0, l0); split2(q[j+1], h1, l1);
        *(uint32_t*)(g_poly_h + base + j) = (uint32_t)h0 | ((uint32_t)h1 << 16);
        *(uint32_t*)(g_poly_l + base + j) = (uint32_t)l0 | ((uint32_t)l1 << 16);
    }
    #pragma unroll
    for (int j = 16; j < 32; j += 2) {
        *(uint32_t*)(g_poly_h + base + j) = 0u;
        *(uint32_t*)(g_poly_l + base + j) = 0u;
    }
}

__global__ void conv_ln_kernel(const float* __restrict__ agg, const float* __restrict__ fk,
                               const float* __restrict__ bconv, const float* __restrict__ lng,
                               const float* __restrict__ lnb) {
    int v = blockIdx.x;
    int c = threadIdx.x;
    float a[NGRID];
    #pragma unroll
    for (int o = 0; o < NGRID; o++) a[o] = agg[(v * NGRID + o) * HID + c];
    __shared__ float warp_red[4];
    __shared__ float bc_val;
    int lane = c & 31, wd = c >> 5;
    float gc = lng[c], bbc = lnb[c], bcv = bconv[c];
    for (int p = 0; p < NGRID; p++) {
        float s = 0.0f;
        #pragma unroll
        for (int o = 0; o < NGRID; o++) s = fmaf(a[o], fk[(p * NGRID + o) * HID + c], s);
        s = s * (1.0f / NGRID) + bcv;
        float t = s;
        #pragma unroll
        for (int off = 16; off > 0; off >>= 1) t += __shfl_xor_sync(0xffffffffu, t, off);
        if (lane == 0) warp_red[wd] = t;
        __syncthreads();
        if (c == 0) bc_val = (warp_red[0]+warp_red[1]+warp_red[2]+warp_red[3]) * (1.0f / HID);
        __syncthreads();
        float mu = bc_val, d = s - mu;
        t = d * d;
        #pragma unroll
        for (int off = 16; off > 0; off >>= 1) t += __shfl_xor_sync(0xffffffffu, t, off);
        if (lane == 0) warp_red[wd] = t;
        __syncthreads();
        if (c == 0) bc_val = rsqrtf((warp_red[0]+warp_red[1]+warp_red[2]+warp_red[3]) * (1.0f/HID) + 1e-5f);
        __syncthreads();
        float val = d * bc_val * gc + bbc;
        unsigned short hh, lll;
        split2(val, hh, lll);
        size_t idx = (size_t)(v * NGRID + p) * HID + c;
        g_hn_h[idx] = hh;
        g_hn_l[idx] = lll;
        __syncthreads();
    }
}

__global__ void readout_kernel(const float* __restrict__ h, const float* __restrict__ Wro,
                               const float* __restrict__ bro) {
    __shared__ float hs[16 * 129];
    int tid = threadIdx.x;
    int r0 = blockIdx.x * 16;
    for (int i = tid; i < 16 * 128; i += 160) {
        int row = i >> 7, cc = i & 127;
        hs[row * 129 + cc] = h[(size_t)(r0 + row) * HID + cc];
    }
    __syncthreads();
    if (tid < 16 * 9) {
        int row = tid / 9, oc = tid % 9;
        float acc = bro[oc];
        #pragma unroll 8
        for (int cc = 0; cc < 128; cc++) acc = fmaf(hs[row * 129 + cc], Wro[cc * 9 + oc], acc);
        g_readout[(r0 + row) * 9 + oc] += acc * (1.0f / NLAYERS);
    }
}

__global__ void finalize_kernel(const int* __restrict__ batch, float* __restrict__ out) {
    int v = blockIdx.x * 256 + threadIdx.x;
    if (v >= N_NODES) return;
    float ssum[OUT_S] = {0,0,0,0,0,0,0,0};
    float vsum[3] = {0,0,0};
    for (int n = 0; n < NGRID; n++) {
        const float* rr = &g_readout[(v * NGRID + n) * 9];
        #pragma unroll
        for (int j = 0; j < OUT_S; j++) ssum[j] += rr[j];
        float rv = rr[OUT_S];
        const float* g = &g_node_grid[(v * NGRID + n) * 3];
        vsum[0] += rv * g[0]; vsum[1] += rv * g[1]; vsum[2] += rv * g[2];
    }
    int b = batch[v];
    #pragma unroll
    for (int j = 0; j < OUT_S; j++) atomicAdd(&out[b * OUT_S + j], ssum[j] * (1.0f / NGRID));
    #pragma unroll
    for (int d = 0; d < 3; d++) atomicAdd(&out[NBATCH * OUT_S + b * 3 + d], vsum[d] * (1.0f / NGRID));
}

__global__ void zero_kernel(float* __restrict__ p, int n) {
    for (int i = blockIdx.x * blockDim.x + threadIdx.x; i < n; i += gridDim.x * blockDim.x)
        p[i] = 0.0f;
}
__global__ void zero_sym_kernel(int which) {
    int stride = gridDim.x * blockDim.x;
    if (which == 0) {
        for (int i = blockIdx.x*blockDim.x+threadIdx.x; i < R_N*HID; i += stride) g_agg[i] = 0.0f;
    } else {
        for (int i = blockIdx.x*blockDim.x+threadIdx.x; i < R_N*9; i += stride) g_readout[i] = 0.0f;
    }
}

// ---------------------------------------------------------------------------
// Host launcher
// ---------------------------------------------------------------------------
extern "C" void kernel_launch(void* const* d_in, const int* in_sizes, int n_in,
                              void* d_out, int out_size) {
    const float* x    = (const float*)d_in[0];
    const float* vec  = (const float*)d_in[1];
    const float* pos  = (const float*)d_in[2];
    const float* Q    = (const float*)d_in[3];
    const float* Wsp1 = (const float*)d_in[4];
    const float* bsp1 = (const float*)d_in[5];
    const float* Wsp2 = (const float*)d_in[6];
    const float* bsp2 = (const float*)d_in[7];
    const float* Wsh1 = (const float*)d_in[8];
    const float* bsh1 = (const float*)d_in[9];
    const float* Wsh2 = (const float*)d_in[10];
    const float* bsh2 = (const float*)d_in[11];
    const float* Wemb = (const float*)d_in[12];
    const float* Wk   = (const float*)d_in[13];
    const float* Wfk  = (const float*)d_in[14];
    const float* bconv= (const float*)d_in[15];
    const float* ln_g = (const float*)d_in[16];
    const float* ln_b = (const float*)d_in[17];
    const float* W1   = (const float*)d_in[18];
    const float* b1   = (const float*)d_in[19];
    const float* W2   = (const float*)d_in[20];
    const float* b2   = (const float*)d_in[21];
    const float* Wro  = (const float*)d_in[22];
    const float* bro  = (const float*)d_in[23];
    const int*   eidx = (const int*)d_in[24];
    const int*   batch= (const int*)d_in[25];
    float* out = (float*)d_out;
    const int* send = eidx;
    const int* recv = eidx + N_EDGES;

    float *p_h, *p_agg, *p_fk;
    unsigned short *p_ph,*p_pl,*p_b1h,*p_b1l,*p_kbh,*p_kbl,*p_hnh,*p_hnl;
    unsigned short *p_wsp1h,*p_wsp1l,*p_wsp2h,*p_wsp2l,*p_wkh,*p_wkl,*p_w1h,*p_w1l,*p_w2h,*p_w2l;
    cudaGetSymbolAddress((void**)&p_h,   g_h);
    cudaGetSymbolAddress((void**)&p_agg, g_agg);
    cudaGetSymbolAddress((void**)&p_fk,  g_fk);
    cudaGetSymbolAddress((void**)&p_ph,  g_poly_h);  cudaGetSymbolAddress((void**)&p_pl,  g_poly_l);
    cudaGetSymbolAddress((void**)&p_b1h, g_buf1_h);  cudaGetSymbolAddress((void**)&p_b1l, g_buf1_l);
    cudaGetSymbolAddress((void**)&p_kbh, g_kbsp_h);  cudaGetSymbolAddress((void**)&p_kbl, g_kbsp_l);
    cudaGetSymbolAddress((void**)&p_hnh, g_hn_h);    cudaGetSymbolAddress((void**)&p_hnl, g_hn_l);
    cudaGetSymbolAddress((void**)&p_wsp1h, g_wsp1_h); cudaGetSymbolAddress((void**)&p_wsp1l, g_wsp1_l);
    cudaGetSymbolAddress((void**)&p_wsp2h, g_wsp2_h); cudaGetSymbolAddress((void**)&p_wsp2l, g_wsp2_l);
    cudaGetSymbolAddress((void**)&p_wkh, g_wk_h);    cudaGetSymbolAddress((void**)&p_wkl, g_wk_l);
    cudaGetSymbolAddress((void**)&p_w1h, g_w1_h);    cudaGetSymbolAddress((void**)&p_w1l, g_w1_l);
    cudaGetSymbolAddress((void**)&p_w2h, g_w2_h);    cudaGetSymbolAddress((void**)&p_w2l, g_w2_l);

    cudaFuncSetAttribute(hmma_gemm<0>, cudaFuncAttributeMaxDynamicSharedMemorySize, SMEM_DYN);
    cudaFuncSetAttribute(hmma_gemm<1>, cudaFuncAttributeMaxDynamicSharedMemorySize, SMEM_DYN);
    cudaFuncSetAttribute(hmma_gemm<2>, cudaFuncAttributeMaxDynamicSharedMemorySize, SMEM_DYN);

    // weight prep (split once)
    wprep_kernel<<<(32*128 + 255)/256, 256>>>(Wsp1, 14, 32, 128, p_wsp1h, p_wsp1l);
    wprep_kernel<<<(128*128 + 255)/256, 256>>>(Wsp2, 128, 128, 128, p_wsp2h, p_wsp2l);
    for (int l = 0; l < NLAYERS; l++) {
        wprep_kernel<<<(128*128 + 255)/256, 256>>>(Wk + l*128*128, 128, 128, 128,
                                                   p_wkh + l*128*128, p_wkl + l*128*128);
        wprep_kernel<<<(128*512 + 255)/256, 256>>>(W1 + l*128*512, 128, 128, 512,
                                                   p_w1h + l*128*512, p_w1l + l*128*512);
        wprep_kernel<<<(512*128 + 255)/256, 256>>>(W2 + l*512*128, 512, 512, 128,
                                                   p_w2h + l*512*128, p_w2l + l*512*128);
    }

    grid0_kernel<<<1, 32>>>();
    kbsh_kernel<<<144, 128>>>(Wsh1, bsh1, Wsh2, bsh2);
    fk_kernel<<<NLAYERS * 144, 128>>>(Wfk);
    embed_kernel<<<N_NODES, 128>>>(x, vec, Q, batch, Wemb);
    poly_kernel<<<(R_E + 255) / 256, 256>>>(pos, send, recv);

    // kb_sp MLP: [R_E x 14(pad32)] -> 128 (gelu) -> 128 (gelu)
    hmma_gemm<0><<<dim3(R_E / 128, 1), 128, SMEM_DYN>>>(p_ph, p_pl, 32, p_wsp1h, p_wsp1l, 128,
                                                        1, 1, 128, bsp1, nullptr, nullptr, p_b1h, p_b1l,
                                                        nullptr, nullptr);
    hmma_gemm<0><<<dim3(R_E / 128, 1), 128, SMEM_DYN>>>(p_b1h, p_b1l, 128, p_wsp2h, p_wsp2l, 128,
                                                        4, 8, 128, bsp2, nullptr, nullptr, p_kbh, p_kbl,
                                                        nullptr, nullptr);

    zero_sym_kernel<<<1024, 256>>>(1);

    for (int l = 0; l < NLAYERS; l++) {
        zero_sym_kernel<<<4096, 256>>>(0);
        hmma_gemm<1><<<dim3(R_E / 128, 1), 128, SMEM_DYN>>>(p_kbh, p_kbl, 128,
                                                  p_wkh + l*128*128, p_wkl + l*128*128, 128,
                                                  4, 8, 128, nullptr, p_h, p_agg, nullptr, nullptr,
                                                  send, recv);
        conv_ln_kernel<<<N_NODES, 128>>>(p_agg, p_fk + l * 144 * HID,
                                         bconv + l * HID, ln_g + l * HID, ln_b + l * HID);
        hmma_gemm<0><<<dim3(R_N / 128, 4), 128, SMEM_DYN>>>(p_hnh, p_hnl, 128,
                                                  p_w1h + l*128*512, p_w1l + l*128*512, 512,
                                                  4, 8, 512, b1 + l*512, nullptr, nullptr, p_b1h, p_b1l,
                                                  nullptr, nullptr);
        hmma_gemm<2><<<dim3(R_N / 128, 1), 128, SMEM_DYN>>>(p_b1h, p_b1l, 512,
                                                  p_w2h + l*512*128, p_w2l + l*512*128, 128,
                                                  16, 32, 128, b2 + l*128, p_h, p_h, nullptr, nullptr,
                                                  nullptr, nullptr);
        readout_kernel<<<R_N / 16, 160>>>(p_h, Wro + l * HID * 9, bro + l * 9);
    }

    int out_elems = NBATCH * OUT_S + NBATCH * 3;
    zero_kernel<<<(out_elems + 255) / 256, 256>>>(out, out_elems);
    finalize_kernel<<<(N_NODES + 255) / 256, 256>>>(batch, out);
}

// round 12
// speedup vs baseline: 2.5979x; 1.0083x over previous
#include <cuda_runtime.h>
#include <cuda_bf16.h>
#include <math.h>
#include <stdint.h>

#define N_NODES 8000
#define N_EDGES 64000
#define NBATCH  64
#define NGRID   12
#define HID     128
#define NLAYERS 3
#define IN_S    16
#define OUT_S   8
#define WIDE    4
#define R_E (N_EDGES * NGRID)   // 768000
#define R_N (N_NODES * NGRID)   // 96000

// ---------------------------------------------------------------------------
// Device scratch
// ---------------------------------------------------------------------------
__device__ float g_grid0[NGRID * 3];
__device__ float g_node_grid[R_N * 3];
__device__ float g_kb_sh[144 * HID];
__device__ float g_fk[NLAYERS * 144 * HID];
__device__ float g_h[R_N * HID];
__device__ float g_agg[R_N * HID];
__device__ float g_readout[R_N * (OUT_S + 1)];

// bf16 hi/lo split operand storage
__device__ unsigned short g_poly_h[R_E * 32],  g_poly_l[R_E * 32];
__device__ unsigned short g_buf1_h[R_E * 128], g_buf1_l[R_E * 128];
__device__ unsigned short g_kbsp_h[R_E * 128], g_kbsp_l[R_E * 128];
__device__ unsigned short g_hn_h[R_N * 128],   g_hn_l[R_N * 128];
__device__ unsigned short g_wsp1_h[32 * 128],  g_wsp1_l[32 * 128];
__device__ unsigned short g_wsp2_h[128 * 128], g_wsp2_l[128 * 128];
__device__ unsigned short g_wk_h[NLAYERS * 128 * 128], g_wk_l[NLAYERS * 128 * 128];
__device__ unsigned short g_w1_h[NLAYERS * 128 * 512], g_w1_l[NLAYERS * 128 * 512];
__device__ unsigned short g_w2_h[NLAYERS * 512 * 128], g_w2_l[NLAYERS * 512 * 128];

__device__ __forceinline__ float gelu_f(float x) {
    return 0.5f * x * (1.0f + erff(x * 0.70710678118654752440f));
}
__device__ __forceinline__ uint32_t sptr(const void* p) {
    uint32_t a;
    asm("{ .reg .u64 t; cvta.to.shared.u64 t, %1; cvt.u32.u64 %0, t; }" : "=r"(a) : "l"(p));
    return a;
}
__device__ __forceinline__ void ldsm_x4(uint32_t* r, uint32_t addr) {
    asm volatile("ldmatrix.sync.aligned.m8n8.x4.shared.b16 {%0,%1,%2,%3}, [%4];"
                 : "=r"(r[0]), "=r"(r[1]), "=r"(r[2]), "=r"(r[3]) : "r"(addr));
}
__device__ __forceinline__ void ldsm_x4t(uint32_t* r, uint32_t addr) {
    asm volatile("ldmatrix.sync.aligned.m8n8.x4.trans.shared.b16 {%0,%1,%2,%3}, [%4];"
                 : "=r"(r[0]), "=r"(r[1]), "=r"(r[2]), "=r"(r[3]) : "r"(addr));
}
__device__ __forceinline__ void mma16816(float* c, const uint32_t* a, const uint32_t* b) {
    asm volatile("mma.sync.aligned.m16n8k16.row.col.f32.bf16.bf16.f32 "
                 "{%0,%1,%2,%3}, {%4,%5,%6,%7}, {%8,%9}, {%0,%1,%2,%3};"
                 : "+f"(c[0]), "+f"(c[1]), "+f"(c[2]), "+f"(c[3])
                 : "r"(a[0]), "r"(a[1]), "r"(a[2]), "r"(a[3]), "r"(b[0]), "r"(b[1]));
}
__device__ __forceinline__ void split2(float v, unsigned short& h, unsigned short& l) {
    __nv_bfloat16 hb = __float2bfloat16(v);
    h = __bfloat16_as_ushort(hb);
    l = __bfloat16_as_ushort(__float2bfloat16(v - __bfloat162float(hb)));
}
__device__ __forceinline__ void cpasync16(uint32_t dst, const void* src) {
    asm volatile("cp.async.cg.shared.global [%0], [%1], 16;" :: "r"(dst), "l"(src));
}
__device__ __forceinline__ void cp_commit() {
    asm volatile("cp.async.commit_group;" ::: "memory");
}
template<int N>
__device__ __forceinline__ void cp_wait() {
    asm volatile("cp.async.wait_group %0;" :: "n"(N) : "memory");
}

// ---------------------------------------------------------------------------
// smem stage layout (ushort units)
// ---------------------------------------------------------------------------
#define A_STR 40
#define B_STR 136
#define ST_AH 0
#define ST_AL (128 * A_STR)
#define ST_BH (2 * 128 * A_STR)
#define ST_BL (2 * 128 * A_STR + 32 * B_STR)
#define STAGE_USH (2 * 128 * A_STR + 2 * 32 * B_STR)
#define SMEM_DYN (2 * STAGE_USH * 2)

// ---------------------------------------------------------------------------
// HMMA GEMM: 128x128 block, 4 warps (2m x 2n), warp tile 64x64.
// cp.async double-buffered; split-bf16 3-pass; PASS-MAJOR MMA order:
// per k16 all fragments hoisted, then 3 passes of 32 independent MMAs.
// ---------------------------------------------------------------------------
template<int MODE>
__global__ __launch_bounds__(128, 2)
void hmma_gemm(const unsigned short* __restrict__ Ah, const unsigned short* __restrict__ Al, int lda,
               const unsigned short* __restrict__ Bh, const unsigned short* __restrict__ Bl, int ldb,
               int Ktiles, int Ks16, int N,
               const float* __restrict__ bias, const float* __restrict__ aux,
               float* __restrict__ Cf, unsigned short* __restrict__ Ch, unsigned short* __restrict__ Cl,
               const int* __restrict__ send, const int* __restrict__ recv)
{
    extern __shared__ __align__(16) unsigned short smem[];
    __shared__ int hrow[128], arow[128];

    const int tid = threadIdx.x;
    const int l   = tid & 31;
    const int wid = tid >> 5;
    const int wm  = wid & 1;
    const int wn  = wid >> 1;
    const int row0 = blockIdx.x * 128;
    const int nbase = blockIdx.y * 128;

    if (MODE == 1) {
        int r = row0 + tid;
        int e = r / NGRID, o = r - e * NGRID;
        hrow[tid] = send[e] * NGRID + o;
        arow[tid] = recv[e] * NGRID + o;
    }

    float acc[4][8][4];
    #pragma unroll
    for (int i = 0; i < 4; i++)
        #pragma unroll
        for (int j = 0; j < 8; j++)
            #pragma unroll
            for (int q = 0; q < 4; q++) acc[i][j][q] = 0.0f;

    const int a_row = (l & 7) + (((l >> 3) & 1) << 3);
    const int a_col = (l >> 4) << 3;
    const int bg = l >> 3, br = l & 7;
    const int b_lane_off = ((bg & 1) * 8 + br) * B_STR + (bg >> 1) * 8;

    auto issue_tile = [&](int kt, int stage) {
        unsigned short* st = smem + stage * STAGE_USH;
        const int k0 = kt * 32;
        uint32_t sA = sptr(st);
        #pragma unroll
        for (int j = 0; j < 4; j++) {
            int i = tid + j * 128;
            int ar = i >> 2, ac = (i & 3) << 3;
            size_t gA = (size_t)(row0 + ar) * lda + k0 + ac;
            cpasync16(sA + (ST_AH + ar * A_STR + ac) * 2, Ah + gA);
            cpasync16(sA + (ST_AL + ar * A_STR + ac) * 2, Al + gA);
            int bk = i >> 4, bc = (i & 15) << 3;
            size_t gB = (size_t)(k0 + bk) * ldb + nbase + bc;
            cpasync16(sA + (ST_BH + bk * B_STR + bc) * 2, Bh + gB);
            cpasync16(sA + (ST_BL + bk * B_STR + bc) * 2, Bl + gB);
        }
        cp_commit();
    };

    issue_tile(0, 0);

    for (int kt = 0; kt < Ktiles; kt++) {
        const int stage = kt & 1;
        if (kt + 1 < Ktiles) {
            issue_tile(kt + 1, stage ^ 1);
            cp_wait<1>();
        } else {
            cp_wait<0>();
        }
        __syncthreads();

        unsigned short* st = smem + stage * STAGE_USH;
        unsigned short* sAh = st + ST_AH;
        unsigned short* sAl = st + ST_AL;
        unsigned short* sBh = st + ST_BH;
        unsigned short* sBl = st + ST_BL;

        const int ksmax = min(2, Ks16 - kt * 2);
        for (int ks = 0; ks < ksmax; ks++) {
            uint32_t ah[4][4], al[4][4], bh[4][4], bl[4][4];
            #pragma unroll
            for (int tm = 0; tm < 4; tm++) {
                int rr = wm * 64 + tm * 16 + a_row;
                int cc = ks * 16 + a_col;
                ldsm_x4(ah[tm], sptr(sAh + rr * A_STR + cc));
                ldsm_x4(al[tm], sptr(sAl + rr * A_STR + cc));
            }
            #pragma unroll
            for (int tn2 = 0; tn2 < 4; tn2++) {
                int nn = wn * 64 + tn2 * 16;
                uint32_t baddr = ks * 16 * B_STR + nn + b_lane_off;
                ldsm_x4t(bh[tn2], sptr(sBh + baddr));
                ldsm_x4t(bl[tn2], sptr(sBl + baddr));
            }
            // pass 0: ah * bh  (32 independent MMAs)
            #pragma unroll
            for (int tm = 0; tm < 4; tm++)
                #pragma unroll
                for (int tn2 = 0; tn2 < 4; tn2++) {
                    mma16816(acc[tm][2*tn2],     ah[tm], bh[tn2]);
                    mma16816(acc[tm][2*tn2 + 1], ah[tm], bh[tn2] + 2);
                }
            // pass 1: ah * bl
            #pragma unroll
            for (int tm = 0; tm < 4; tm++)
                #pragma unroll
                for (int tn2 = 0; tn2 < 4; tn2++) {
                    mma16816(acc[tm][2*tn2],     ah[tm], bl[tn2]);
                    mma16816(acc[tm][2*tn2 + 1], ah[tm], bl[tn2] + 2);
                }
            // pass 2: al * bh
            #pragma unroll
            for (int tm = 0; tm < 4; tm++)
                #pragma unroll
                for (int tn2 = 0; tn2 < 4; tn2++) {
                    mma16816(acc[tm][2*tn2],     al[tm], bh[tn2]);
                    mma16816(acc[tm][2*tn2 + 1], al[tm], bh[tn2] + 2);
                }
        }
        __syncthreads();
    }

    // epilogue
    #pragma unroll
    for (int tm = 0; tm < 4; tm++) {
        int lr0 = wm * 64 + tm * 16 + (l >> 2);
        int lr1 = lr0 + 8;
        #pragma unroll
        for (int tn = 0; tn < 8; tn++) {
            int cc = nbase + wn * 64 + tn * 8 + (l & 3) * 2;
            float* a4 = acc[tm][tn];
            if (MODE == 0) {
                float v00 = gelu_f(a4[0] + bias[cc]);
                float v01 = gelu_f(a4[1] + bias[cc + 1]);
                float v10 = gelu_f(a4[2] + bias[cc]);
                float v11 = gelu_f(a4[3] + bias[cc + 1]);
                unsigned short h0, l0, h1, l1;
                size_t o0 = (size_t)(row0 + lr0) * N + cc;
                size_t o1 = (size_t)(row0 + lr1) * N + cc;
                split2(v00, h0, l0); split2(v01, h1, l1);
                *(uint32_t*)(Ch + o0) = (uint32_t)h0 | ((uint32_t)h1 << 16);
                *(uint32_t*)(Cl + o0) = (uint32_t)l0 | ((uint32_t)l1 << 16);
                split2(v10, h0, l0); split2(v11, h1, l1);
                *(uint32_t*)(Ch + o1) = (uint32_t)h0 | ((uint32_t)h1 << 16);
                *(uint32_t*)(Cl + o1) = (uint32_t)l0 | ((uint32_t)l1 << 16);
            } else if (MODE == 1) {
                int h0 = hrow[lr0] * 128 + cc, gg0 = arow[lr0] * 128 + cc;
                int h1 = hrow[lr1] * 128 + cc, gg1 = arow[lr1] * 128 + cc;
                float2 hv0 = *(const float2*)(aux + h0);
                float2 hv1 = *(const float2*)(aux + h1);
                atomicAdd(&Cf[gg0],     a4[0] * hv0.x);
                atomicAdd(&Cf[gg0 + 1], a4[1] * hv0.y);
                atomicAdd(&Cf[gg1],     a4[2] * hv1.x);
                atomicAdd(&Cf[gg1 + 1], a4[3] * hv1.y);
            } else {
                size_t o0 = (size_t)(row0 + lr0) * N + cc;
                size_t o1 = (size_t)(row0 + lr1) * N + cc;
                Cf[o0]     = a4[0] + bias[cc]     + aux[o0];
                Cf[o0 + 1] = a4[1] + bias[cc + 1] + aux[o0 + 1];
                Cf[o1]     = a4[2] + bias[cc]     + aux[o1];
                Cf[o1 + 1] = a4[3] + bias[cc + 1] + aux[o1 + 1];
            }
        }
    }
}

// ---------------------------------------------------------------------------
// Weight prep
// ---------------------------------------------------------------------------
__global__ void wprep_kernel(const float* __restrict__ W, int Ktrue, int Kpad, int N,
                             unsigned short* __restrict__ hi, unsigned short* __restrict__ lo) {
    int i = blockIdx.x * 256 + threadIdx.x;
    if (i >= Kpad * N) return;
    int k = i / N;
    float v = (k < Ktrue) ? W[i] : 0.0f;
    unsigned short h, l;
    split2(v, h, l);
    hi[i] = h; lo[i] = l;
}

// ---------------------------------------------------------------------------
// embed: computes fibonacci grid0 inline (writes g_grid0 too), node_grid, h0
// ---------------------------------------------------------------------------
__global__ void embed_kernel(const float* __restrict__ x, const float* __restrict__ vec,
                             const float* __restrict__ Q, const int* __restrict__ batch,
                             const float* __restrict__ Wemb) {
    int v = blockIdx.x;
    int c = threadIdx.x;
    __shared__ float sQ[9], sx[IN_S], sv[6], sng[NGRID * 3], sg0[NGRID * 3];
    int b = batch[v];
    if (c < NGRID) {
        const float golden = 1.61803398874989484820f;
        float fi = (float)c;
        float theta = 6.28318530717958647692f * fi / golden;
        float z = 1.0f - (2.0f * fi + 1.0f) / (float)NGRID;
        float r = sqrtf(fmaxf(1.0f - z * z, 0.0f));
        float g0 = r * cosf(theta), g1 = r * sinf(theta);
        sg0[c*3+0] = g0; sg0[c*3+1] = g1; sg0[c*3+2] = z;
        if (v == 0) { g_grid0[c*3+0] = g0; g_grid0[c*3+1] = g1; g_grid0[c*3+2] = z; }
    }
    if (c < 9)  sQ[c] = Q[b * 9 + c];
    if (c < IN_S) sx[c] = x[v * IN_S + c];
    if (c < 6)  sv[c] = vec[v * 6 + c];
    __syncthreads();
    if (c < NGRID * 3) {
        int n = c / 3, i = c % 3;
        float t = sQ[i*3+0]*sg0[n*3+0] + sQ[i*3+1]*sg0[n*3+1] + sQ[i*3+2]*sg0[n*3+2];
        sng[c] = t;
        g_node_grid[v * NGRID * 3 + c] = t;
    }
    __syncthreads();
    float s = 0.0f;
    #pragma unroll
    for (int j = 0; j < IN_S; j++) s = fmaf(sx[j], Wemb[j * HID + c], s);
    float w16 = Wemb[IN_S * HID + c], w17 = Wemb[(IN_S + 1) * HID + c];
    #pragma unroll
    for (int n = 0; n < NGRID; n++) {
        float xv0 = sv[0]*sng[n*3+0] + sv[1]*sng[n*3+1] + sv[2]*sng[n*3+2];
        float xv1 = sv[3]*sng[n*3+0] + sv[4]*sng[n*3+1] + sv[5]*sng[n*3+2];
        g_h[(v * NGRID + n) * HID + c] = s + xv0 * w16 + xv1 * w17;
    }
}

__global__ void kbsh_kernel(const float* __restrict__ Wsh1, const float* __restrict__ bsh1,
                            const float* __restrict__ Wsh2, const float* __restrict__ bsh2) {
    int row = blockIdx.x;
    int p = row / NGRID, o = row % NGRID;
    int c = threadIdx.x;
    __shared__ float h1[HID];
    float t = g_grid0[p*3+0]*g_grid0[o*3+0] + g_grid0[p*3+1]*g_grid0[o*3+1] + g_grid0[p*3+2]*g_grid0[o*3+2];
    float v = t*Wsh1[c] + t*t*Wsh1[HID+c] + t*t*t*Wsh1[2*HID+c] + bsh1[c];
    h1[c] = gelu_f(v);
    __syncthreads();
    float acc = bsh2[c];
    #pragma unroll 8
    for (int k = 0; k < HID; k++) acc = fmaf(h1[k], Wsh2[k*HID + c], acc);
    g_kb_sh[row * HID + c] = gelu_f(acc);
}

__global__ void fk_kernel(const float* __restrict__ Wfk) {
    int blk = blockIdx.x;
    int ll = blk / 144, row = blk % 144;
    int c = threadIdx.x;
    __shared__ float r128[HID];
    r128[c] = g_kb_sh[row * HID + c];
    __syncthreads();
    const float* W = Wfk + ll * HID * HID;
    float acc = 0.0f;
    #pragma unroll 8
    for (int k = 0; k < HID; k++) acc = fmaf(r128[k], W[k*HID + c], acc);
    g_fk[ll * 144 * HID + row * HID + c] = acc;
}

__global__ void poly_kernel(const float* __restrict__ pos,
                            const int* __restrict__ send, const int* __restrict__ recv) {
    int r = blockIdx.x * 256 + threadIdx.x;
    if (r >= R_E) return;
    int e = r / NGRID, o = r % NGRID;
    int s = send[e], rc = recv[e];
    float rx = pos[s*3+0]-pos[rc*3+0], ry = pos[s*3+1]-pos[rc*3+1], rz = pos[s*3+2]-pos[rc*3+2];
    const float* g = &g_node_grid[(rc * NGRID + o) * 3];
    float inv1 = rx*g[0] + ry*g[1] + rz*g[2];
    float dx = rx-inv1*g[0], dy = ry-inv1*g[1], dz = rz-inv1*g[2];
    float inv2 = sqrtf(dx*dx + dy*dy + dz*dz);
    float q[16];
    float a = inv1, b = inv2;
    q[0]=a; q[1]=b; q[2]=a*a; q[3]=a*b; q[4]=b*a; q[5]=b*b;
    q[6]=q[2]*a; q[7]=q[2]*b; q[8]=q[3]*a; q[9]=q[3]*b;
    q[10]=q[4]*a; q[11]=q[4]*b; q[12]=q[5]*a; q[13]=q[5]*b;
    q[14]=0.0f; q[15]=0.0f;
    size_t base = (size_t)r * 32;
    #pragma unroll
    for (int j = 0; j < 16; j += 2) {
        unsigned short h0, l0, h1, l1;
        split2(q[j], h0, l0); split2(q[j+1], h1, l1);
        *(uint32_t*)(g_poly_h + base + j) = (uint32_t)h0 | ((uint32_t)h1 << 16);
        *(uint32_t*)(g_poly_l + base + j) = (uint32_t)l0 | ((uint32_t)l1 << 16);
    }
    #pragma unroll
    for (int j = 16; j < 32; j += 2) {
        *(uint32_t*)(g_poly_h + base + j) = 0u;
        *(uint32_t*)(g_poly_l + base + j) = 0u;
    }
}

__global__ void conv_ln_kernel(const float* __restrict__ agg, const float* __restrict__ fk,
                               const float* __restrict__ bconv, const float* __restrict__ lng,
                               const float* __restrict__ lnb) {
    int v = blockIdx.x;
    int c = threadIdx.x;
    float a[NGRID];
    #pragma unroll
    for (int o = 0; o < NGRID; o++) a[o] = agg[(v * NGRID + o) * HID + c];
    __shared__ float warp_red[4];
    __shared__ float bc_val;
    int lane = c & 31, wd = c >> 5;
    float gc = lng[c], bbc = lnb[c], bcv = bconv[c];
    for (int p = 0; p < NGRID; p++) {
        float s = 0.0f;
        #pragma unroll
        for (int o = 0; o < NGRID; o++) s = fmaf(a[o], fk[(p * NGRID + o) * HID + c], s);
        s = s * (1.0f / NGRID) + bcv;
        float t = s;
        #pragma unroll
        for (int off = 16; off > 0; off >>= 1) t += __shfl_xor_sync(0xffffffffu, t, off);
        if (lane == 0) warp_red[wd] = t;
        __syncthreads();
        if (c == 0) bc_val = (warp_red[0]+warp_red[1]+warp_red[2]+warp_red[3]) * (1.0f / HID);
        __syncthreads();
        float mu = bc_val, d = s - mu;
        t = d * d;
        #pragma unroll
        for (int off = 16; off > 0; off >>= 1) t += __shfl_xor_sync(0xffffffffu, t, off);
        if (lane == 0) warp_red[wd] = t;
        __syncthreads();
        if (c == 0) bc_val = rsqrtf((warp_red[0]+warp_red[1]+warp_red[2]+warp_red[3]) * (1.0f/HID) + 1e-5f);
        __syncthreads();
        float val = d * bc_val * gc + bbc;
        unsigned short hh, lll;
        split2(val, hh, lll);
        size_t idx = (size_t)(v * NGRID + p) * HID + c;
        g_hn_h[idx] = hh;
        g_hn_l[idx] = lll;
        __syncthreads();
    }
}

__global__ void readout_kernel(const float* __restrict__ h, const float* __restrict__ Wro,
                               const float* __restrict__ bro) {
    __shared__ float hs[16 * 129];
    int tid = threadIdx.x;
    int r0 = blockIdx.x * 16;
    for (int i = tid; i < 16 * 128; i += 160) {
        int row = i >> 7, cc = i & 127;
        hs[row * 129 + cc] = h[(size_t)(r0 + row) * HID + cc];
    }
    __syncthreads();
    if (tid < 16 * 9) {
        int row = tid / 9, oc = tid % 9;
        float acc = bro[oc];
        #pragma unroll 8
        for (int cc = 0; cc < 128; cc++) acc = fmaf(hs[row * 129 + cc], Wro[cc * 9 + oc], acc);
        g_readout[(r0 + row) * 9 + oc] += acc * (1.0f / NLAYERS);
    }
}

__global__ void finalize_kernel(const int* __restrict__ batch, float* __restrict__ out) {
    int v = blockIdx.x * 256 + threadIdx.x;
    if (v >= N_NODES) return;
    float ssum[OUT_S] = {0,0,0,0,0,0,0,0};
    float vsum[3] = {0,0,0};
    for (int n = 0; n < NGRID; n++) {
        const float* rr = &g_readout[(v * NGRID + n) * 9];
        #pragma unroll
        for (int j = 0; j < OUT_S; j++) ssum[j] += rr[j];
        float rv = rr[OUT_S];
        const float* g = &g_node_grid[(v * NGRID + n) * 3];
        vsum[0] += rv * g[0]; vsum[1] += rv * g[1]; vsum[2] += rv * g[2];
    }
    int b = batch[v];
    #pragma unroll
    for (int j = 0; j < OUT_S; j++) atomicAdd(&out[b * OUT_S + j], ssum[j] * (1.0f / NGRID));
    #pragma unroll
    for (int d = 0; d < 3; d++) atomicAdd(&out[NBATCH * OUT_S + b * 3 + d], vsum[d] * (1.0f / NGRID));
}

__global__ void zero_kernel(float* __restrict__ p, int n) {
    for (int i = blockIdx.x * blockDim.x + threadIdx.x; i < n; i += gridDim.x * blockDim.x)
        p[i] = 0.0f;
}
__global__ void zero_sym_kernel(int which) {
    int stride = gridDim.x * blockDim.x;
    if (which == 0) {
        for (int i = blockIdx.x*blockDim.x+threadIdx.x; i < R_N*HID; i += stride) g_agg[i] = 0.0f;
    } else {
        for (int i = blockIdx.x*blockDim.x+threadIdx.x; i < R_N*9; i += stride) g_readout[i] = 0.0f;
    }
}

// ---------------------------------------------------------------------------
// Host launcher — ordered so launch #6 (ncu -s 5 -c 1) is the K=128 edge GEMM
// ---------------------------------------------------------------------------
extern "C" void kernel_launch(void* const* d_in, const int* in_sizes, int n_in,
                              void* d_out, int out_size) {
    const float* x    = (const float*)d_in[0];
    const float* vec  = (const float*)d_in[1];
    const float* pos  = (const float*)d_in[2];
    const float* Q    = (const float*)d_in[3];
    const float* Wsp1 = (const float*)d_in[4];
    const float* bsp1 = (const float*)d_in[5];
    const float* Wsp2 = (const float*)d_in[6];
    const float* bsp2 = (const float*)d_in[7];
    const float* Wsh1 = (const float*)d_in[8];
    const float* bsh1 = (const float*)d_in[9];
    const float* Wsh2 = (const float*)d_in[10];
    const float* bsh2 = (const float*)d_in[11];
    const float* Wemb = (const float*)d_in[12];
    const float* Wk   = (const float*)d_in[13];
    const float* Wfk  = (const float*)d_in[14];
    const float* bconv= (const float*)d_in[15];
    const float* ln_g = (const float*)d_in[16];
    const float* ln_b = (const float*)d_in[17];
    const float* W1   = (const float*)d_in[18];
    const float* b1   = (const float*)d_in[19];
    const float* W2   = (const float*)d_in[20];
    const float* b2   = (const float*)d_in[21];
    const float* Wro  = (const float*)d_in[22];
    const float* bro  = (const float*)d_in[23];
    const int*   eidx = (const int*)d_in[24];
    const int*   batch= (const int*)d_in[25];
    float* out = (float*)d_out;
    const int* send = eidx;
    const int* recv = eidx + N_EDGES;

    float *p_h, *p_agg, *p_fk;
    unsigned short *p_ph,*p_pl,*p_b1h,*p_b1l,*p_kbh,*p_kbl,*p_hnh,*p_hnl;
    unsigned short *p_wsp1h,*p_wsp1l,*p_wsp2h,*p_wsp2l,*p_wkh,*p_wkl,*p_w1h,*p_w1l,*p_w2h,*p_w2l;
    cudaGetSymbolAddress((void**)&p_h,   g_h);
    cudaGetSymbolAddress((void**)&p_agg, g_agg);
    cudaGetSymbolAddress((void**)&p_fk,  g_fk);
    cudaGetSymbolAddress((void**)&p_ph,  g_poly_h);  cudaGetSymbolAddress((void**)&p_pl,  g_poly_l);
    cudaGetSymbolAddress((void**)&p_b1h, g_buf1_h);  cudaGetSymbolAddress((void**)&p_b1l, g_buf1_l);
    cudaGetSymbolAddress((void**)&p_kbh, g_kbsp_h);  cudaGetSymbolAddress((void**)&p_kbl, g_kbsp_l);
    cudaGetSymbolAddress((void**)&p_hnh, g_hn_h);    cudaGetSymbolAddress((void**)&p_hnl, g_hn_l);
    cudaGetSymbolAddress((void**)&p_wsp1h, g_wsp1_h); cudaGetSymbolAddress((void**)&p_wsp1l, g_wsp1_l);
    cudaGetSymbolAddress((void**)&p_wsp2h, g_wsp2_h); cudaGetSymbolAddress((void**)&p_wsp2l, g_wsp2_l);
    cudaGetSymbolAddress((void**)&p_wkh, g_wk_h);    cudaGetSymbolAddress((void**)&p_wkl, g_wk_l);
    cudaGetSymbolAddress((void**)&p_w1h, g_w1_h);    cudaGetSymbolAddress((void**)&p_w1l, g_w1_l);
    cudaGetSymbolAddress((void**)&p_w2h, g_w2_h);    cudaGetSymbolAddress((void**)&p_w2l, g_w2_l);

    cudaFuncSetAttribute(hmma_gemm<0>, cudaFuncAttributeMaxDynamicSharedMemorySize, SMEM_DYN);
    cudaFuncSetAttribute(hmma_gemm<1>, cudaFuncAttributeMaxDynamicSharedMemorySize, SMEM_DYN);
    cudaFuncSetAttribute(hmma_gemm<2>, cudaFuncAttributeMaxDynamicSharedMemorySize, SMEM_DYN);

    // launches 1-5: embed, poly, wprep(wsp1), wprep(wsp2), gemm1
    embed_kernel<<<N_NODES, 128>>>(x, vec, Q, batch, Wemb);                       // 1
    poly_kernel<<<(R_E + 255) / 256, 256>>>(pos, send, recv);                     // 2
    wprep_kernel<<<(32*128 + 255)/256, 256>>>(Wsp1, 14, 32, 128, p_wsp1h, p_wsp1l);       // 3
    wprep_kernel<<<(128*128 + 255)/256, 256>>>(Wsp2, 128, 128, 128, p_wsp2h, p_wsp2l);    // 4
    hmma_gemm<0><<<dim3(R_E / 128, 1), 128, SMEM_DYN>>>(p_ph, p_pl, 32, p_wsp1h, p_wsp1l, 128,
                                                        1, 1, 128, bsp1, nullptr, nullptr, p_b1h, p_b1l,
                                                        nullptr, nullptr);                 // 5
    // launch 6 — PROFILED by ncu (-s 5 -c 1): representative K=128 edge GEMM
    hmma_gemm<0><<<dim3(R_E / 128, 1), 128, SMEM_DYN>>>(p_b1h, p_b1l, 128, p_wsp2h, p_wsp2l, 128,
                                                        4, 8, 128, bsp2, nullptr, nullptr, p_kbh, p_kbl,
                                                        nullptr, nullptr);                 // 6

    // remaining setup
    kbsh_kernel<<<144, 128>>>(Wsh1, bsh1, Wsh2, bsh2);
    fk_kernel<<<NLAYERS * 144, 128>>>(Wfk);
    for (int l = 0; l < NLAYERS; l++) {
        wprep_kernel<<<(128*128 + 255)/256, 256>>>(Wk + l*128*128, 128, 128, 128,
                                                   p_wkh + l*128*128, p_wkl + l*128*128);
        wprep_kernel<<<(128*512 + 255)/256, 256>>>(W1 + l*128*512, 128, 128, 512,
                                                   p_w1h + l*128*512, p_w1l + l*128*512);
        wprep_kernel<<<(512*128 + 255)/256, 256>>>(W2 + l*512*128, 512, 512, 128,
                                                   p_w2h + l*512*128, p_w2l + l*512*128);
    }

    zero_sym_kernel<<<1024, 256>>>(1);

    for (int l = 0; l < NLAYERS; l++) {
        zero_sym_kernel<<<4096, 256>>>(0);
        hmma_gemm<1><<<dim3(R_E / 128, 1), 128, SMEM_DYN>>>(p_kbh, p_kbl, 128,
                                                  p_wkh + l*128*128, p_wkl + l*128*128, 128,
                                                  4, 8, 128, nullptr, p_h, p_agg, nullptr, nullptr,
                                                  send, recv);
        conv_ln_kernel<<<N_NODES, 128>>>(p_agg, p_fk + l * 144 * HID,
                                         bconv + l * HID, ln_g + l * HID, ln_b + l * HID);
        hmma_gemm<0><<<dim3(R_N / 128, 4), 128, SMEM_DYN>>>(p_hnh, p_hnl, 128,
                                                  p_w1h + l*128*512, p_w1l + l*128*512, 512,
                                                  4, 8, 512, b1 + l*512, nullptr, nullptr, p_b1h, p_b1l,
                                                  nullptr, nullptr);
        hmma_gemm<2><<<dim3(R_N / 128, 1), 128, SMEM_DYN>>>(p_b1h, p_b1l, 512,
                                                  p_w2h + l*512*128, p_w2l + l*512*128, 128,
                                                  16, 32, 128, b2 + l*128, p_h, p_h, nullptr, nullptr,
                                                  nullptr, nullptr);
        readout_kernel<<<R_N / 16, 160>>>(p_h, Wro + l * HID * 9, bro + l * 9);
    }

    int out_elems = NBATCH * OUT_S + NBATCH * 3;
    zero_kernel<<<(out_elems + 255) / 256, 256>>>(out, out_elems);
    finalize_kernel<<<(N_NODES + 255) / 256, 256>>>(batch, out);
}

// round 13
// speedup vs baseline: 2.6338x; 1.0138x over previous
#include <cuda_runtime.h>
#include <cuda_bf16.h>
#include <math.h>
#include <stdint.h>

#define N_NODES 8000
#define N_EDGES 64000
#define NBATCH  64
#define NGRID   12
#define HID     128
#define NLAYERS 3
#define IN_S    16
#define OUT_S   8
#define WIDE    4
#define R_E (N_EDGES * NGRID)   // 768000
#define R_N (N_NODES * NGRID)   // 96000

// ---------------------------------------------------------------------------
// Device scratch
// ---------------------------------------------------------------------------
__device__ float g_grid0[NGRID * 3];
__device__ float g_node_grid[R_N * 3];
__device__ float g_kb_sh[144 * HID];
__device__ float g_fk[NLAYERS * 144 * HID];
__device__ float g_h[R_N * HID];
__device__ float g_agg[R_N * HID];
__device__ float g_readout[R_N * (OUT_S + 1)];

// bf16 hi/lo split operand storage
__device__ unsigned short g_poly_h[R_E * 32],  g_poly_l[R_E * 32];
__device__ unsigned short g_buf1_h[R_E * 128], g_buf1_l[R_E * 128];
__device__ unsigned short g_kbsp_h[R_E * 128], g_kbsp_l[R_E * 128];
__device__ unsigned short g_hn_h[R_N * 128],   g_hn_l[R_N * 128];
__device__ unsigned short g_wsp1_h[32 * 128],  g_wsp1_l[32 * 128];
__device__ unsigned short g_wsp2_h[128 * 128], g_wsp2_l[128 * 128];
__device__ unsigned short g_wk_h[NLAYERS * 128 * 128], g_wk_l[NLAYERS * 128 * 128];
__device__ unsigned short g_w1_h[NLAYERS * 128 * 512], g_w1_l[NLAYERS * 128 * 512];
__device__ unsigned short g_w2_h[NLAYERS * 512 * 128], g_w2_l[NLAYERS * 512 * 128];

__device__ __forceinline__ float gelu_f(float x) {
    return 0.5f * x * (1.0f + erff(x * 0.70710678118654752440f));
}
__device__ __forceinline__ uint32_t sptr(const void* p) {
    uint32_t a;
    asm("{ .reg .u64 t; cvta.to.shared.u64 t, %1; cvt.u32.u64 %0, t; }" : "=r"(a) : "l"(p));
    return a;
}
__device__ __forceinline__ void ldsm_x4(uint32_t* r, uint32_t addr) {
    asm volatile("ldmatrix.sync.aligned.m8n8.x4.shared.b16 {%0,%1,%2,%3}, [%4];"
                 : "=r"(r[0]), "=r"(r[1]), "=r"(r[2]), "=r"(r[3]) : "r"(addr));
}
__device__ __forceinline__ void ldsm_x4t(uint32_t* r, uint32_t addr) {
    asm volatile("ldmatrix.sync.aligned.m8n8.x4.trans.shared.b16 {%0,%1,%2,%3}, [%4];"
                 : "=r"(r[0]), "=r"(r[1]), "=r"(r[2]), "=r"(r[3]) : "r"(addr));
}
__device__ __forceinline__ void mma16816(float* c, const uint32_t* a, const uint32_t* b) {
    asm volatile("mma.sync.aligned.m16n8k16.row.col.f32.bf16.bf16.f32 "
                 "{%0,%1,%2,%3}, {%4,%5,%6,%7}, {%8,%9}, {%0,%1,%2,%3};"
                 : "+f"(c[0]), "+f"(c[1]), "+f"(c[2]), "+f"(c[3])
                 : "r"(a[0]), "r"(a[1]), "r"(a[2]), "r"(a[3]), "r"(b[0]), "r"(b[1]));
}
__device__ __forceinline__ void split2(float v, unsigned short& h, unsigned short& l) {
    __nv_bfloat16 hb = __float2bfloat16(v);
    h = __bfloat16_as_ushort(hb);
    l = __bfloat16_as_ushort(__float2bfloat16(v - __bfloat162float(hb)));
}
__device__ __forceinline__ void cpasync16(uint32_t dst, const void* src) {
    asm volatile("cp.async.cg.shared.global [%0], [%1], 16;" :: "r"(dst), "l"(src));
}
__device__ __forceinline__ void cp_commit() {
    asm volatile("cp.async.commit_group;" ::: "memory");
}
template<int N>
__device__ __forceinline__ void cp_wait() {
    asm volatile("cp.async.wait_group %0;" :: "n"(N) : "memory");
}

// ---------------------------------------------------------------------------
// smem stage layout (ushort units)
// ---------------------------------------------------------------------------
#define A_STR 40
#define B_STR 136
#define ST_AH 0
#define ST_AL (128 * A_STR)
#define ST_BH (2 * 128 * A_STR)
#define ST_BL (2 * 128 * A_STR + 32 * B_STR)
#define STAGE_USH (2 * 128 * A_STR + 2 * 32 * B_STR)
#define SMEM_DYN (2 * STAGE_USH * 2)

// ---------------------------------------------------------------------------
// HMMA GEMM (unchanged from R12 pass-major version)
// ---------------------------------------------------------------------------
template<int MODE>
__global__ __launch_bounds__(128, 2)
void hmma_gemm(const unsigned short* __restrict__ Ah, const unsigned short* __restrict__ Al, int lda,
               const unsigned short* __restrict__ Bh, const unsigned short* __restrict__ Bl, int ldb,
               int Ktiles, int Ks16, int N,
               const float* __restrict__ bias, const float* __restrict__ aux,
               float* __restrict__ Cf, unsigned short* __restrict__ Ch, unsigned short* __restrict__ Cl,
               const int* __restrict__ send, const int* __restrict__ recv)
{
    extern __shared__ __align__(16) unsigned short smem[];
    __shared__ int hrow[128], arow[128];

    const int tid = threadIdx.x;
    const int l   = tid & 31;
    const int wid = tid >> 5;
    const int wm  = wid & 1;
    const int wn  = wid >> 1;
    const int row0 = blockIdx.x * 128;
    const int nbase = blockIdx.y * 128;

    if (MODE == 1) {
        int r = row0 + tid;
        int e = r / NGRID, o = r - e * NGRID;
        hrow[tid] = send[e] * NGRID + o;
        arow[tid] = recv[e] * NGRID + o;
    }

    float acc[4][8][4];
    #pragma unroll
    for (int i = 0; i < 4; i++)
        #pragma unroll
        for (int j = 0; j < 8; j++)
            #pragma unroll
            for (int q = 0; q < 4; q++) acc[i][j][q] = 0.0f;

    const int a_row = (l & 7) + (((l >> 3) & 1) << 3);
    const int a_col = (l >> 4) << 3;
    const int bg = l >> 3, br = l & 7;
    const int b_lane_off = ((bg & 1) * 8 + br) * B_STR + (bg >> 1) * 8;

    auto issue_tile = [&](int kt, int stage) {
        unsigned short* st = smem + stage * STAGE_USH;
        const int k0 = kt * 32;
        uint32_t sA = sptr(st);
        #pragma unroll
        for (int j = 0; j < 4; j++) {
            int i = tid + j * 128;
            int ar = i >> 2, ac = (i & 3) << 3;
            size_t gA = (size_t)(row0 + ar) * lda + k0 + ac;
            cpasync16(sA + (ST_AH + ar * A_STR + ac) * 2, Ah + gA);
            cpasync16(sA + (ST_AL + ar * A_STR + ac) * 2, Al + gA);
            int bk = i >> 4, bc = (i & 15) << 3;
            size_t gB = (size_t)(k0 + bk) * ldb + nbase + bc;
            cpasync16(sA + (ST_BH + bk * B_STR + bc) * 2, Bh + gB);
            cpasync16(sA + (ST_BL + bk * B_STR + bc) * 2, Bl + gB);
        }
        cp_commit();
    };

    issue_tile(0, 0);

    for (int kt = 0; kt < Ktiles; kt++) {
        const int stage = kt & 1;
        if (kt + 1 < Ktiles) {
            issue_tile(kt + 1, stage ^ 1);
            cp_wait<1>();
        } else {
            cp_wait<0>();
        }
        __syncthreads();

        unsigned short* st = smem + stage * STAGE_USH;
        unsigned short* sAh = st + ST_AH;
        unsigned short* sAl = st + ST_AL;
        unsigned short* sBh = st + ST_BH;
        unsigned short* sBl = st + ST_BL;

        const int ksmax = min(2, Ks16 - kt * 2);
        for (int ks = 0; ks < ksmax; ks++) {
            uint32_t ah[4][4], al[4][4], bh[4][4], bl[4][4];
            #pragma unroll
            for (int tm = 0; tm < 4; tm++) {
                int rr = wm * 64 + tm * 16 + a_row;
                int cc = ks * 16 + a_col;
                ldsm_x4(ah[tm], sptr(sAh + rr * A_STR + cc));
                ldsm_x4(al[tm], sptr(sAl + rr * A_STR + cc));
            }
            #pragma unroll
            for (int tn2 = 0; tn2 < 4; tn2++) {
                int nn = wn * 64 + tn2 * 16;
                uint32_t baddr = ks * 16 * B_STR + nn + b_lane_off;
                ldsm_x4t(bh[tn2], sptr(sBh + baddr));
                ldsm_x4t(bl[tn2], sptr(sBl + baddr));
            }
            #pragma unroll
            for (int tm = 0; tm < 4; tm++)
                #pragma unroll
                for (int tn2 = 0; tn2 < 4; tn2++) {
                    mma16816(acc[tm][2*tn2],     ah[tm], bh[tn2]);
                    mma16816(acc[tm][2*tn2 + 1], ah[tm], bh[tn2] + 2);
                }
            #pragma unroll
            for (int tm = 0; tm < 4; tm++)
                #pragma unroll
                for (int tn2 = 0; tn2 < 4; tn2++) {
                    mma16816(acc[tm][2*tn2],     ah[tm], bl[tn2]);
                    mma16816(acc[tm][2*tn2 + 1], ah[tm], bl[tn2] + 2);
                }
            #pragma unroll
            for (int tm = 0; tm < 4; tm++)
                #pragma unroll
                for (int tn2 = 0; tn2 < 4; tn2++) {
                    mma16816(acc[tm][2*tn2],     al[tm], bh[tn2]);
                    mma16816(acc[tm][2*tn2 + 1], al[tm], bh[tn2] + 2);
                }
        }
        __syncthreads();
    }

    // epilogue
    #pragma unroll
    for (int tm = 0; tm < 4; tm++) {
        int lr0 = wm * 64 + tm * 16 + (l >> 2);
        int lr1 = lr0 + 8;
        #pragma unroll
        for (int tn = 0; tn < 8; tn++) {
            int cc = nbase + wn * 64 + tn * 8 + (l & 3) * 2;
            float* a4 = acc[tm][tn];
            if (MODE == 0) {
                float v00 = gelu_f(a4[0] + bias[cc]);
                float v01 = gelu_f(a4[1] + bias[cc + 1]);
                float v10 = gelu_f(a4[2] + bias[cc]);
                float v11 = gelu_f(a4[3] + bias[cc + 1]);
                unsigned short h0, l0, h1, l1;
                size_t o0 = (size_t)(row0 + lr0) * N + cc;
                size_t o1 = (size_t)(row0 + lr1) * N + cc;
                split2(v00, h0, l0); split2(v01, h1, l1);
                *(uint32_t*)(Ch + o0) = (uint32_t)h0 | ((uint32_t)h1 << 16);
                *(uint32_t*)(Cl + o0) = (uint32_t)l0 | ((uint32_t)l1 << 16);
                split2(v10, h0, l0); split2(v11, h1, l1);
                *(uint32_t*)(Ch + o1) = (uint32_t)h0 | ((uint32_t)h1 << 16);
                *(uint32_t*)(Cl + o1) = (uint32_t)l0 | ((uint32_t)l1 << 16);
            } else if (MODE == 1) {
                int h0 = hrow[lr0] * 128 + cc, gg0 = arow[lr0] * 128 + cc;
                int h1 = hrow[lr1] * 128 + cc, gg1 = arow[lr1] * 128 + cc;
                float2 hv0 = *(const float2*)(aux + h0);
                float2 hv1 = *(const float2*)(aux + h1);
                atomicAdd(&Cf[gg0],     a4[0] * hv0.x);
                atomicAdd(&Cf[gg0 + 1], a4[1] * hv0.y);
                atomicAdd(&Cf[gg1],     a4[2] * hv1.x);
                atomicAdd(&Cf[gg1 + 1], a4[3] * hv1.y);
            } else {
                size_t o0 = (size_t)(row0 + lr0) * N + cc;
                size_t o1 = (size_t)(row0 + lr1) * N + cc;
                Cf[o0]     = a4[0] + bias[cc]     + aux[o0];
                Cf[o0 + 1] = a4[1] + bias[cc + 1] + aux[o0 + 1];
                Cf[o1]     = a4[2] + bias[cc]     + aux[o1];
                Cf[o1 + 1] = a4[3] + bias[cc + 1] + aux[o1 + 1];
            }
        }
    }
}

// ---------------------------------------------------------------------------
// embed (includes fibonacci grid0)
// ---------------------------------------------------------------------------
__global__ void embed_kernel(const float* __restrict__ x, const float* __restrict__ vec,
                             const float* __restrict__ Q, const int* __restrict__ batch,
                             const float* __restrict__ Wemb) {
    int v = blockIdx.x;
    int c = threadIdx.x;
    __shared__ float sQ[9], sx[IN_S], sv[6], sng[NGRID * 3], sg0[NGRID * 3];
    int b = batch[v];
    if (c < NGRID) {
        const float golden = 1.61803398874989484820f;
        float fi = (float)c;
        float theta = 6.28318530717958647692f * fi / golden;
        float z = 1.0f - (2.0f * fi + 1.0f) / (float)NGRID;
        float r = sqrtf(fmaxf(1.0f - z * z, 0.0f));
        float g0 = r * cosf(theta), g1 = r * sinf(theta);
        sg0[c*3+0] = g0; sg0[c*3+1] = g1; sg0[c*3+2] = z;
        if (v == 0) { g_grid0[c*3+0] = g0; g_grid0[c*3+1] = g1; g_grid0[c*3+2] = z; }
    }
    if (c < 9)  sQ[c] = Q[b * 9 + c];
    if (c < IN_S) sx[c] = x[v * IN_S + c];
    if (c < 6)  sv[c] = vec[v * 6 + c];
    __syncthreads();
    if (c < NGRID * 3) {
        int n = c / 3, i = c % 3;
        float t = sQ[i*3+0]*sg0[n*3+0] + sQ[i*3+1]*sg0[n*3+1] + sQ[i*3+2]*sg0[n*3+2];
        sng[c] = t;
        g_node_grid[v * NGRID * 3 + c] = t;
    }
    __syncthreads();
    float s = 0.0f;
    #pragma unroll
    for (int j = 0; j < IN_S; j++) s = fmaf(sx[j], Wemb[j * HID + c], s);
    float w16 = Wemb[IN_S * HID + c], w17 = Wemb[(IN_S + 1) * HID + c];
    #pragma unroll
    for (int n = 0; n < NGRID; n++) {
        float xv0 = sv[0]*sng[n*3+0] + sv[1]*sng[n*3+1] + sv[2]*sng[n*3+2];
        float xv1 = sv[3]*sng[n*3+0] + sv[4]*sng[n*3+1] + sv[5]*sng[n*3+2];
        g_h[(v * NGRID + n) * HID + c] = s + xv0 * w16 + xv1 * w17;
    }
}

// ---------------------------------------------------------------------------
// Combined poly + ALL weight-prep in one launch.
// Blocks [0, 3000): poly rows. Blocks [3000, 4808): weight splitting.
// ---------------------------------------------------------------------------
#define POLY_BLOCKS 3000
#define WPREP_ELEMS 462848   // 4096 + 16384 + 3*(16384+65536+65536)
#define WPREP_BLOCKS 1808

__global__ void poly_wprep_kernel(const float* __restrict__ pos,
                                  const int* __restrict__ send, const int* __restrict__ recv,
                                  const float* __restrict__ Wsp1, const float* __restrict__ Wsp2,
                                  const float* __restrict__ Wk, const float* __restrict__ W1,
                                  const float* __restrict__ W2) {
    if (blockIdx.x < POLY_BLOCKS) {
        int r = blockIdx.x * 256 + threadIdx.x;
        int e = r / NGRID, o = r % NGRID;
        int s = send[e], rc = recv[e];
        float rx = pos[s*3+0]-pos[rc*3+0], ry = pos[s*3+1]-pos[rc*3+1], rz = pos[s*3+2]-pos[rc*3+2];
        const float* g = &g_node_grid[(rc * NGRID + o) * 3];
        float inv1 = rx*g[0] + ry*g[1] + rz*g[2];
        float dx = rx-inv1*g[0], dy = ry-inv1*g[1], dz = rz-inv1*g[2];
        float inv2 = sqrtf(dx*dx + dy*dy + dz*dz);
        float q[16];
        float a = inv1, b = inv2;
        q[0]=a; q[1]=b; q[2]=a*a; q[3]=a*b; q[4]=b*a; q[5]=b*b;
        q[6]=q[2]*a; q[7]=q[2]*b; q[8]=q[3]*a; q[9]=q[3]*b;
        q[10]=q[4]*a; q[11]=q[4]*b; q[12]=q[5]*a; q[13]=q[5]*b;
        q[14]=0.0f; q[15]=0.0f;
        size_t base = (size_t)r * 32;
        #pragma unroll
        for (int j = 0; j < 16; j += 2) {
            unsigned short h0, l0, h1, l1;
            split2(q[j], h0, l0); split2(q[j+1], h1, l1);
            *(uint32_t*)(g_poly_h + base + j) = (uint32_t)h0 | ((uint32_t)h1 << 16);
            *(uint32_t*)(g_poly_l + base + j) = (uint32_t)l0 | ((uint32_t)l1 << 16);
        }
        #pragma unroll
        for (int j = 16; j < 32; j += 2) {
            *(uint32_t*)(g_poly_h + base + j) = 0u;
            *(uint32_t*)(g_poly_l + base + j) = 0u;
        }
    } else {
        int i = (blockIdx.x - POLY_BLOCKS) * 256 + threadIdx.x;
        if (i >= WPREP_ELEMS) return;
        float v;
        unsigned short *hi, *lo;
        size_t idx;
        if (i < 4096) {                       // Wsp1: Ktrue=14, Kpad=32, N=128
            int k = i >> 7;
            v = (k < 14) ? Wsp1[i] : 0.0f;
            hi = g_wsp1_h; lo = g_wsp1_l; idx = i;
        } else if (i < 20480) {               // Wsp2: 128x128
            int j = i - 4096;
            v = Wsp2[j];
            hi = g_wsp2_h; lo = g_wsp2_l; idx = j;
        } else {
            int j = i - 20480;
            int ll = j / 147456;
            int r2 = j - ll * 147456;
            if (r2 < 16384) {                 // Wk[ll]
                v = Wk[ll * 16384 + r2];
                hi = g_wk_h; lo = g_wk_l; idx = (size_t)ll * 16384 + r2;
            } else if (r2 < 81920) {          // W1[ll]
                int j2 = r2 - 16384;
                v = W1[ll * 65536 + j2];
                hi = g_w1_h; lo = g_w1_l; idx = (size_t)ll * 65536 + j2;
            } else {                          // W2[ll]
                int j2 = r2 - 81920;
                v = W2[ll * 65536 + j2];
                hi = g_w2_h; lo = g_w2_l; idx = (size_t)ll * 65536 + j2;
            }
        }
        unsigned short h, l;
        split2(v, h, l);
        hi[idx] = h; lo[idx] = l;
    }
}

__global__ void kbsh_kernel(const float* __restrict__ Wsh1, const float* __restrict__ bsh1,
                            const float* __restrict__ Wsh2, const float* __restrict__ bsh2) {
    int row = blockIdx.x;
    int p = row / NGRID, o = row % NGRID;
    int c = threadIdx.x;
    __shared__ float h1[HID];
    float t = g_grid0[p*3+0]*g_grid0[o*3+0] + g_grid0[p*3+1]*g_grid0[o*3+1] + g_grid0[p*3+2]*g_grid0[o*3+2];
    float v = t*Wsh1[c] + t*t*Wsh1[HID+c] + t*t*t*Wsh1[2*HID+c] + bsh1[c];
    h1[c] = gelu_f(v);
    __syncthreads();
    float acc = bsh2[c];
    #pragma unroll 8
    for (int k = 0; k < HID; k++) acc = fmaf(h1[k], Wsh2[k*HID + c], acc);
    g_kb_sh[row * HID + c] = gelu_f(acc);
}

__global__ void fk_kernel(const float* __restrict__ Wfk) {
    int blk = blockIdx.x;
    int ll = blk / 144, row = blk % 144;
    int c = threadIdx.x;
    __shared__ float r128[HID];
    r128[c] = g_kb_sh[row * HID + c];
    __syncthreads();
    const float* W = Wfk + ll * HID * HID;
    float acc = 0.0f;
    #pragma unroll 8
    for (int k = 0; k < HID; k++) acc = fmaf(r128[k], W[k*HID + c], acc);
    g_fk[ll * 144 * HID + row * HID + c] = acc;
}

// ---------------------------------------------------------------------------
// conv_ln v2: block = 384 threads = 12 warps (one per p), ONE barrier.
// agg staged in smem; fk via L1-cached float4 loads; shfl-only LN reduction.
// ---------------------------------------------------------------------------
__global__ __launch_bounds__(384)
void conv_ln_kernel(const float* __restrict__ agg, const float* __restrict__ fk,
                    const float* __restrict__ bconv, const float* __restrict__ lng,
                    const float* __restrict__ lnb) {
    int v = blockIdx.x;
    int tid = threadIdx.x, lane = tid & 31, wp = tid >> 5;   // wp = p (0..11)
    __shared__ float sagg[NGRID][HID];
    for (int i = tid; i < NGRID * HID; i += 384)
        sagg[i >> 7][i & 127] = agg[(size_t)v * NGRID * HID + i];
    __syncthreads();

    int c0 = lane * 4;
    float4 s = {0.0f, 0.0f, 0.0f, 0.0f};
    #pragma unroll
    for (int o = 0; o < NGRID; o++) {
        float4 a = *(const float4*)&sagg[o][c0];
        float4 f = *(const float4*)&fk[(size_t)(wp * NGRID + o) * HID + c0];
        s.x = fmaf(a.x, f.x, s.x);
        s.y = fmaf(a.y, f.y, s.y);
        s.z = fmaf(a.z, f.z, s.z);
        s.w = fmaf(a.w, f.w, s.w);
    }
    float4 bc = *(const float4*)&bconv[c0];
    float4 x;
    x.x = s.x * (1.0f / NGRID) + bc.x;
    x.y = s.y * (1.0f / NGRID) + bc.y;
    x.z = s.z * (1.0f / NGRID) + bc.z;
    x.w = s.w * (1.0f / NGRID) + bc.w;

    float t = x.x + x.y + x.z + x.w;
    #pragma unroll
    for (int off = 16; off > 0; off >>= 1) t += __shfl_xor_sync(0xffffffffu, t, off);
    float mu = t * (1.0f / HID);
    float4 d = {x.x - mu, x.y - mu, x.z - mu, x.w - mu};
    float t2 = d.x*d.x + d.y*d.y + d.z*d.z + d.w*d.w;
    #pragma unroll
    for (int off = 16; off > 0; off >>= 1) t2 += __shfl_xor_sync(0xffffffffu, t2, off);
    float rstd = rsqrtf(t2 * (1.0f / HID) + 1e-5f);

    float4 g = *(const float4*)&lng[c0];
    float4 bb = *(const float4*)&lnb[c0];
    float v0 = d.x * rstd * g.x + bb.x;
    float v1 = d.y * rstd * g.y + bb.y;
    float v2 = d.z * rstd * g.z + bb.z;
    float v3 = d.w * rstd * g.w + bb.w;

    unsigned short h0,l0,h1,l1,h2,l2,h3,l3;
    split2(v0,h0,l0); split2(v1,h1,l1); split2(v2,h2,l2); split2(v3,h3,l3);
    size_t idx = (size_t)(v * NGRID + wp) * HID + c0;
    uint2 ph = { (uint32_t)h0 | ((uint32_t)h1 << 16), (uint32_t)h2 | ((uint32_t)h3 << 16) };
    uint2 pl = { (uint32_t)l0 | ((uint32_t)l1 << 16), (uint32_t)l2 | ((uint32_t)l3 << 16) };
    *(uint2*)(g_hn_h + idx) = ph;
    *(uint2*)(g_hn_l + idx) = pl;
}

__global__ void readout_kernel(const float* __restrict__ h, const float* __restrict__ Wro,
                               const float* __restrict__ bro) {
    __shared__ float hs[16 * 129];
    int tid = threadIdx.x;
    int r0 = blockIdx.x * 16;
    for (int i = tid; i < 16 * 128; i += 160) {
        int row = i >> 7, cc = i & 127;
        hs[row * 129 + cc] = h[(size_t)(r0 + row) * HID + cc];
    }
    __syncthreads();
    if (tid < 16 * 9) {
        int row = tid / 9, oc = tid % 9;
        float acc = bro[oc];
        #pragma unroll 8
        for (int cc = 0; cc < 128; cc++) acc = fmaf(hs[row * 129 + cc], Wro[cc * 9 + oc], acc);
        g_readout[(r0 + row) * 9 + oc] += acc * (1.0f / NLAYERS);
    }
}

__global__ void finalize_kernel(const int* __restrict__ batch, float* __restrict__ out) {
    int v = blockIdx.x * 256 + threadIdx.x;
    if (v >= N_NODES) return;
    float ssum[OUT_S] = {0,0,0,0,0,0,0,0};
    float vsum[3] = {0,0,0};
    for (int n = 0; n < NGRID; n++) {
        const float* rr = &g_readout[(v * NGRID + n) * 9];
        #pragma unroll
        for (int j = 0; j < OUT_S; j++) ssum[j] += rr[j];
        float rv = rr[OUT_S];
        const float* g = &g_node_grid[(v * NGRID + n) * 3];
        vsum[0] += rv * g[0]; vsum[1] += rv * g[1]; vsum[2] += rv * g[2];
    }
    int b = batch[v];
    #pragma unroll
    for (int j = 0; j < OUT_S; j++) atomicAdd(&out[b * OUT_S + j], ssum[j] * (1.0f / NGRID));
    #pragma unroll
    for (int d = 0; d < 3; d++) atomicAdd(&out[NBATCH * OUT_S + b * 3 + d], vsum[d] * (1.0f / NGRID));
}

__global__ void zero_kernel(float* __restrict__ p, int n) {
    for (int i = blockIdx.x * blockDim.x + threadIdx.x; i < n; i += gridDim.x * blockDim.x)
        p[i] = 0.0f;
}
__global__ void zero_sym_kernel(int which) {
    int stride = gridDim.x * blockDim.x;
    if (which == 0) {
        for (int i = blockIdx.x*blockDim.x+threadIdx.x; i < R_N*HID; i += stride) g_agg[i] = 0.0f;
    } else {
        for (int i = blockIdx.x*blockDim.x+threadIdx.x; i < R_N*9; i += stride) g_readout[i] = 0.0f;
    }
}

// ---------------------------------------------------------------------------
// Host launcher — launch #4 (= ncu-profiled) is the representative K=128 GEMM
// ---------------------------------------------------------------------------
extern "C" void kernel_launch(void* const* d_in, const int* in_sizes, int n_in,
                              void* d_out, int out_size) {
    const float* x    = (const float*)d_in[0];
    const float* vec  = (const float*)d_in[1];
    const float* pos  = (const float*)d_in[2];
    const float* Q    = (const float*)d_in[3];
    const float* Wsp1 = (const float*)d_in[4];
    const float* bsp1 = (const float*)d_in[5];
    const float* Wsp2 = (const float*)d_in[6];
    const float* bsp2 = (const float*)d_in[7];
    const float* Wsh1 = (const float*)d_in[8];
    const float* bsh1 = (const float*)d_in[9];
    const float* Wsh2 = (const float*)d_in[10];
    const float* bsh2 = (const float*)d_in[11];
    const float* Wemb = (const float*)d_in[12];
    const float* Wk   = (const float*)d_in[13];
    const float* Wfk  = (const float*)d_in[14];
    const float* bconv= (const float*)d_in[15];
    const float* ln_g = (const float*)d_in[16];
    const float* ln_b = (const float*)d_in[17];
    const float* W1   = (const float*)d_in[18];
    const float* b1   = (const float*)d_in[19];
    const float* W2   = (const float*)d_in[20];
    const float* b2   = (const float*)d_in[21];
    const float* Wro  = (const float*)d_in[22];
    const float* bro  = (const float*)d_in[23];
    const int*   eidx = (const int*)d_in[24];
    const int*   batch= (const int*)d_in[25];
    float* out = (float*)d_out;
    const int* send = eidx;
    const int* recv = eidx + N_EDGES;

    float *p_h, *p_agg, *p_fk;
    unsigned short *p_ph,*p_pl,*p_b1h,*p_b1l,*p_kbh,*p_kbl,*p_hnh,*p_hnl;
    unsigned short *p_wsp1h,*p_wsp1l,*p_wsp2h,*p_wsp2l,*p_wkh,*p_wkl,*p_w1h,*p_w1l,*p_w2h,*p_w2l;
    cudaGetSymbolAddress((void**)&p_h,   g_h);
    cudaGetSymbolAddress((void**)&p_agg, g_agg);
    cudaGetSymbolAddress((void**)&p_fk,  g_fk);
    cudaGetSymbolAddress((void**)&p_ph,  g_poly_h);  cudaGetSymbolAddress((void**)&p_pl,  g_poly_l);
    cudaGetSymbolAddress((void**)&p_b1h, g_buf1_h);  cudaGetSymbolAddress((void**)&p_b1l, g_buf1_l);
    cudaGetSymbolAddress((void**)&p_kbh, g_kbsp_h);  cudaGetSymbolAddress((void**)&p_kbl, g_kbsp_l);
    cudaGetSymbolAddress((void**)&p_hnh, g_hn_h);    cudaGetSymbolAddress((void**)&p_hnl, g_hn_l);
    cudaGetSymbolAddress((void**)&p_wsp1h, g_wsp1_h); cudaGetSymbolAddress((void**)&p_wsp1l, g_wsp1_l);
    cudaGetSymbolAddress((void**)&p_wsp2h, g_wsp2_h); cudaGetSymbolAddress((void**)&p_wsp2l, g_wsp2_l);
    cudaGetSymbolAddress((void**)&p_wkh, g_wk_h);    cudaGetSymbolAddress((void**)&p_wkl, g_wk_l);
    cudaGetSymbolAddress((void**)&p_w1h, g_w1_h);    cudaGetSymbolAddress((void**)&p_w1l, g_w1_l);
    cudaGetSymbolAddress((void**)&p_w2h, g_w2_h);    cudaGetSymbolAddress((void**)&p_w2l, g_w2_l);

    cudaFuncSetAttribute(hmma_gemm<0>, cudaFuncAttributeMaxDynamicSharedMemorySize, SMEM_DYN);
    cudaFuncSetAttribute(hmma_gemm<1>, cudaFuncAttributeMaxDynamicSharedMemorySize, SMEM_DYN);
    cudaFuncSetAttribute(hmma_gemm<2>, cudaFuncAttributeMaxDynamicSharedMemorySize, SMEM_DYN);

    // 1: embed (grid0 + node_grid + h0)
    embed_kernel<<<N_NODES, 128>>>(x, vec, Q, batch, Wemb);
    // 2: poly features + ALL weight prep (fused)
    poly_wprep_kernel<<<POLY_BLOCKS + WPREP_BLOCKS, 256>>>(pos, send, recv, Wsp1, Wsp2, Wk, W1, W2);
    // 3: kb_sp GEMM1 (K=14 pad 16)
    hmma_gemm<0><<<dim3(R_E / 128, 1), 128, SMEM_DYN>>>(p_ph, p_pl, 32, p_wsp1h, p_wsp1l, 128,
                                                        1, 1, 128, bsp1, nullptr, nullptr, p_b1h, p_b1l,
                                                        nullptr, nullptr);
    // 4: kb_sp GEMM2 (K=128) — ncu-profiled launch
    hmma_gemm<0><<<dim3(R_E / 128, 1), 128, SMEM_DYN>>>(p_b1h, p_b1l, 128, p_wsp2h, p_wsp2l, 128,
                                                        4, 8, 128, bsp2, nullptr, nullptr, p_kbh, p_kbl,
                                                        nullptr, nullptr);
    // remaining setup
    kbsh_kernel<<<144, 128>>>(Wsh1, bsh1, Wsh2, bsh2);
    fk_kernel<<<NLAYERS * 144, 128>>>(Wfk);
    zero_sym_kernel<<<1024, 256>>>(1);

    for (int l = 0; l < NLAYERS; l++) {
        zero_sym_kernel<<<4096, 256>>>(0);
        hmma_gemm<1><<<dim3(R_E / 128, 1), 128, SMEM_DYN>>>(p_kbh, p_kbl, 128,
                                                  p_wkh + l*128*128, p_wkl + l*128*128, 128,
                                                  4, 8, 128, nullptr, p_h, p_agg, nullptr, nullptr,
                                                  send, recv);
        conv_ln_kernel<<<N_NODES, 384>>>(p_agg, p_fk + l * 144 * HID,
                                         bconv + l * HID, ln_g + l * HID, ln_b + l * HID);
        hmma_gemm<0><<<dim3(R_N / 128, 4), 128, SMEM_DYN>>>(p_hnh, p_hnl, 128,
                                                  p_w1h + l*128*512, p_w1l + l*128*512, 512,
                                                  4, 8, 512, b1 + l*512, nullptr, nullptr, p_b1h, p_b1l,
                                                  nullptr, nullptr);
        hmma_gemm<2><<<dim3(R_N / 128, 1), 128, SMEM_DYN>>>(p_b1h, p_b1l, 512,
                                                  p_w2h + l*512*128, p_w2l + l*512*128, 128,
                                                  16, 32, 128, b2 + l*128, p_h, p_h, nullptr, nullptr,
                                                  nullptr, nullptr);
        readout_kernel<<<R_N / 16, 160>>>(p_h, Wro + l * HID * 9, bro + l * 9);
    }

    int out_elems = NBATCH * OUT_S + NBATCH * 3;
    zero_kernel<<<(out_elems + 255) / 256, 256>>>(out, out_elems);
    finalize_kernel<<<(N_NODES + 255) / 256, 256>>>(batch, out);
}

// round 15
// speedup vs baseline: 2.6406x; 1.0026x over previous
#include <cuda_runtime.h>
#include <cuda_bf16.h>
#include <math.h>
#include <stdint.h>

#define N_NODES 8000
#define N_EDGES 64000
#define NBATCH  64
#define NGRID   12
#define HID     128
#define NLAYERS 3
#define IN_S    16
#define OUT_S   8
#define WIDE    4
#define R_E (N_EDGES * NGRID)   // 768000
#define R_N (N_NODES * NGRID)   // 96000

// ---------------------------------------------------------------------------
// Device scratch
// ---------------------------------------------------------------------------
__device__ float g_grid0[NGRID * 3];
__device__ float g_node_grid[R_N * 3];
__device__ float g_kb_sh[144 * HID];
__device__ float g_fk[NLAYERS * 144 * HID];
__device__ float g_h[R_N * HID];
__device__ float g_agg[R_N * HID];
__device__ float g_readout[R_N * (OUT_S + 1)];

// bf16 hi/lo split operand storage
__device__ unsigned short g_poly_h[R_E * 32],  g_poly_l[R_E * 32];
__device__ unsigned short g_buf1_h[R_E * 128], g_buf1_l[R_E * 128];
__device__ unsigned short g_kbsp_h[R_E * 128], g_kbsp_l[R_E * 128];
__device__ unsigned short g_hn_h[R_N * 128],   g_hn_l[R_N * 128];
__device__ unsigned short g_wsp1_h[32 * 128],  g_wsp1_l[32 * 128];
__device__ unsigned short g_wsp2_h[128 * 128], g_wsp2_l[128 * 128];
__device__ unsigned short g_wk_h[NLAYERS * 128 * 128], g_wk_l[NLAYERS * 128 * 128];
__device__ unsigned short g_w1_h[NLAYERS * 128 * 512], g_w1_l[NLAYERS * 128 * 512];
__device__ unsigned short g_w2_h[NLAYERS * 512 * 128], g_w2_l[NLAYERS * 512 * 128];

__device__ __forceinline__ float gelu_f(float x) {
    return 0.5f * x * (1.0f + erff(x * 0.70710678118654752440f));
}
__device__ __forceinline__ uint32_t sptr(const void* p) {
    uint32_t a;
    asm("{ .reg .u64 t; cvta.to.shared.u64 t, %1; cvt.u32.u64 %0, t; }" : "=r"(a) : "l"(p));
    return a;
}
__device__ __forceinline__ void ldsm_x4(uint32_t* r, uint32_t addr) {
    asm volatile("ldmatrix.sync.aligned.m8n8.x4.shared.b16 {%0,%1,%2,%3}, [%4];"
                 : "=r"(r[0]), "=r"(r[1]), "=r"(r[2]), "=r"(r[3]) : "r"(addr));
}
__device__ __forceinline__ void ldsm_x4t(uint32_t* r, uint32_t addr) {
    asm volatile("ldmatrix.sync.aligned.m8n8.x4.trans.shared.b16 {%0,%1,%2,%3}, [%4];"
                 : "=r"(r[0]), "=r"(r[1]), "=r"(r[2]), "=r"(r[3]) : "r"(addr));
}
__device__ __forceinline__ void mma16816(float* c, const uint32_t* a, const uint32_t* b) {
    asm volatile("mma.sync.aligned.m16n8k16.row.col.f32.bf16.bf16.f32 "
                 "{%0,%1,%2,%3}, {%4,%5,%6,%7}, {%8,%9}, {%0,%1,%2,%3};"
                 : "+f"(c[0]), "+f"(c[1]), "+f"(c[2]), "+f"(c[3])
                 : "r"(a[0]), "r"(a[1]), "r"(a[2]), "r"(a[3]), "r"(b[0]), "r"(b[1]));
}
__device__ __forceinline__ void split2(float v, unsigned short& h, unsigned short& l) {
    __nv_bfloat16 hb = __float2bfloat16(v);
    h = __bfloat16_as_ushort(hb);
    l = __bfloat16_as_ushort(__float2bfloat16(v - __bfloat162float(hb)));
}
__device__ __forceinline__ void cpasync16(uint32_t dst, const void* src) {
    asm volatile("cp.async.cg.shared.global [%0], [%1], 16;" :: "r"(dst), "l"(src));
}
__device__ __forceinline__ void cp_commit() {
    asm volatile("cp.async.commit_group;" ::: "memory");
}
template<int N>
__device__ __forceinline__ void cp_wait() {
    asm volatile("cp.async.wait_group %0;" :: "n"(N) : "memory");
}

// ---------------------------------------------------------------------------
// smem stage layout (ushort units)
// ---------------------------------------------------------------------------
#define A_STR 40
#define B_STR 136
#define ST_AH 0
#define ST_AL (128 * A_STR)
#define ST_BH (2 * 128 * A_STR)
#define ST_BL (2 * 128 * A_STR + 32 * B_STR)
#define STAGE_USH (2 * 128 * A_STR + 2 * 32 * B_STR)
#define SMEM_DYN (2 * STAGE_USH * 2)

// ---------------------------------------------------------------------------
// HMMA GEMM v3: 128x128 block, 256 threads = 8 warps (2m x 4n), warp tile 64x32.
// acc 64 regs/thread -> no spills, 2 CTAs/SM = 16 warps/SM (25% occ).
// cp.async double-buffered; split-bf16 3-pass.
// MODE 0: gelu(acc+bias[col]) -> split hi/lo out
// MODE 1: kconv: atomicAdd(Cf[arow*128+col], acc * aux[hrow*128+col])
// MODE 2: Cf = acc + bias[col] + aux (residual)
// ---------------------------------------------------------------------------
template<int MODE>
__global__ __launch_bounds__(256, 2)
void hmma_gemm(const unsigned short* __restrict__ Ah, const unsigned short* __restrict__ Al, int lda,
               const unsigned short* __restrict__ Bh, const unsigned short* __restrict__ Bl, int ldb,
               int Ktiles, int Ks16, int N,
               const float* __restrict__ bias, const float* __restrict__ aux,
               float* __restrict__ Cf, unsigned short* __restrict__ Ch, unsigned short* __restrict__ Cl,
               const int* __restrict__ send, const int* __restrict__ recv)
{
    extern __shared__ __align__(16) unsigned short smem[];
    __shared__ int hrow[128], arow[128];

    const int tid = threadIdx.x;
    const int l   = tid & 31;
    const int wid = tid >> 5;
    const int wm  = wid & 1;       // 64-row half
    const int wn  = wid >> 1;      // 32-col quarter (0..3)
    const int row0 = blockIdx.x * 128;
    const int nbase = blockIdx.y * 128;

    if (MODE == 1 && tid < 128) {
        int r = row0 + tid;
        int e = r / NGRID, o = r - e * NGRID;
        hrow[tid] = send[e] * NGRID + o;
        arow[tid] = recv[e] * NGRID + o;
    }

    float acc[4][4][4];
    #pragma unroll
    for (int i = 0; i < 4; i++)
        #pragma unroll
        for (int j = 0; j < 4; j++)
            #pragma unroll
            for (int q = 0; q < 4; q++) acc[i][j][q] = 0.0f;

    const int a_row = (l & 7) + (((l >> 3) & 1) << 3);
    const int a_col = (l >> 4) << 3;
    const int bg = l >> 3, br = l & 7;
    const int b_lane_off = ((bg & 1) * 8 + br) * B_STR + (bg >> 1) * 8;

    auto issue_tile = [&](int kt, int stage) {
        unsigned short* st = smem + stage * STAGE_USH;
        const int k0 = kt * 32;
        uint32_t sA = sptr(st);
        #pragma unroll
        for (int j = 0; j < 2; j++) {
            int i = tid + j * 256;
            int ar = i >> 2, ac = (i & 3) << 3;
            size_t gA = (size_t)(row0 + ar) * lda + k0 + ac;
            cpasync16(sA + (ST_AH + ar * A_STR + ac) * 2, Ah + gA);
            cpasync16(sA + (ST_AL + ar * A_STR + ac) * 2, Al + gA);
            int bk = i >> 4, bc = (i & 15) << 3;
            size_t gB = (size_t)(k0 + bk) * ldb + nbase + bc;
            cpasync16(sA + (ST_BH + bk * B_STR + bc) * 2, Bh + gB);
            cpasync16(sA + (ST_BL + bk * B_STR + bc) * 2, Bl + gB);
        }
        cp_commit();
    };

    issue_tile(0, 0);

    for (int kt = 0; kt < Ktiles; kt++) {
        const int stage = kt & 1;
        if (kt + 1 < Ktiles) {
            issue_tile(kt + 1, stage ^ 1);
            cp_wait<1>();
        } else {
            cp_wait<0>();
        }
        __syncthreads();

        unsigned short* st = smem + stage * STAGE_USH;
        unsigned short* sAh = st + ST_AH;
        unsigned short* sAl = st + ST_AL;
        unsigned short* sBh = st + ST_BH;
        unsigned short* sBl = st + ST_BL;

        const int ksmax = min(2, Ks16 - kt * 2);
        for (int ks = 0; ks < ksmax; ks++) {
            // B fragments for this warp's 32 cols: 2 groups of 16
            uint32_t bh[2][4], bl[2][4];
            #pragma unroll
            for (int g = 0; g < 2; g++) {
                uint32_t baddr = ks * 16 * B_STR + (wn * 32 + g * 16) + b_lane_off;
                ldsm_x4t(bh[g], sptr(sBh + baddr));
                ldsm_x4t(bl[g], sptr(sBl + baddr));
            }
            #pragma unroll
            for (int tm = 0; tm < 4; tm++) {
                uint32_t ah[4], al[4];
                int rr = wm * 64 + tm * 16 + a_row;
                int cc = ks * 16 + a_col;
                ldsm_x4(ah, sptr(sAh + rr * A_STR + cc));
                ldsm_x4(al, sptr(sAl + rr * A_STR + cc));
                // pass 0: ah*bh (4 independent)
                mma16816(acc[tm][0], ah, bh[0]);
                mma16816(acc[tm][1], ah, bh[0] + 2);
                mma16816(acc[tm][2], ah, bh[1]);
                mma16816(acc[tm][3], ah, bh[1] + 2);
                // pass 1: ah*bl
                mma16816(acc[tm][0], ah, bl[0]);
                mma16816(acc[tm][1], ah, bl[0] + 2);
                mma16816(acc[tm][2], ah, bl[1]);
                mma16816(acc[tm][3], ah, bl[1] + 2);
                // pass 2: al*bh
                mma16816(acc[tm][0], al, bh[0]);
                mma16816(acc[tm][1], al, bh[0] + 2);
                mma16816(acc[tm][2], al, bh[1]);
                mma16816(acc[tm][3], al, bh[1] + 2);
            }
        }
        __syncthreads();
    }

    // epilogue (warp cols: nbase + wn*32 .. +32)
    #pragma unroll
    for (int tm = 0; tm < 4; tm++) {
        int lr0 = wm * 64 + tm * 16 + (l >> 2);
        int lr1 = lr0 + 8;
        #pragma unroll
        for (int tn = 0; tn < 4; tn++) {
            int cc = nbase + wn * 32 + tn * 8 + (l & 3) * 2;
            float* a4 = acc[tm][tn];
            if (MODE == 0) {
                float v00 = gelu_f(a4[0] + bias[cc]);
                float v01 = gelu_f(a4[1] + bias[cc + 1]);
                float v10 = gelu_f(a4[2] + bias[cc]);
                float v11 = gelu_f(a4[3] + bias[cc + 1]);
                unsigned short h0, l0, h1, l1;
                size_t o0 = (size_t)(row0 + lr0) * N + cc;
                size_t o1 = (size_t)(row0 + lr1) * N + cc;
                split2(v00, h0, l0); split2(v01, h1, l1);
                *(uint32_t*)(Ch + o0) = (uint32_t)h0 | ((uint32_t)h1 << 16);
                *(uint32_t*)(Cl + o0) = (uint32_t)l0 | ((uint32_t)l1 << 16);
                split2(v10, h0, l0); split2(v11, h1, l1);
                *(uint32_t*)(Ch + o1) = (uint32_t)h0 | ((uint32_t)h1 << 16);
                *(uint32_t*)(Cl + o1) = (uint32_t)l0 | ((uint32_t)l1 << 16);
            } else if (MODE == 1) {
                int h0 = hrow[lr0] * 128 + cc, gg0 = arow[lr0] * 128 + cc;
                int h1 = hrow[lr1] * 128 + cc, gg1 = arow[lr1] * 128 + cc;
                float2 hv0 = *(const float2*)(aux + h0);
                float2 hv1 = *(const float2*)(aux + h1);
                atomicAdd(&Cf[gg0],     a4[0] * hv0.x);
                atomicAdd(&Cf[gg0 + 1], a4[1] * hv0.y);
                atomicAdd(&Cf[gg1],     a4[2] * hv1.x);
                atomicAdd(&Cf[gg1 + 1], a4[3] * hv1.y);
            } else {
                size_t o0 = (size_t)(row0 + lr0) * N + cc;
                size_t o1 = (size_t)(row0 + lr1) * N + cc;
                Cf[o0]     = a4[0] + bias[cc]     + aux[o0];
                Cf[o0 + 1] = a4[1] + bias[cc + 1] + aux[o0 + 1];
                Cf[o1]     = a4[2] + bias[cc]     + aux[o1];
                Cf[o1 + 1] = a4[3] + bias[cc + 1] + aux[o1 + 1];
            }
        }
    }
}

// ---------------------------------------------------------------------------
// embed (includes fibonacci grid0)
// ---------------------------------------------------------------------------
__global__ void embed_kernel(const float* __restrict__ x, const float* __restrict__ vec,
                             const float* __restrict__ Q, const int* __restrict__ batch,
                             const float* __restrict__ Wemb) {
    int v = blockIdx.x;
    int c = threadIdx.x;
    __shared__ float sQ[9], sx[IN_S], sv[6], sng[NGRID * 3], sg0[NGRID * 3];
    int b = batch[v];
    if (c < NGRID) {
        const float golden = 1.61803398874989484820f;
        float fi = (float)c;
        float theta = 6.28318530717958647692f * fi / golden;
        float z = 1.0f - (2.0f * fi + 1.0f) / (float)NGRID;
        float r = sqrtf(fmaxf(1.0f - z * z, 0.0f));
        float g0 = r * cosf(theta), g1 = r * sinf(theta);
        sg0[c*3+0] = g0; sg0[c*3+1] = g1; sg0[c*3+2] = z;
        if (v == 0) { g_grid0[c*3+0] = g0; g_grid0[c*3+1] = g1; g_grid0[c*3+2] = z; }
    }
    if (c < 9)  sQ[c] = Q[b * 9 + c];
    if (c < IN_S) sx[c] = x[v * IN_S + c];
    if (c < 6)  sv[c] = vec[v * 6 + c];
    __syncthreads();
    if (c < NGRID * 3) {
        int n = c / 3, i = c % 3;
        float t = sQ[i*3+0]*sg0[n*3+0] + sQ[i*3+1]*sg0[n*3+1] + sQ[i*3+2]*sg0[n*3+2];
        sng[c] = t;
        g_node_grid[v * NGRID * 3 + c] = t;
    }
    __syncthreads();
    float s = 0.0f;
    #pragma unroll
    for (int j = 0; j < IN_S; j++) s = fmaf(sx[j], Wemb[j * HID + c], s);
    float w16 = Wemb[IN_S * HID + c], w17 = Wemb[(IN_S + 1) * HID + c];
    #pragma unroll
    for (int n = 0; n < NGRID; n++) {
        float xv0 = sv[0]*sng[n*3+0] + sv[1]*sng[n*3+1] + sv[2]*sng[n*3+2];
        float xv1 = sv[3]*sng[n*3+0] + sv[4]*sng[n*3+1] + sv[5]*sng[n*3+2];
        g_h[(v * NGRID + n) * HID + c] = s + xv0 * w16 + xv1 * w17;
    }
}

// ---------------------------------------------------------------------------
// Combined poly + ALL weight-prep in one launch.
// ---------------------------------------------------------------------------
#define POLY_BLOCKS 3000
#define WPREP_ELEMS 462848
#define WPREP_BLOCKS 1808

__global__ void poly_wprep_kernel(const float* __restrict__ pos,
                                  const int* __restrict__ send, const int* __restrict__ recv,
                                  const float* __restrict__ Wsp1, const float* __restrict__ Wsp2,
                                  const float* __restrict__ Wk, const float* __restrict__ W1,
                                  const float* __restrict__ W2) {
    if (blockIdx.x < POLY_BLOCKS) {
        int r = blockIdx.x * 256 + threadIdx.x;
        int e = r / NGRID, o = r % NGRID;
        int s = send[e], rc = recv[e];
        float rx = pos[s*3+0]-pos[rc*3+0], ry = pos[s*3+1]-pos[rc*3+1], rz = pos[s*3+2]-pos[rc*3+2];
        const float* g = &g_node_grid[(rc * NGRID + o) * 3];
        float inv1 = rx*g[0] + ry*g[1] + rz*g[2];
        float dx = rx-inv1*g[0], dy = ry-inv1*g[1], dz = rz-inv1*g[2];
        float inv2 = sqrtf(dx*dx + dy*dy + dz*dz);
        float q[16];
        float a = inv1, b = inv2;
        q[0]=a; q[1]=b; q[2]=a*a; q[3]=a*b; q[4]=b*a; q[5]=b*b;
        q[6]=q[2]*a; q[7]=q[2]*b; q[8]=q[3]*a; q[9]=q[3]*b;
        q[10]=q[4]*a; q[11]=q[4]*b; q[12]=q[5]*a; q[13]=q[5]*b;
        q[14]=0.0f; q[15]=0.0f;
        size_t base = (size_t)r * 32;
        #pragma unroll
        for (int j = 0; j < 16; j += 2) {
            unsigned short h0, l0, h1, l1;
            split2(q[j], h0, l0); split2(q[j+1], h1, l1);
            *(uint32_t*)(g_poly_h + base + j) = (uint32_t)h0 | ((uint32_t)h1 << 16);
            *(uint32_t*)(g_poly_l + base + j) = (uint32_t)l0 | ((uint32_t)l1 << 16);
        }
        #pragma unroll
        for (int j = 16; j < 32; j += 2) {
            *(uint32_t*)(g_poly_h + base + j) = 0u;
            *(uint32_t*)(g_poly_l + base + j) = 0u;
        }
    } else {
        int i = (blockIdx.x - POLY_BLOCKS) * 256 + threadIdx.x;
        if (i >= WPREP_ELEMS) return;
        float v;
        unsigned short *hi, *lo;
        size_t idx;
        if (i < 4096) {
            int k = i >> 7;
            v = (k < 14) ? Wsp1[i] : 0.0f;
            hi = g_wsp1_h; lo = g_wsp1_l; idx = i;
        } else if (i < 20480) {
            int j = i - 4096;
            v = Wsp2[j];
            hi = g_wsp2_h; lo = g_wsp2_l; idx = j;
        } else {
            int j = i - 20480;
            int ll = j / 147456;
            int r2 = j - ll * 147456;
            if (r2 < 16384) {
                v = Wk[ll * 16384 + r2];
                hi = g_wk_h; lo = g_wk_l; idx = (size_t)ll * 16384 + r2;
            } else if (r2 < 81920) {
                int j2 = r2 - 16384;
                v = W1[ll * 65536 + j2];
                hi = g_w1_h; lo = g_w1_l; idx = (size_t)ll * 65536 + j2;
            } else {
                int j2 = r2 - 81920;
                v = W2[ll * 65536 + j2];
                hi = g_w2_h; lo = g_w2_l; idx = (size_t)ll * 65536 + j2;
            }
        }
        unsigned short h, l;
        split2(v, h, l);
        hi[idx] = h; lo[idx] = l;
    }
}

__global__ void kbsh_kernel(const float* __restrict__ Wsh1, const float* __restrict__ bsh1,
                            const float* __restrict__ Wsh2, const float* __restrict__ bsh2) {
    int row = blockIdx.x;
    int p = row / NGRID, o = row % NGRID;
    int c = threadIdx.x;
    __shared__ float h1[HID];
    float t = g_grid0[p*3+0]*g_grid0[o*3+0] + g_grid0[p*3+1]*g_grid0[o*3+1] + g_grid0[p*3+2]*g_grid0[o*3+2];
    float v = t*Wsh1[c] + t*t*Wsh1[HID+c] + t*t*t*Wsh1[2*HID+c] + bsh1[c];
    h1[c] = gelu_f(v);
    __syncthreads();
    float acc = bsh2[c];
    #pragma unroll 8
    for (int k = 0; k < HID; k++) acc = fmaf(h1[k], Wsh2[k*HID + c], acc);
    g_kb_sh[row * HID + c] = gelu_f(acc);
}

__global__ void fk_kernel(const float* __restrict__ Wfk) {
    int blk = blockIdx.x;
    int ll = blk / 144, row = blk % 144;
    int c = threadIdx.x;
    __shared__ float r128[HID];
    r128[c] = g_kb_sh[row * HID + c];
    __syncthreads();
    const float* W = Wfk + ll * HID * HID;
    float acc = 0.0f;
    #pragma unroll 8
    for (int k = 0; k < HID; k++) acc = fmaf(r128[k], W[k*HID + c], acc);
    g_fk[ll * 144 * HID + row * HID + c] = acc;
}

// conv_ln v2: 384 threads = 12 warps (one per p), one barrier
__global__ __launch_bounds__(384)
void conv_ln_kernel(const float* __restrict__ agg, const float* __restrict__ fk,
                    const float* __restrict__ bconv, const float* __restrict__ lng,
                    const float* __restrict__ lnb) {
    int v = blockIdx.x;
    int tid = threadIdx.x, lane = tid & 31, wp = tid >> 5;
    __shared__ float sagg[NGRID][HID];
    for (int i = tid; i < NGRID * HID; i += 384)
        sagg[i >> 7][i & 127] = agg[(size_t)v * NGRID * HID + i];
    __syncthreads();

    int c0 = lane * 4;
    float4 s = {0.0f, 0.0f, 0.0f, 0.0f};
    #pragma unroll
    for (int o = 0; o < NGRID; o++) {
        float4 a = *(const float4*)&sagg[o][c0];
        float4 f = *(const float4*)&fk[(size_t)(wp * NGRID + o) * HID + c0];
        s.x = fmaf(a.x, f.x, s.x);
        s.y = fmaf(a.y, f.y, s.y);
        s.z = fmaf(a.z, f.z, s.z);
        s.w = fmaf(a.w, f.w, s.w);
    }
    float4 bc = *(const float4*)&bconv[c0];
    float4 x;
    x.x = s.x * (1.0f / NGRID) + bc.x;
    x.y = s.y * (1.0f / NGRID) + bc.y;
    x.z = s.z * (1.0f / NGRID) + bc.z;
    x.w = s.w * (1.0f / NGRID) + bc.w;

    float t = x.x + x.y + x.z + x.w;
    #pragma unroll
    for (int off = 16; off > 0; off >>= 1) t += __shfl_xor_sync(0xffffffffu, t, off);
    float mu = t * (1.0f / HID);
    float4 d = {x.x - mu, x.y - mu, x.z - mu, x.w - mu};
    float t2 = d.x*d.x + d.y*d.y + d.z*d.z + d.w*d.w;
    #pragma unroll
    for (int off = 16; off > 0; off >>= 1) t2 += __shfl_xor_sync(0xffffffffu, t2, off);
    float rstd = rsqrtf(t2 * (1.0f / HID) + 1e-5f);

    float4 g = *(const float4*)&lng[c0];
    float4 bb = *(const float4*)&lnb[c0];
    float v0 = d.x * rstd * g.x + bb.x;
    float v1 = d.y * rstd * g.y + bb.y;
    float v2 = d.z * rstd * g.z + bb.z;
    float v3 = d.w * rstd * g.w + bb.w;

    unsigned short h0,l0,h1,l1,h2,l2,h3,l3;
    split2(v0,h0,l0); split2(v1,h1,l1); split2(v2,h2,l2); split2(v3,h3,l3);
    size_t idx = (size_t)(v * NGRID + wp) * HID + c0;
    uint2 ph = { (uint32_t)h0 | ((uint32_t)h1 << 16), (uint32_t)h2 | ((uint32_t)h3 << 16) };
    uint2 pl = { (uint32_t)l0 | ((uint32_t)l1 << 16), (uint32_t)l2 | ((uint32_t)l3 << 16) };
    *(uint2*)(g_hn_h + idx) = ph;
    *(uint2*)(g_hn_l + idx) = pl;
}

__global__ void readout_kernel(const float* __restrict__ h, const float* __restrict__ Wro,
                               const float* __restrict__ bro) {
    __shared__ float hs[16 * 129];
    int tid = threadIdx.x;
    int r0 = blockIdx.x * 16;
    for (int i = tid; i < 16 * 128; i += 160) {
        int row = i >> 7, cc = i & 127;
        hs[row * 129 + cc] = h[(size_t)(r0 + row) * HID + cc];
    }
    __syncthreads();
    if (tid < 16 * 9) {
        int row = tid / 9, oc = tid % 9;
        float acc = bro[oc];
        #pragma unroll 8
        for (int cc = 0; cc < 128; cc++) acc = fmaf(hs[row * 129 + cc], Wro[cc * 9 + oc], acc);
        g_readout[(r0 + row) * 9 + oc] += acc * (1.0f / NLAYERS);
    }
}

__global__ void finalize_kernel(const int* __restrict__ batch, float* __restrict__ out) {
    int v = blockIdx.x * 256 + threadIdx.x;
    if (v >= N_NODES) return;
    float ssum[OUT_S] = {0,0,0,0,0,0,0,0};
    float vsum[3] = {0,0,0};
    for (int n = 0; n < NGRID; n++) {
        const float* rr = &g_readout[(v * NGRID + n) * 9];
        #pragma unroll
        for (int j = 0; j < OUT_S; j++) ssum[j] += rr[j];
        float rv = rr[OUT_S];
        const float* g = &g_node_grid[(v * NGRID + n) * 3];
        vsum[0] += rv * g[0]; vsum[1] += rv * g[1]; vsum[2] += rv * g[2];
    }
    int b = batch[v];
    #pragma unroll
    for (int j = 0; j < OUT_S; j++) atomicAdd(&out[b * OUT_S + j], ssum[j] * (1.0f / NGRID));
    #pragma unroll
    for (int d = 0; d < 3; d++) atomicAdd(&out[NBATCH * OUT_S + b * 3 + d], vsum[d] * (1.0f / NGRID));
}

__global__ void zero_kernel(float* __restrict__ p, int n) {
    for (int i = blockIdx.x * blockDim.x + threadIdx.x; i < n; i += gridDim.x * blockDim.x)
        p[i] = 0.0f;
}
__global__ void zero_sym_kernel(int which) {
    int stride = gridDim.x * blockDim.x;
    if (which == 0) {
        for (int i = blockIdx.x*blockDim.x+threadIdx.x; i < R_N*HID; i += stride) g_agg[i] = 0.0f;
    } else {
        for (int i = blockIdx.x*blockDim.x+threadIdx.x; i < R_N*9; i += stride) g_readout[i] = 0.0f;
    }
}

// ---------------------------------------------------------------------------
// Host launcher — launch #4 (= ncu-profiled) is the representative K=128 GEMM
// ---------------------------------------------------------------------------
extern "C" void kernel_launch(void* const* d_in, const int* in_sizes, int n_in,
                              void* d_out, int out_size) {
    const float* x    = (const float*)d_in[0];
    const float* vec  = (const float*)d_in[1];
    const float* pos  = (const float*)d_in[2];
    const float* Q    = (const float*)d_in[3];
    const float* Wsp1 = (const float*)d_in[4];
    const float* bsp1 = (const float*)d_in[5];
    const float* Wsp2 = (const float*)d_in[6];
    const float* bsp2 = (const float*)d_in[7];
    const float* Wsh1 = (const float*)d_in[8];
    const float* bsh1 = (const float*)d_in[9];
    const float* Wsh2 = (const float*)d_in[10];
    const float* bsh2 = (const float*)d_in[11];
    const float* Wemb = (const float*)d_in[12];
    const float* Wk   = (const float*)d_in[13];
    const float* Wfk  = (const float*)d_in[14];
    const float* bconv= (const float*)d_in[15];
    const float* ln_g = (const float*)d_in[16];
    const float* ln_b = (const float*)d_in[17];
    const float* W1   = (const float*)d_in[18];
    const float* b1   = (const float*)d_in[19];
    const float* W2   = (const float*)d_in[20];
    const float* b2   = (const float*)d_in[21];
    const float* Wro  = (const float*)d_in[22];
    const float* bro  = (const float*)d_in[23];
    const int*   eidx = (const int*)d_in[24];
    const int*   batch= (const int*)d_in[25];
    float* out = (float*)d_out;
    const int* send = eidx;
    const int* recv = eidx + N_EDGES;

    float *p_h, *p_agg, *p_fk;
    unsigned short *p_ph,*p_pl,*p_b1h,*p_b1l,*p_kbh,*p_kbl,*p_hnh,*p_hnl;
    unsigned short *p_wsp1h,*p_wsp1l,*p_wsp2h,*p_wsp2l,*p_wkh,*p_wkl,*p_w1h,*p_w1l,*p_w2h,*p_w2l;
    cudaGetSymbolAddress((void**)&p_h,   g_h);
    cudaGetSymbolAddress((void**)&p_agg, g_agg);
    cudaGetSymbolAddress((void**)&p_fk,  g_fk);
    cudaGetSymbolAddress((void**)&p_ph,  g_poly_h);  cudaGetSymbolAddress((void**)&p_pl,  g_poly_l);
    cudaGetSymbolAddress((void**)&p_b1h, g_buf1_h);  cudaGetSymbolAddress((void**)&p_b1l, g_buf1_l);
    cudaGetSymbolAddress((void**)&p_kbh, g_kbsp_h);  cudaGetSymbolAddress((void**)&p_kbl, g_kbsp_l);
    cudaGetSymbolAddress((void**)&p_hnh, g_hn_h);    cudaGetSymbolAddress((void**)&p_hnl, g_hn_l);
    cudaGetSymbolAddress((void**)&p_wsp1h, g_wsp1_h); cudaGetSymbolAddress((void**)&p_wsp1l, g_wsp1_l);
    cudaGetSymbolAddress((void**)&p_wsp2h, g_wsp2_h); cudaGetSymbolAddress((void**)&p_wsp2l, g_wsp2_l);
    cudaGetSymbolAddress((void**)&p_wkh, g_wk_h);    cudaGetSymbolAddress((void**)&p_wkl, g_wk_l);
    cudaGetSymbolAddress((void**)&p_w1h, g_w1_h);    cudaGetSymbolAddress((void**)&p_w1l, g_w1_l);
    cudaGetSymbolAddress((void**)&p_w2h, g_w2_h);    cudaGetSymbolAddress((void**)&p_w2l, g_w2_l);

    cudaFuncSetAttribute(hmma_gemm<0>, cudaFuncAttributeMaxDynamicSharedMemorySize, SMEM_DYN);
    cudaFuncSetAttribute(hmma_gemm<1>, cudaFuncAttributeMaxDynamicSharedMemorySize, SMEM_DYN);
    cudaFuncSetAttribute(hmma_gemm<2>, cudaFuncAttributeMaxDynamicSharedMemorySize, SMEM_DYN);

    // 1: embed
    embed_kernel<<<N_NODES, 128>>>(x, vec, Q, batch, Wemb);
    // 2: poly + weight prep
    poly_wprep_kernel<<<POLY_BLOCKS + WPREP_BLOCKS, 256>>>(pos, send, recv, Wsp1, Wsp2, Wk, W1, W2);
    // 3: kb_sp GEMM1
    hmma_gemm<0><<<dim3(R_E / 128, 1), 256, SMEM_DYN>>>(p_ph, p_pl, 32, p_wsp1h, p_wsp1l, 128,
                                                        1, 1, 128, bsp1, nullptr, nullptr, p_b1h, p_b1l,
                                                        nullptr, nullptr);
    // 4: kb_sp GEMM2 (K=128) — ncu-profiled launch
    hmma_gemm<0><<<dim3(R_E / 128, 1), 256, SMEM_DYN>>>(p_b1h, p_b1l, 128, p_wsp2h, p_wsp2l, 128,
                                                        4, 8, 128, bsp2, nullptr, nullptr, p_kbh, p_kbl,
                                                        nullptr, nullptr);
    // remaining setup
    kbsh_kernel<<<144, 128>>>(Wsh1, bsh1, Wsh2, bsh2);
    fk_kernel<<<NLAYERS * 144, 128>>>(Wfk);
    zero_sym_kernel<<<1024, 256>>>(1);

    for (int l = 0; l < NLAYERS; l++) {
        zero_sym_kernel<<<4096, 256>>>(0);
        hmma_gemm<1><<<dim3(R_E / 128, 1), 256, SMEM_DYN>>>(p_kbh, p_kbl, 128,
                                                  p_wkh + l*128*128, p_wkl + l*128*128, 128,
                                                  4, 8, 128, nullptr, p_h, p_agg, nullptr, nullptr,
                                                  send, recv);
        conv_ln_kernel<<<N_NODES, 384>>>(p_agg, p_fk + l * 144 * HID,
                                         bconv + l * HID, ln_g + l * HID, ln_b + l * HID);
        hmma_gemm<0><<<dim3(R_N / 128, 4), 256, SMEM_DYN>>>(p_hnh, p_hnl, 128,
                                                  p_w1h + l*128*512, p_w1l + l*128*512, 512,
                                                  4, 8, 512, b1 + l*512, nullptr, nullptr, p_b1h, p_b1l,
                                                  nullptr, nullptr);
        hmma_gemm<2><<<dim3(R_N / 128, 1), 256, SMEM_DYN>>>(p_b1h, p_b1l, 512,
                                                  p_w2h + l*512*128, p_w2l + l*512*128, 128,
                                                  16, 32, 128, b2 + l*128, p_h, p_h, nullptr, nullptr,
                                                  nullptr, nullptr);
        readout_kernel<<<R_N / 16, 160>>>(p_h, Wro + l * HID * 9, bro + l * 9);
    }

    int out_elems = NBATCH * OUT_S + NBATCH * 3;
    zero_kernel<<<(out_elems + 255) / 256, 256>>>(out, out_elems);
    finalize_kernel<<<(N_NODES + 255) / 256, 256>>>(batch, out);
}

// round 17
// speedup vs baseline: 2.7670x; 1.0479x over previous
#include <cuda_runtime.h>
#include <cuda_bf16.h>
#include <math.h>
#include <stdint.h>

#define N_NODES 8000
#define N_EDGES 64000
#define NBATCH  64
#define NGRID   12
#define HID     128
#define NLAYERS 3
#define IN_S    16
#define OUT_S   8
#define WIDE    4
#define R_E (N_EDGES * NGRID)   // 768000
#define R_N (N_NODES * NGRID)   // 96000

// ---------------------------------------------------------------------------
// Device scratch
// ---------------------------------------------------------------------------
__device__ float g_grid0[NGRID * 3];
__device__ float g_node_grid[R_N * 3];
__device__ float g_kb_sh[144 * HID];
__device__ float g_fk[NLAYERS * 144 * HID];
__device__ float g_h[R_N * HID];
__device__ float g_agg[R_N * HID];
__device__ float g_readout[R_N * (OUT_S + 1)];

// bf16 hi/lo split operand storage
__device__ unsigned short g_poly_h[R_E * 32],  g_poly_l[R_E * 32];
__device__ unsigned short g_buf1_h[R_E * 128], g_buf1_l[R_E * 128];   // MLP hidden
__device__ unsigned short g_kbsp_h[R_E * 128], g_kbsp_l[R_E * 128];
__device__ unsigned short g_hn_h[R_N * 128],   g_hn_l[R_N * 128];
__device__ unsigned short g_wsp1_h[32 * 128],  g_wsp1_l[32 * 128];
__device__ unsigned short g_wsp2_h[128 * 128], g_wsp2_l[128 * 128];
__device__ unsigned short g_wk_h[NLAYERS * 128 * 128], g_wk_l[NLAYERS * 128 * 128];
__device__ unsigned short g_w1_h[NLAYERS * 128 * 512], g_w1_l[NLAYERS * 128 * 512];
__device__ unsigned short g_w2_h[NLAYERS * 512 * 128], g_w2_l[NLAYERS * 512 * 128];

// fast gelu: Abramowitz-Stegun 7.1.26 erf (max abs err 1.5e-7)
__device__ __forceinline__ float gelu_f(float x) {
    float u = fabsf(x) * 0.70710678118654752440f;
    float t = __fdividef(1.0f, fmaf(0.3275911f, u, 1.0f));
    float p = t * fmaf(t, fmaf(t, fmaf(t, fmaf(t, 1.061405429f, -1.453152027f),
                                       1.421413741f), -0.284496736f), 0.254829592f);
    float e = 1.0f - p * __expf(-u * u);
    e = copysignf(e, x);
    return 0.5f * x * (1.0f + e);
}
__device__ __forceinline__ uint32_t sptr(const void* p) {
    uint32_t a;
    asm("{ .reg .u64 t; cvta.to.shared.u64 t, %1; cvt.u32.u64 %0, t; }" : "=r"(a) : "l"(p));
    return a;
}
__device__ __forceinline__ void ldsm_x4(uint32_t* r, uint32_t addr) {
    asm volatile("ldmatrix.sync.aligned.m8n8.x4.shared.b16 {%0,%1,%2,%3}, [%4];"
                 : "=r"(r[0]), "=r"(r[1]), "=r"(r[2]), "=r"(r[3]) : "r"(addr));
}
__device__ __forceinline__ void ldsm_x4t(uint32_t* r, uint32_t addr) {
    asm volatile("ldmatrix.sync.aligned.m8n8.x4.trans.shared.b16 {%0,%1,%2,%3}, [%4];"
                 : "=r"(r[0]), "=r"(r[1]), "=r"(r[2]), "=r"(r[3]) : "r"(addr));
}
__device__ __forceinline__ void mma16816(float* c, const uint32_t* a, const uint32_t* b) {
    asm volatile("mma.sync.aligned.m16n8k16.row.col.f32.bf16.bf16.f32 "
                 "{%0,%1,%2,%3}, {%4,%5,%6,%7}, {%8,%9}, {%0,%1,%2,%3};"
                 : "+f"(c[0]), "+f"(c[1]), "+f"(c[2]), "+f"(c[3])
                 : "r"(a[0]), "r"(a[1]), "r"(a[2]), "r"(a[3]), "r"(b[0]), "r"(b[1]));
}
__device__ __forceinline__ void split2(float v, unsigned short& h, unsigned short& l) {
    __nv_bfloat16 hb = __float2bfloat16(v);
    h = __bfloat16_as_ushort(hb);
    l = __bfloat16_as_ushort(__float2bfloat16(v - __bfloat162float(hb)));
}
__device__ __forceinline__ void cpasync16(uint32_t dst, const void* src) {
    asm volatile("cp.async.cg.shared.global [%0], [%1], 16;" :: "r"(dst), "l"(src));
}
__device__ __forceinline__ void cp_commit() {
    asm volatile("cp.async.commit_group;" ::: "memory");
}
template<int N>
__device__ __forceinline__ void cp_wait() {
    asm volatile("cp.async.wait_group %0;" :: "n"(N) : "memory");
}

// ---------------------------------------------------------------------------
// smem stage layout (ushort units) for generic hmma_gemm
// ---------------------------------------------------------------------------
#define A_STR 40
#define B_STR 136
#define ST_AH 0
#define ST_AL (128 * A_STR)
#define ST_BH (2 * 128 * A_STR)
#define ST_BL (2 * 128 * A_STR + 32 * B_STR)
#define STAGE_USH (2 * 128 * A_STR + 2 * 32 * B_STR)
#define SMEM_DYN (2 * STAGE_USH * 2)

// ---------------------------------------------------------------------------
// HMMA GEMM v3 (unchanged structure from R15): 256 thr, 8 warps (2m x 4n), 64x32 tiles
// ---------------------------------------------------------------------------
template<int MODE>
__global__ __launch_bounds__(256, 2)
void hmma_gemm(const unsigned short* __restrict__ Ah, const unsigned short* __restrict__ Al, int lda,
               const unsigned short* __restrict__ Bh, const unsigned short* __restrict__ Bl, int ldb,
               int Ktiles, int Ks16, int N,
               const float* __restrict__ bias, const float* __restrict__ aux,
               float* __restrict__ Cf, unsigned short* __restrict__ Ch, unsigned short* __restrict__ Cl,
               const int* __restrict__ send, const int* __restrict__ recv)
{
    extern __shared__ __align__(16) unsigned short smem[];
    __shared__ int hrow[128], arow[128];

    const int tid = threadIdx.x;
    const int l   = tid & 31;
    const int wid = tid >> 5;
    const int wm  = wid & 1;
    const int wn  = wid >> 1;
    const int row0 = blockIdx.x * 128;
    const int nbase = blockIdx.y * 128;

    if (MODE == 1 && tid < 128) {
        int r = row0 + tid;
        int e = r / NGRID, o = r - e * NGRID;
        hrow[tid] = send[e] * NGRID + o;
        arow[tid] = recv[e] * NGRID + o;
    }

    float acc[4][4][4];
    #pragma unroll
    for (int i = 0; i < 4; i++)
        #pragma unroll
        for (int j = 0; j < 4; j++)
            #pragma unroll
            for (int q = 0; q < 4; q++) acc[i][j][q] = 0.0f;

    const int a_row = (l & 7) + (((l >> 3) & 1) << 3);
    const int a_col = (l >> 4) << 3;
    const int bg = l >> 3, br = l & 7;
    const int b_lane_off = ((bg & 1) * 8 + br) * B_STR + (bg >> 1) * 8;

    auto issue_tile = [&](int kt, int stage) {
        unsigned short* st = smem + stage * STAGE_USH;
        const int k0 = kt * 32;
        uint32_t sA = sptr(st);
        #pragma unroll
        for (int j = 0; j < 2; j++) {
            int i = tid + j * 256;
            int ar = i >> 2, ac = (i & 3) << 3;
            size_t gA = (size_t)(row0 + ar) * lda + k0 + ac;
            cpasync16(sA + (ST_AH + ar * A_STR + ac) * 2, Ah + gA);
            cpasync16(sA + (ST_AL + ar * A_STR + ac) * 2, Al + gA);
            int bk = i >> 4, bc = (i & 15) << 3;
            size_t gB = (size_t)(k0 + bk) * ldb + nbase + bc;
            cpasync16(sA + (ST_BH + bk * B_STR + bc) * 2, Bh + gB);
            cpasync16(sA + (ST_BL + bk * B_STR + bc) * 2, Bl + gB);
        }
        cp_commit();
    };

    issue_tile(0, 0);

    for (int kt = 0; kt < Ktiles; kt++) {
        const int stage = kt & 1;
        if (kt + 1 < Ktiles) {
            issue_tile(kt + 1, stage ^ 1);
            cp_wait<1>();
        } else {
            cp_wait<0>();
        }
        __syncthreads();

        unsigned short* st = smem + stage * STAGE_USH;
        unsigned short* sAh = st + ST_AH;
        unsigned short* sAl = st + ST_AL;
        unsigned short* sBh = st + ST_BH;
        unsigned short* sBl = st + ST_BL;

        const int ksmax = min(2, Ks16 - kt * 2);
        for (int ks = 0; ks < ksmax; ks++) {
            uint32_t bh[2][4], bl[2][4];
            #pragma unroll
            for (int g = 0; g < 2; g++) {
                uint32_t baddr = ks * 16 * B_STR + (wn * 32 + g * 16) + b_lane_off;
                ldsm_x4t(bh[g], sptr(sBh + baddr));
                ldsm_x4t(bl[g], sptr(sBl + baddr));
            }
            #pragma unroll
            for (int tm = 0; tm < 4; tm++) {
                uint32_t ah[4], al[4];
                int rr = wm * 64 + tm * 16 + a_row;
                int cc = ks * 16 + a_col;
                ldsm_x4(ah, sptr(sAh + rr * A_STR + cc));
                ldsm_x4(al, sptr(sAl + rr * A_STR + cc));
                mma16816(acc[tm][0], ah, bh[0]);
                mma16816(acc[tm][1], ah, bh[0] + 2);
                mma16816(acc[tm][2], ah, bh[1]);
                mma16816(acc[tm][3], ah, bh[1] + 2);
                mma16816(acc[tm][0], ah, bl[0]);
                mma16816(acc[tm][1], ah, bl[0] + 2);
                mma16816(acc[tm][2], ah, bl[1]);
                mma16816(acc[tm][3], ah, bl[1] + 2);
                mma16816(acc[tm][0], al, bh[0]);
                mma16816(acc[tm][1], al, bh[0] + 2);
                mma16816(acc[tm][2], al, bh[1]);
                mma16816(acc[tm][3], al, bh[1] + 2);
            }
        }
        __syncthreads();
    }

    #pragma unroll
    for (int tm = 0; tm < 4; tm++) {
        int lr0 = wm * 64 + tm * 16 + (l >> 2);
        int lr1 = lr0 + 8;
        #pragma unroll
        for (int tn = 0; tn < 4; tn++) {
            int cc = nbase + wn * 32 + tn * 8 + (l & 3) * 2;
            float* a4 = acc[tm][tn];
            if (MODE == 0) {
                float v00 = gelu_f(a4[0] + bias[cc]);
                float v01 = gelu_f(a4[1] + bias[cc + 1]);
                float v10 = gelu_f(a4[2] + bias[cc]);
                float v11 = gelu_f(a4[3] + bias[cc + 1]);
                unsigned short h0, l0, h1, l1;
                size_t o0 = (size_t)(row0 + lr0) * N + cc;
                size_t o1 = (size_t)(row0 + lr1) * N + cc;
                split2(v00, h0, l0); split2(v01, h1, l1);
                *(uint32_t*)(Ch + o0) = (uint32_t)h0 | ((uint32_t)h1 << 16);
                *(uint32_t*)(Cl + o0) = (uint32_t)l0 | ((uint32_t)l1 << 16);
                split2(v10, h0, l0); split2(v11, h1, l1);
                *(uint32_t*)(Ch + o1) = (uint32_t)h0 | ((uint32_t)h1 << 16);
                *(uint32_t*)(Cl + o1) = (uint32_t)l0 | ((uint32_t)l1 << 16);
            } else if (MODE == 1) {
                int h0 = hrow[lr0] * 128 + cc, gg0 = arow[lr0] * 128 + cc;
                int h1 = hrow[lr1] * 128 + cc, gg1 = arow[lr1] * 128 + cc;
                float2 hv0 = *(const float2*)(aux + h0);
                float2 hv1 = *(const float2*)(aux + h1);
                atomicAdd(&Cf[gg0],     a4[0] * hv0.x);
                atomicAdd(&Cf[gg0 + 1], a4[1] * hv0.y);
                atomicAdd(&Cf[gg1],     a4[2] * hv1.x);
                atomicAdd(&Cf[gg1 + 1], a4[3] * hv1.y);
            } else {
                size_t o0 = (size_t)(row0 + lr0) * N + cc;
                size_t o1 = (size_t)(row0 + lr1) * N + cc;
                Cf[o0]     = a4[0] + bias[cc]     + aux[o0];
                Cf[o0 + 1] = a4[1] + bias[cc + 1] + aux[o0 + 1];
                Cf[o1]     = a4[2] + bias[cc]     + aux[o1];
                Cf[o1 + 1] = a4[3] + bias[cc + 1] + aux[o1 + 1];
            }
        }
    }
}

// ---------------------------------------------------------------------------
// FUSED kb_sp kernel: C1 = gelu(poly@Wsp1+b1) kept split-bf16 in smem;
// kb_sp = gelu(C1@Wsp2+b2) -> global split. One block = 128 rows.
// smem: C1h[128*136], C1l[128*136], then 2 B stages of (Bh+Bl)[32*136] each.
// Phase-1 A tile (poly, 128x32, A_STR=40) aliases into the C1 region.
// ---------------------------------------------------------------------------
#define FB_STR 136
#define C1_USH (128 * FB_STR)          // 17408 ushorts per array
#define FB_OFF (2 * C1_USH)            // B stages start (ushorts)
#define FB_STAGE (2 * 32 * FB_STR)     // Bh+Bl per stage = 8704 ushorts
#define FUSED_SMEM ((2 * C1_USH + 2 * FB_STAGE) * 2)   // 104448 bytes

__global__ __launch_bounds__(256, 2)
void kbsp_fused(const unsigned short* __restrict__ ph, const unsigned short* __restrict__ pl,
                const unsigned short* __restrict__ w1h, const unsigned short* __restrict__ w1l,
                const unsigned short* __restrict__ w2h, const unsigned short* __restrict__ w2l,
                const float* __restrict__ b1, const float* __restrict__ b2,
                unsigned short* __restrict__ Ch, unsigned short* __restrict__ Cl)
{
    extern __shared__ __align__(16) unsigned short smem[];
    unsigned short* sC1h = smem;
    unsigned short* sC1l = smem + C1_USH;
    const int tid = threadIdx.x;
    const int l   = tid & 31;
    const int wid = tid >> 5;
    const int wm  = wid & 1;
    const int wn  = wid >> 1;
    const int row0 = blockIdx.x * 128;

    const int a_row = (l & 7) + (((l >> 3) & 1) << 3);
    const int a_col = (l >> 4) << 3;
    const int bg = l >> 3, br = l & 7;
    const int b_lane_off = ((bg & 1) * 8 + br) * FB_STR + (bg >> 1) * 8;

    float acc[4][4][4];
    #pragma unroll
    for (int i = 0; i < 4; i++)
        #pragma unroll
        for (int j = 0; j < 4; j++)
            #pragma unroll
            for (int q = 0; q < 4; q++) acc[i][j][q] = 0.0f;

    // ---- phase 1 fill: A(poly 128x32, lda=32) into C1 region (Ah@0 str40, Al@5120); B(Wsp1) into stage0
    {
        uint32_t sA = sptr(smem);
        uint32_t sB = sptr(smem + FB_OFF);
        #pragma unroll
        for (int j = 0; j < 2; j++) {
            int i = tid + j * 256;
            int ar = i >> 2, ac = (i & 3) << 3;
            size_t gA = (size_t)(row0 + ar) * 32 + ac;
            cpasync16(sA + (ar * A_STR + ac) * 2, ph + gA);
            cpasync16(sA + (128 * A_STR + ar * A_STR + ac) * 2, pl + gA);
            int bk = i >> 4, bc = (i & 15) << 3;
            size_t gB = (size_t)bk * 128 + bc;
            cpasync16(sB + (bk * FB_STR + bc) * 2, w1h + gB);
            cpasync16(sB + (32 * FB_STR + bk * FB_STR + bc) * 2, w1l + gB);
        }
        cp_commit();
        cp_wait<0>();
    }
    __syncthreads();

    // ---- phase 1 mainloop: single k16 step (poly cols 0..15; 14..15 are zero)
    {
        unsigned short* sAh = smem;
        unsigned short* sAl = smem + 128 * A_STR;
        unsigned short* sBh = smem + FB_OFF;
        unsigned short* sBl = sBh + 32 * FB_STR;
        uint32_t bh[2][4], bl[2][4];
        #pragma unroll
        for (int g = 0; g < 2; g++) {
            uint32_t baddr = (wn * 32 + g * 16) + b_lane_off;
            ldsm_x4t(bh[g], sptr(sBh + baddr));
            ldsm_x4t(bl[g], sptr(sBl + baddr));
        }
        #pragma unroll
        for (int tm = 0; tm < 4; tm++) {
            uint32_t ah[4], al[4];
            int rr = wm * 64 + tm * 16 + a_row;
            ldsm_x4(ah, sptr(sAh + rr * A_STR + a_col));
            ldsm_x4(al, sptr(sAl + rr * A_STR + a_col));
            mma16816(acc[tm][0], ah, bh[0]);
            mma16816(acc[tm][1], ah, bh[0] + 2);
            mma16816(acc[tm][2], ah, bh[1]);
            mma16816(acc[tm][3], ah, bh[1] + 2);
            mma16816(acc[tm][0], ah, bl[0]);
            mma16816(acc[tm][1], ah, bl[0] + 2);
            mma16816(acc[tm][2], ah, bl[1]);
            mma16816(acc[tm][3], ah, bl[1] + 2);
            mma16816(acc[tm][0], al, bh[0]);
            mma16816(acc[tm][1], al, bh[0] + 2);
            mma16816(acc[tm][2], al, bh[1]);
            mma16816(acc[tm][3], al, bh[1] + 2);
        }
    }
    __syncthreads();   // all reads of phase-1 tiles done

    // prefetch phase-2 B tile kt=0 (stage 0) while doing phase-1 epilogue
    auto fill_B2 = [&](int kt, int stage) {
        uint32_t sB = sptr(smem + FB_OFF + stage * FB_STAGE);
        #pragma unroll
        for (int j = 0; j < 2; j++) {
            int i = tid + j * 256;
            int bk = i >> 4, bc = (i & 15) << 3;
            size_t gB = (size_t)(kt * 32 + bk) * 128 + bc;
            cpasync16(sB + (bk * FB_STR + bc) * 2, w2h + gB);
            cpasync16(sB + (32 * FB_STR + bk * FB_STR + bc) * 2, w2l + gB);
        }
        cp_commit();
    };
    fill_B2(0, 0);

    // ---- phase 1 epilogue: gelu + split into smem C1 (stride FB_STR)
    #pragma unroll
    for (int tm = 0; tm < 4; tm++) {
        int lr0 = wm * 64 + tm * 16 + (l >> 2);
        int lr1 = lr0 + 8;
        #pragma unroll
        for (int tn = 0; tn < 4; tn++) {
            int cc = wn * 32 + tn * 8 + (l & 3) * 2;
            float* a4 = acc[tm][tn];
            float v00 = gelu_f(a4[0] + b1[cc]);
            float v01 = gelu_f(a4[1] + b1[cc + 1]);
            float v10 = gelu_f(a4[2] + b1[cc]);
            float v11 = gelu_f(a4[3] + b1[cc + 1]);
            unsigned short h0, l0, h1, l1;
            split2(v00, h0, l0); split2(v01, h1, l1);
            *(uint32_t*)(sC1h + lr0 * FB_STR + cc) = (uint32_t)h0 | ((uint32_t)h1 << 16);
            *(uint32_t*)(sC1l + lr0 * FB_STR + cc) = (uint32_t)l0 | ((uint32_t)l1 << 16);
            split2(v10, h0, l0); split2(v11, h1, l1);
            *(uint32_t*)(sC1h + lr1 * FB_STR + cc) = (uint32_t)h0 | ((uint32_t)h1 << 16);
            *(uint32_t*)(sC1l + lr1 * FB_STR + cc) = (uint32_t)l0 | ((uint32_t)l1 << 16);
            a4[0] = a4[1] = a4[2] = a4[3] = 0.0f;
        }
    }
    cp_wait<0>();
    __syncthreads();   // C1 visible, B stage 0 ready

    // ---- phase 2: 4 ktiles over C1 columns; B = Wsp2 (double-buffered)
    for (int kt = 0; kt < 4; kt++) {
        const int stage = kt & 1;
        if (kt + 1 < 4) {
            fill_B2(kt + 1, stage ^ 1);
            cp_wait<1>();
        } else {
            cp_wait<0>();
        }
        __syncthreads();

        unsigned short* sBh = smem + FB_OFF + stage * FB_STAGE;
        unsigned short* sBl = sBh + 32 * FB_STR;

        #pragma unroll
        for (int ks = 0; ks < 2; ks++) {
            uint32_t bh[2][4], bl[2][4];
            #pragma unroll
            for (int g = 0; g < 2; g++) {
                uint32_t baddr = ks * 16 * FB_STR + (wn * 32 + g * 16) + b_lane_off;
                ldsm_x4t(bh[g], sptr(sBh + baddr));
                ldsm_x4t(bl[g], sptr(sBl + baddr));
            }
            #pragma unroll
            for (int tm = 0; tm < 4; tm++) {
                uint32_t ah[4], al[4];
                int rr = wm * 64 + tm * 16 + a_row;
                int cc = kt * 32 + ks * 16 + a_col;
                ldsm_x4(ah, sptr(sC1h + rr * FB_STR + cc));
                ldsm_x4(al, sptr(sC1l + rr * FB_STR + cc));
                mma16816(acc[tm][0], ah, bh[0]);
                mma16816(acc[tm][1], ah, bh[0] + 2);
                mma16816(acc[tm][2], ah, bh[1]);
                mma16816(acc[tm][3], ah, bh[1] + 2);
                mma16816(acc[tm][0], ah, bl[0]);
                mma16816(acc[tm][1], ah, bl[0] + 2);
                mma16816(acc[tm][2], ah, bl[1]);
                mma16816(acc[tm][3], ah, bl[1] + 2);
                mma16816(acc[tm][0], al, bh[0]);
                mma16816(acc[tm][1], al, bh[0] + 2);
                mma16816(acc[tm][2], al, bh[1]);
                mma16816(acc[tm][3], al, bh[1] + 2);
            }
        }
        __syncthreads();
    }

    // ---- phase 2 epilogue -> global kb_sp (split)
    #pragma unroll
    for (int tm = 0; tm < 4; tm++) {
        int lr0 = wm * 64 + tm * 16 + (l >> 2);
        int lr1 = lr0 + 8;
        #pragma unroll
        for (int tn = 0; tn < 4; tn++) {
            int cc = wn * 32 + tn * 8 + (l & 3) * 2;
            float* a4 = acc[tm][tn];
            float v00 = gelu_f(a4[0] + b2[cc]);
            float v01 = gelu_f(a4[1] + b2[cc + 1]);
            float v10 = gelu_f(a4[2] + b2[cc]);
            float v11 = gelu_f(a4[3] + b2[cc + 1]);
            unsigned short h0, l0, h1, l1;
            size_t o0 = (size_t)(row0 + lr0) * 128 + cc;
            size_t o1 = (size_t)(row0 + lr1) * 128 + cc;
            split2(v00, h0, l0); split2(v01, h1, l1);
            *(uint32_t*)(Ch + o0) = (uint32_t)h0 | ((uint32_t)h1 << 16);
            *(uint32_t*)(Cl + o0) = (uint32_t)l0 | ((uint32_t)l1 << 16);
            split2(v10, h0, l0); split2(v11, h1, l1);
            *(uint32_t*)(Ch + o1) = (uint32_t)h0 | ((uint32_t)h1 << 16);
            *(uint32_t*)(Cl + o1) = (uint32_t)l0 | ((uint32_t)l1 << 16);
        }
    }
}

// ---------------------------------------------------------------------------
// embed (includes fibonacci grid0)
// ---------------------------------------------------------------------------
__global__ void embed_kernel(const float* __restrict__ x, const float* __restrict__ vec,
                             const float* __restrict__ Q, const int* __restrict__ batch,
                             const float* __restrict__ Wemb) {
    int v = blockIdx.x;
    int c = threadIdx.x;
    __shared__ float sQ[9], sx[IN_S], sv[6], sng[NGRID * 3], sg0[NGRID * 3];
    int b = batch[v];
    if (c < NGRID) {
        const float golden = 1.61803398874989484820f;
        float fi = (float)c;
        float theta = 6.28318530717958647692f * fi / golden;
        float z = 1.0f - (2.0f * fi + 1.0f) / (float)NGRID;
        float r = sqrtf(fmaxf(1.0f - z * z, 0.0f));
        float g0 = r * cosf(theta), g1 = r * sinf(theta);
        sg0[c*3+0] = g0; sg0[c*3+1] = g1; sg0[c*3+2] = z;
        if (v == 0) { g_grid0[c*3+0] = g0; g_grid0[c*3+1] = g1; g_grid0[c*3+2] = z; }
    }
    if (c < 9)  sQ[c] = Q[b * 9 + c];
    if (c < IN_S) sx[c] = x[v * IN_S + c];
    if (c < 6)  sv[c] = vec[v * 6 + c];
    __syncthreads();
    if (c < NGRID * 3) {
        int n = c / 3, i = c % 3;
        float t = sQ[i*3+0]*sg0[n*3+0] + sQ[i*3+1]*sg0[n*3+1] + sQ[i*3+2]*sg0[n*3+2];
        sng[c] = t;
        g_node_grid[v * NGRID * 3 + c] = t;
    }
    __syncthreads();
    float s = 0.0f;
    #pragma unroll
    for (int j = 0; j < IN_S; j++) s = fmaf(sx[j], Wemb[j * HID + c], s);
    float w16 = Wemb[IN_S * HID + c], w17 = Wemb[(IN_S + 1) * HID + c];
    #pragma unroll
    for (int n = 0; n < NGRID; n++) {
        float xv0 = sv[0]*sng[n*3+0] + sv[1]*sng[n*3+1] + sv[2]*sng[n*3+2];
        float xv1 = sv[3]*sng[n*3+0] + sv[4]*sng[n*3+1] + sv[5]*sng[n*3+2];
        g_h[(v * NGRID + n) * HID + c] = s + xv0 * w16 + xv1 * w17;
    }
}

// ---------------------------------------------------------------------------
// Combined poly + ALL weight-prep in one launch
// ---------------------------------------------------------------------------
#define POLY_BLOCKS 3000
#define WPREP_ELEMS 462848
#define WPREP_BLOCKS 1808

__global__ void poly_wprep_kernel(const float* __restrict__ pos,
                                  const int* __restrict__ send, const int* __restrict__ recv,
                                  const float* __restrict__ Wsp1, const float* __restrict__ Wsp2,
                                  const float* __restrict__ Wk, const float* __restrict__ W1,
                                  const float* __restrict__ W2) {
    if (blockIdx.x < POLY_BLOCKS) {
        int r = blockIdx.x * 256 + threadIdx.x;
        int e = r / NGRID, o = r % NGRID;
        int s = send[e], rc = recv[e];
        float rx = pos[s*3+0]-pos[rc*3+0], ry = pos[s*3+1]-pos[rc*3+1], rz = pos[s*3+2]-pos[rc*3+2];
        const float* g = &g_node_grid[(rc * NGRID + o) * 3];
        float inv1 = rx*g[0] + ry*g[1] + rz*g[2];
        float dx = rx-inv1*g[0], dy = ry-inv1*g[1], dz = rz-inv1*g[2];
        float inv2 = sqrtf(dx*dx + dy*dy + dz*dz);
        float q[16];
        float a = inv1, b = inv2;
        q[0]=a; q[1]=b; q[2]=a*a; q[3]=a*b; q[4]=b*a; q[5]=b*b;
        q[6]=q[2]*a; q[7]=q[2]*b; q[8]=q[3]*a; q[9]=q[3]*b;
        q[10]=q[4]*a; q[11]=q[4]*b; q[12]=q[5]*a; q[13]=q[5]*b;
        q[14]=0.0f; q[15]=0.0f;
        size_t base = (size_t)r * 32;
        #pragma unroll
        for (int j = 0; j < 16; j += 2) {
            unsigned short h0, l0, h1, l1;
            split2(q[j], h0, l0); split2(q[j+1], h1, l1);
            *(uint32_t*)(g_poly_h + base + j) = (uint32_t)h0 | ((uint32_t)h1 << 16);
            *(uint32_t*)(g_poly_l + base + j) = (uint32_t)l0 | ((uint32_t)l1 << 16);
        }
        #pragma unroll
        for (int j = 16; j < 32; j += 2) {
            *(uint32_t*)(g_poly_h + base + j) = 0u;
            *(uint32_t*)(g_poly_l + base + j) = 0u;
        }
    } else {
        int i = (blockIdx.x - POLY_BLOCKS) * 256 + threadIdx.x;
        if (i >= WPREP_ELEMS) return;
        float v;
        unsigned short *hi, *lo;
        size_t idx;
        if (i < 4096) {
            int k = i >> 7;
            v = (k < 14) ? Wsp1[i] : 0.0f;
            hi = g_wsp1_h; lo = g_wsp1_l; idx = i;
        } else if (i < 20480) {
            int j = i - 4096;
            v = Wsp2[j];
            hi = g_wsp2_h; lo = g_wsp2_l; idx = j;
        } else {
            int j = i - 20480;
            int ll = j / 147456;
            int r2 = j - ll * 147456;
            if (r2 < 16384) {
                v = Wk[ll * 16384 + r2];
                hi = g_wk_h; lo = g_wk_l; idx = (size_t)ll * 16384 + r2;
            } else if (r2 < 81920) {
                int j2 = r2 - 16384;
                v = W1[ll * 65536 + j2];
                hi = g_w1_h; lo = g_w1_l; idx = (size_t)ll * 65536 + j2;
            } else {
                int j2 = r2 - 81920;
                v = W2[ll * 65536 + j2];
                hi = g_w2_h; lo = g_w2_l; idx = (size_t)ll * 65536 + j2;
            }
        }
        unsigned short h, l;
        split2(v, h, l);
        hi[idx] = h; lo[idx] = l;
    }
}

__global__ void kbsh_kernel(const float* __restrict__ Wsh1, const float* __restrict__ bsh1,
                            const float* __restrict__ Wsh2, const float* __restrict__ bsh2) {
    int row = blockIdx.x;
    int p = row / NGRID, o = row % NGRID;
    int c = threadIdx.x;
    __shared__ float h1[HID];
    float t = g_grid0[p*3+0]*g_grid0[o*3+0] + g_grid0[p*3+1]*g_grid0[o*3+1] + g_grid0[p*3+2]*g_grid0[o*3+2];
    float v = t*Wsh1[c] + t*t*Wsh1[HID+c] + t*t*t*Wsh1[2*HID+c] + bsh1[c];
    h1[c] = gelu_f(v);
    __syncthreads();
    float acc = bsh2[c];
    #pragma unroll 8
    for (int k = 0; k < HID; k++) acc = fmaf(h1[k], Wsh2[k*HID + c], acc);
    g_kb_sh[row * HID + c] = gelu_f(acc);
}

__global__ void fk_kernel(const float* __restrict__ Wfk) {
    int blk = blockIdx.x;
    int ll = blk / 144, row = blk % 144;
    int c = threadIdx.x;
    __shared__ float r128[HID];
    r128[c] = g_kb_sh[row * HID + c];
    __syncthreads();
    const float* W = Wfk + ll * HID * HID;
    float acc = 0.0f;
    #pragma unroll 8
    for (int k = 0; k < HID; k++) acc = fmaf(r128[k], W[k*HID + c], acc);
    g_fk[ll * 144 * HID + row * HID + c] = acc;
}

// conv_ln: 384 threads = 12 warps (one per p), one barrier
__global__ __launch_bounds__(384)
void conv_ln_kernel(const float* __restrict__ agg, const float* __restrict__ fk,
                    const float* __restrict__ bconv, const float* __restrict__ lng,
                    const float* __restrict__ lnb) {
    int v = blockIdx.x;
    int tid = threadIdx.x, lane = tid & 31, wp = tid >> 5;
    __shared__ float sagg[NGRID][HID];
    for (int i = tid; i < NGRID * HID; i += 384)
        sagg[i >> 7][i & 127] = agg[(size_t)v * NGRID * HID + i];
    __syncthreads();

    int c0 = lane * 4;
    float4 s = {0.0f, 0.0f, 0.0f, 0.0f};
    #pragma unroll
    for (int o = 0; o < NGRID; o++) {
        float4 a = *(const float4*)&sagg[o][c0];
        float4 f = *(const float4*)&fk[(size_t)(wp * NGRID + o) * HID + c0];
        s.x = fmaf(a.x, f.x, s.x);
        s.y = fmaf(a.y, f.y, s.y);
        s.z = fmaf(a.z, f.z, s.z);
        s.w = fmaf(a.w, f.w, s.w);
    }
    float4 bc = *(const float4*)&bconv[c0];
    float4 x;
    x.x = s.x * (1.0f / NGRID) + bc.x;
    x.y = s.y * (1.0f / NGRID) + bc.y;
    x.z = s.z * (1.0f / NGRID) + bc.z;
    x.w = s.w * (1.0f / NGRID) + bc.w;

    float t = x.x + x.y + x.z + x.w;
    #pragma unroll
    for (int off = 16; off > 0; off >>= 1) t += __shfl_xor_sync(0xffffffffu, t, off);
    float mu = t * (1.0f / HID);
    float4 d = {x.x - mu, x.y - mu, x.z - mu, x.w - mu};
    float t2 = d.x*d.x + d.y*d.y + d.z*d.z + d.w*d.w;
    #pragma unroll
    for (int off = 16; off > 0; off >>= 1) t2 += __shfl_xor_sync(0xffffffffu, t2, off);
    float rstd = rsqrtf(t2 * (1.0f / HID) + 1e-5f);

    float4 g = *(const float4*)&lng[c0];
    float4 bb = *(const float4*)&lnb[c0];
    float v0 = d.x * rstd * g.x + bb.x;
    float v1 = d.y * rstd * g.y + bb.y;
    float v2 = d.z * rstd * g.z + bb.z;
    float v3 = d.w * rstd * g.w + bb.w;

    unsigned short h0,l0,h1,l1,h2,l2,h3,l3;
    split2(v0,h0,l0); split2(v1,h1,l1); split2(v2,h2,l2); split2(v3,h3,l3);
    size_t idx = (size_t)(v * NGRID + wp) * HID + c0;
    uint2 ph = { (uint32_t)h0 | ((uint32_t)h1 << 16), (uint32_t)h2 | ((uint32_t)h3 << 16) };
    uint2 pl = { (uint32_t)l0 | ((uint32_t)l1 << 16), (uint32_t)l2 | ((uint32_t)l3 << 16) };
    *(uint2*)(g_hn_h + idx) = ph;
    *(uint2*)(g_hn_l + idx) = pl;
}

__global__ void readout_kernel(const float* __restrict__ h, const float* __restrict__ Wro,
                               const float* __restrict__ bro) {
    __shared__ float hs[16 * 129];
    int tid = threadIdx.x;
    int r0 = blockIdx.x * 16;
    for (int i = tid; i < 16 * 128; i += 160) {
        int row = i >> 7, cc = i & 127;
        hs[row * 129 + cc] = h[(size_t)(r0 + row) * HID + cc];
    }
    __syncthreads();
    if (tid < 16 * 9) {
        int row = tid / 9, oc = tid % 9;
        float acc = bro[oc];
        #pragma unroll 8
        for (int cc = 0; cc < 128; cc++) acc = fmaf(hs[row * 129 + cc], Wro[cc * 9 + oc], acc);
        g_readout[(r0 + row) * 9 + oc] += acc * (1.0f / NLAYERS);
    }
}

__global__ void finalize_kernel(const int* __restrict__ batch, float* __restrict__ out) {
    int v = blockIdx.x * 256 + threadIdx.x;
    if (v >= N_NODES) return;
    float ssum[OUT_S] = {0,0,0,0,0,0,0,0};
    float vsum[3] = {0,0,0};
    for (int n = 0; n < NGRID; n++) {
        const float* rr = &g_readout[(v * NGRID + n) * 9];
        #pragma unroll
        for (int j = 0; j < OUT_S; j++) ssum[j] += rr[j];
        float rv = rr[OUT_S];
        const float* g = &g_node_grid[(v * NGRID + n) * 3];
        vsum[0] += rv * g[0]; vsum[1] += rv * g[1]; vsum[2] += rv * g[2];
    }
    int b = batch[v];
    #pragma unroll
    for (int j = 0; j < OUT_S; j++) atomicAdd(&out[b * OUT_S + j], ssum[j] * (1.0f / NGRID));
    #pragma unroll
    for (int d = 0; d < 3; d++) atomicAdd(&out[NBATCH * OUT_S + b * 3 + d], vsum[d] * (1.0f / NGRID));
}

__global__ void zero_kernel(float* __restrict__ p, int n) {
    for (int i = blockIdx.x * blockDim.x + threadIdx.x; i < n; i += gridDim.x * blockDim.x)
        p[i] = 0.0f;
}
__global__ void zero_sym_kernel(int which) {
    int stride = gridDim.x * blockDim.x;
    if (which == 0) {
        for (int i = blockIdx.x*blockDim.x+threadIdx.x; i < R_N*HID; i += stride) g_agg[i] = 0.0f;
    } else {
        for (int i = blockIdx.x*blockDim.x+threadIdx.x; i < R_N*9; i += stride) g_readout[i] = 0.0f;
    }
}

// ---------------------------------------------------------------------------
// Host launcher — launch #4 (ncu) = kbsp_fused
// ---------------------------------------------------------------------------
extern "C" void kernel_launch(void* const* d_in, const int* in_sizes, int n_in,
                              void* d_out, int out_size) {
    const float* x    = (const float*)d_in[0];
    const float* vec  = (const float*)d_in[1];
    const float* pos  = (const float*)d_in[2];
    const float* Q    = (const float*)d_in[3];
    const float* Wsp1 = (const float*)d_in[4];
    const float* bsp1 = (const float*)d_in[5];
    const float* Wsp2 = (const float*)d_in[6];
    const float* bsp2 = (const float*)d_in[7];
    const float* Wsh1 = (const float*)d_in[8];
    const float* bsh1 = (const float*)d_in[9];
    const float* Wsh2 = (const float*)d_in[10];
    const float* bsh2 = (const float*)d_in[11];
    const float* Wemb = (const float*)d_in[12];
    const float* Wk   = (const float*)d_in[13];
    const float* Wfk  = (const float*)d_in[14];
    const float* bconv= (const float*)d_in[15];
    const float* ln_g = (const float*)d_in[16];
    const float* ln_b = (const float*)d_in[17];
    const float* W1   = (const float*)d_in[18];
    const float* b1   = (const float*)d_in[19];
    const float* W2   = (const float*)d_in[20];
    const float* b2   = (const float*)d_in[21];
    const float* Wro  = (const float*)d_in[22];
    const float* bro  = (const float*)d_in[23];
    const int*   eidx = (const int*)d_in[24];
    const int*   batch= (const int*)d_in[25];
    float* out = (float*)d_out;
    const int* send = eidx;
    const int* recv = eidx + N_EDGES;

    float *p_h, *p_agg, *p_fk;
    unsigned short *p_ph,*p_pl,*p_b1h,*p_b1l,*p_kbh,*p_kbl,*p_hnh,*p_hnl;
    unsigned short *p_wsp1h,*p_wsp1l,*p_wsp2h,*p_wsp2l,*p_wkh,*p_wkl,*p_w1h,*p_w1l,*p_w2h,*p_w2l;
    cudaGetSymbolAddress((void**)&p_h,   g_h);
    cudaGetSymbolAddress((void**)&p_agg, g_agg);
    cudaGetSymbolAddress((void**)&p_fk,  g_fk);
    cudaGetSymbolAddress((void**)&p_ph,  g_poly_h);  cudaGetSymbolAddress((void**)&p_pl,  g_poly_l);
    cudaGetSymbolAddress((void**)&p_b1h, g_buf1_h);  cudaGetSymbolAddress((void**)&p_b1l, g_buf1_l);
    cudaGetSymbolAddress((void**)&p_kbh, g_kbsp_h);  cudaGetSymbolAddress((void**)&p_kbl, g_kbsp_l);
    cudaGetSymbolAddress((void**)&p_hnh, g_hn_h);    cudaGetSymbolAddress((void**)&p_hnl, g_hn_l);
    cudaGetSymbolAddress((void**)&p_wsp1h, g_wsp1_h); cudaGetSymbolAddress((void**)&p_wsp1l, g_wsp1_l);
    cudaGetSymbolAddress((void**)&p_wsp2h, g_wsp2_h); cudaGetSymbolAddress((void**)&p_wsp2l, g_wsp2_l);
    cudaGetSymbolAddress((void**)&p_wkh, g_wk_h);    cudaGetSymbolAddress((void**)&p_wkl, g_wk_l);
    cudaGetSymbolAddress((void**)&p_w1h, g_w1_h);    cudaGetSymbolAddress((void**)&p_w1l, g_w1_l);
    cudaGetSymbolAddress((void**)&p_w2h, g_w2_h);    cudaGetSymbolAddress((void**)&p_w2l, g_w2_l);

    cudaFuncSetAttribute(hmma_gemm<0>, cudaFuncAttributeMaxDynamicSharedMemorySize, SMEM_DYN);
    cudaFuncSetAttribute(hmma_gemm<1>, cudaFuncAttributeMaxDynamicSharedMemorySize, SMEM_DYN);
    cudaFuncSetAttribute(hmma_gemm<2>, cudaFuncAttributeMaxDynamicSharedMemorySize, SMEM_DYN);
    cudaFuncSetAttribute(kbsp_fused,   cudaFuncAttributeMaxDynamicSharedMemorySize, FUSED_SMEM);

    // 1: embed
    embed_kernel<<<N_NODES, 128>>>(x, vec, Q, batch, Wemb);
    // 2: poly + weight prep
    poly_wprep_kernel<<<POLY_BLOCKS + WPREP_BLOCKS, 256>>>(pos, send, recv, Wsp1, Wsp2, Wk, W1, W2);
    // 3: zero readout
    zero_sym_kernel<<<1024, 256>>>(1);
    // 4: fused kb_sp MLP (poly -> 128 gelu -> 128 gelu) — ncu-profiled launch
    kbsp_fused<<<R_E / 128, 256, FUSED_SMEM>>>(p_ph, p_pl, p_wsp1h, p_wsp1l, p_wsp2h, p_wsp2l,
                                               bsp1, bsp2, p_kbh, p_kbl);
    // remaining setup
    kbsh_kernel<<<144, 128>>>(Wsh1, bsh1, Wsh2, bsh2);
    fk_kernel<<<NLAYERS * 144, 128>>>(Wfk);

    for (int l = 0; l < NLAYERS; l++) {
        zero_sym_kernel<<<4096, 256>>>(0);
        hmma_gemm<1><<<dim3(R_E / 128, 1), 256, SMEM_DYN>>>(p_kbh, p_kbl, 128,
                                                  p_wkh + l*128*128, p_wkl + l*128*128, 128,
                                                  4, 8, 128, nullptr, p_h, p_agg, nullptr, nullptr,
                                                  send, recv);
        conv_ln_kernel<<<N_NODES, 384>>>(p_agg, p_fk + l * 144 * HID,
                                         bconv + l * HID, ln_g + l * HID, ln_b + l * HID);
        hmma_gemm<0><<<dim3(R_N / 128, 4), 256, SMEM_DYN>>>(p_hnh, p_hnl, 128,
                                                  p_w1h + l*128*512, p_w1l + l*128*512, 512,
                                                  4, 8, 512, b1 + l*512, nullptr, nullptr, p_b1h, p_b1l,
                                                  nullptr, nullptr);
        hmma_gemm<2><<<dim3(R_N / 128, 1), 256, SMEM_DYN>>>(p_b1h, p_b1l, 512,
                                                  p_w2h + l*512*128, p_w2l + l*512*128, 128,
                                                  16, 32, 128, b2 + l*128, p_h, p_h, nullptr, nullptr,
                                                  nullptr, nullptr);
        readout_kernel<<<R_N / 16, 160>>>(p_h, Wro + l * HID * 9, bro + l * 9);
    }

    int out_elems = NBATCH * OUT_S + NBATCH * 3;
    zero_kernel<<<(out_elems + 255) / 256, 256>>>(out, out_elems);
    finalize_kernel<<<(N_NODES + 255) / 256, 256>>>(batch, out);
}